// round 11
// baseline (speedup 1.0000x reference)
#include <cuda_runtime.h>
#include <cuda_bf16.h>
#include <math.h>
#include <stdint.h>

#define L_SEQ   1024
#define INLEN   512
#define DMODEL  1024
#define NLAYERS 4
#define DINNER  2048
#define DSTATE  16
#define DTRANK  64
#define XDBL_W  96   // DT_RANK + 2*D_STATE

typedef __nv_bfloat16 bf16;

// ---------------- fp32 scratch ----------------------------------------------
__device__ float g_res   [L_SEQ * DMODEL];
__device__ float g_h     [L_SEQ * DMODEL];
__device__ float g_xz    [L_SEQ * 2 * DINNER];
__device__ float g_xconv [L_SEQ * DINNER];
__device__ float g_xdbl  [L_SEQ * XDBL_W];
__device__ float g_delta [L_SEQ * DINNER];
__device__ float g_deltaT[DINNER * L_SEQ];
__device__ float g_xcT   [DINNER * L_SEQ];
__device__ float g_zT    [DINNER * L_SEQ];
__device__ float g_yT    [DINNER * L_SEQ];

// ---------------- bf16 hi/lo scratch -----------------------------------------
__device__ bf16 c_in_hi [L_SEQ * INLEN],        c_in_lo [L_SEQ * INLEN];
__device__ bf16 c_inw_hi[DMODEL * INLEN],       c_inw_lo[DMODEL * INLEN];
__device__ bf16 c_ipw_hi[NLAYERS * 2*DINNER * DMODEL], c_ipw_lo[NLAYERS * 2*DINNER * DMODEL];
__device__ bf16 c_xpw_hi[NLAYERS * XDBL_W * DINNER],   c_xpw_lo[NLAYERS * XDBL_W * DINNER];
__device__ bf16 c_dtw_hi[NLAYERS * DINNER * DTRANK],   c_dtw_lo[NLAYERS * DINNER * DTRANK];
__device__ bf16 c_opw_hi[NLAYERS * DMODEL * DINNER],   c_opw_lo[NLAYERS * DMODEL * DINNER];
__device__ bf16 c_hn_hi [L_SEQ * DMODEL],       c_hn_lo [L_SEQ * DMODEL];
__device__ bf16 c_xc_hi [L_SEQ * DINNER],       c_xc_lo [L_SEQ * DINNER];
__device__ bf16 c_xd_hi [L_SEQ * DTRANK],       c_xd_lo [L_SEQ * DTRANK];
__device__ bf16 c_y_hi  [L_SEQ * DINNER],       c_y_lo  [L_SEQ * DINNER];

// ============================ PTX helpers ====================================
__device__ __forceinline__ uint32_t smem_u32(const void* p) {
    uint32_t a;
    asm("{ .reg .u64 t; cvta.to.shared.u64 t, %1; cvt.u32.u64 %0, t; }"
        : "=r"(a) : "l"(p));
    return a;
}
#define CP_ASYNC16(dst, src, sz) \
    asm volatile("cp.async.cg.shared.global [%0], [%1], 16, %2;" \
                 :: "r"(dst), "l"(src), "r"(sz))
#define CP_COMMIT() asm volatile("cp.async.commit_group;" ::: "memory")
#define CP_WAIT0()  asm volatile("cp.async.wait_group 0;" ::: "memory")

#define LDM4(r0, r1, r2, r3, addr) \
    asm volatile("ldmatrix.sync.aligned.m8n8.x4.shared.b16 {%0,%1,%2,%3}, [%4];" \
                 : "=r"(r0), "=r"(r1), "=r"(r2), "=r"(r3) : "r"(addr))

#define MMA_BF16(c, a, b)                                                      \
    asm volatile(                                                              \
        "mma.sync.aligned.m16n8k16.row.col.f32.bf16.bf16.f32 "                 \
        "{%0,%1,%2,%3}, {%4,%5,%6,%7}, {%8,%9}, {%0,%1,%2,%3};"                \
        : "+f"((c)[0]), "+f"((c)[1]), "+f"((c)[2]), "+f"((c)[3])               \
        : "r"((a)[0]), "r"((a)[1]), "r"((a)[2]), "r"((a)[3]),                  \
          "r"((b)[0]), "r"((b)[1]))

__device__ __forceinline__ uint32_t swz(uint32_t off) {
    return off ^ ((off >> 3) & 0x70);
}
__device__ __forceinline__ void split_bf16(float v, bf16& hi, bf16& lo) {
    hi = __float2bfloat16(v);
    lo = __float2bfloat16(v - __bfloat162float(hi));
}

// =============================================================================
// bf16 hi/lo split NT GEMM (3 MMAs per k16), 64x128 tile, 2-stage cp.async,
// 2 CTAs/SM.  C[m,n] = sum_k A[m,k]*B[n,k]
//   Ksplit = K per z-slice.  mode 0: store; 1: softplus(acc+bias); 2: atomicAdd
// =============================================================================
#define G_ABYTES 8192
#define G_BBYTES 16384
#define G_STAGE  (2*G_ABYTES + 2*G_BBYTES)   // 48 KB
#define G_SMEM   (2 * G_STAGE)               // 96 KB

__global__ void __launch_bounds__(256, 2)
mma_gemm(const bf16* __restrict__ Ahi, const bf16* __restrict__ Alo, int lda,
         const bf16* __restrict__ Bhi, const bf16* __restrict__ Blo, int ldb,
         float* __restrict__ C, int ldc,
         int Nvalid, int Ksplit,
         const float* __restrict__ bias, int mode)
{
    extern __shared__ char smem[];
    const uint32_t sb = smem_u32(smem);

    const int tid  = threadIdx.x;
    const int wid  = tid >> 5;
    const int lane = tid & 31;
    const int m0   = blockIdx.y * 64;
    const int n0   = blockIdx.x * 128;
    const int kbase = blockIdx.z * Ksplit;

    const int warp_m = (wid & 1) * 32;
    const int warp_n = (wid >> 1) * 32;

    float acc[2][4][4];
#pragma unroll
    for (int mt = 0; mt < 2; mt++)
#pragma unroll
        for (int nt = 0; nt < 4; nt++)
#pragma unroll
            for (int i = 0; i < 4; i++) acc[mt][nt][i] = 0.f;

    auto stage_load = [&](int c, int buf) {
        const int k0 = kbase + (c << 6);
        const uint32_t st = sb + buf * G_STAGE;
#pragma unroll
        for (int i = 0; i < 2; i++) {
            int j = tid + i * 256;
            int r = j >> 3, u = j & 7;
            uint32_t so = swz((uint32_t)(r * 128 + u * 16));
            const char* ga = (const char*)(Ahi + (size_t)(m0 + r) * lda + k0 + u * 8);
            const char* gl = (const char*)(Alo + (size_t)(m0 + r) * lda + k0 + u * 8);
            CP_ASYNC16(st + so, ga, 16);
            CP_ASYNC16(st + G_ABYTES + so, gl, 16);
        }
#pragma unroll
        for (int i = 0; i < 4; i++) {
            int j = tid + i * 256;
            int r = j >> 3, u = j & 7;
            int gn = n0 + r;
            int sz = (gn < Nvalid) ? 16 : 0;
            int gc = (gn < Nvalid) ? gn : 0;
            uint32_t so = swz((uint32_t)(r * 128 + u * 16));
            const char* gb = (const char*)(Bhi + (size_t)gc * ldb + k0 + u * 8);
            const char* gl = (const char*)(Blo + (size_t)gc * ldb + k0 + u * 8);
            CP_ASYNC16(st + 2 * G_ABYTES + so, gb, sz);
            CP_ASYNC16(st + 2 * G_ABYTES + G_BBYTES + so, gl, sz);
        }
        CP_COMMIT();
    };

    auto mma_chunk = [&](int buf) {
        const uint32_t st  = sb + buf * G_STAGE;
        const uint32_t sAh = st;
        const uint32_t sAl = st + G_ABYTES;
        const uint32_t sBh = st + 2 * G_ABYTES;
        const uint32_t sBl = sBh + G_BBYTES;
#pragma unroll
        for (int ks = 0; ks < 4; ks++) {
            const int kb = ks * 32;
            uint32_t bh[4][2], bl[4][2];
#pragma unroll
            for (int p = 0; p < 2; p++) {
                int row = warp_n + p * 16 + ((lane >> 4) << 3) + (lane & 7);
                int kbyte = kb + ((lane >> 3) & 1) * 16;
                uint32_t off = swz((uint32_t)(row * 128 + kbyte));
                LDM4(bh[2*p][0], bh[2*p][1], bh[2*p+1][0], bh[2*p+1][1], sBh + off);
                LDM4(bl[2*p][0], bl[2*p][1], bl[2*p+1][0], bl[2*p+1][1], sBl + off);
            }
#pragma unroll
            for (int mt = 0; mt < 2; mt++) {
                int row = warp_m + mt * 16 + (lane & 15);
                int kbyte = kb + (lane >> 4) * 16;
                uint32_t off = swz((uint32_t)(row * 128 + kbyte));
                uint32_t ah[4], al[4];
                LDM4(ah[0], ah[1], ah[2], ah[3], sAh + off);
                LDM4(al[0], al[1], al[2], al[3], sAl + off);
#pragma unroll
                for (int nt = 0; nt < 4; nt++) MMA_BF16(acc[mt][nt], ah, bh[nt]);
#pragma unroll
                for (int nt = 0; nt < 4; nt++) MMA_BF16(acc[mt][nt], ah, bl[nt]);
#pragma unroll
                for (int nt = 0; nt < 4; nt++) MMA_BF16(acc[mt][nt], al, bh[nt]);
            }
        }
    };

    const int NC = Ksplit >> 6;
    stage_load(0, 0);
    for (int c = 0; c < NC; c++) {
        CP_WAIT0();
        __syncthreads();
        if (c + 1 < NC) stage_load(c + 1, (c + 1) & 1);
        mma_chunk(c & 1);
    }

    // ---- epilogue ----
    const int qrow = lane >> 2;
    const int qcol = (lane & 3) * 2;
#pragma unroll
    for (int mt = 0; mt < 2; mt++) {
        int row0 = m0 + warp_m + mt * 16 + qrow;
        int row1 = row0 + 8;
#pragma unroll
        for (int nt = 0; nt < 4; nt++) {
            int gn = n0 + warp_n + nt * 8 + qcol;
            if (gn >= Nvalid) continue;
            float2 v0 = make_float2(acc[mt][nt][0], acc[mt][nt][1]);
            float2 v1 = make_float2(acc[mt][nt][2], acc[mt][nt][3]);
            if (mode == 1) {
                float b0 = bias[gn], b1 = bias[gn + 1];
                v0.x += b0; v0.y += b1; v1.x += b0; v1.y += b1;
                v0.x = (v0.x > 20.f) ? v0.x : log1pf(expf(v0.x));
                v0.y = (v0.y > 20.f) ? v0.y : log1pf(expf(v0.y));
                v1.x = (v1.x > 20.f) ? v1.x : log1pf(expf(v1.x));
                v1.y = (v1.y > 20.f) ? v1.y : log1pf(expf(v1.y));
            }
            if (mode == 2) {
                atomicAdd(&C[(size_t)row0 * ldc + gn],     v0.x);
                atomicAdd(&C[(size_t)row0 * ldc + gn + 1], v0.y);
                atomicAdd(&C[(size_t)row1 * ldc + gn],     v1.x);
                atomicAdd(&C[(size_t)row1 * ldc + gn + 1], v1.y);
            } else {
                *reinterpret_cast<float2*>(C + (size_t)row0 * ldc + gn) = v0;
                *reinterpret_cast<float2*>(C + (size_t)row1 * ldc + gn) = v1;
            }
        }
    }
}

// ---------------- fp32 -> bf16 hi/lo converters (MLP=4) ----------------------
__global__ void cvt_kernel(const float* __restrict__ src,
                           bf16* __restrict__ hi, bf16* __restrict__ lo, int n4)
{
    int base = blockIdx.x * blockDim.x * 4 + threadIdx.x;
    float4 v[4];
    int idx[4];
#pragma unroll
    for (int u = 0; u < 4; u++) {
        idx[u] = base + u * 256;
        if (idx[u] < n4) v[u] = reinterpret_cast<const float4*>(src)[idx[u]];
    }
#pragma unroll
    for (int u = 0; u < 4; u++) {
        if (idx[u] >= n4) continue;
        bf16 h0, h1, h2, h3, l0, l1, l2, l3;
        split_bf16(v[u].x, h0, l0); split_bf16(v[u].y, h1, l1);
        split_bf16(v[u].z, h2, l2); split_bf16(v[u].w, h3, l3);
        uint32_t hA = ((uint32_t)__bfloat16_as_ushort(h1) << 16) | __bfloat16_as_ushort(h0);
        uint32_t hB = ((uint32_t)__bfloat16_as_ushort(h3) << 16) | __bfloat16_as_ushort(h2);
        uint32_t lA = ((uint32_t)__bfloat16_as_ushort(l1) << 16) | __bfloat16_as_ushort(l0);
        uint32_t lB = ((uint32_t)__bfloat16_as_ushort(l3) << 16) | __bfloat16_as_ushort(l2);
        reinterpret_cast<uint2*>(hi)[idx[u]] = make_uint2(hA, hB);
        reinterpret_cast<uint2*>(lo)[idx[u]] = make_uint2(lA, lB);
    }
}

__global__ void cvt4_kernel(const float* s0, bf16* h0, bf16* l0, int n0,
                            const float* s1, bf16* h1, bf16* l1, int n1,
                            const float* s2, bf16* h2, bf16* l2, int n2,
                            const float* s3, bf16* h3, bf16* l3, int n3)
{
    int i = blockIdx.x * blockDim.x + threadIdx.x;
    const float* s; bf16 *h, *l; int j = i;
    if (j < n0)      { s = s0; h = h0; l = l0; }
    else { j -= n0;
    if (j < n1)      { s = s1; h = h1; l = l1; }
    else { j -= n1;
    if (j < n2)      { s = s2; h = h2; l = l2; }
    else { j -= n2;
    if (j < n3)      { s = s3; h = h3; l = l3; }
    else return; } } }
    float4 v = reinterpret_cast<const float4*>(s)[j];
    bf16 a0, a1, a2, a3, b0, b1, b2, b3;
    split_bf16(v.x, a0, b0); split_bf16(v.y, a1, b1);
    split_bf16(v.z, a2, b2); split_bf16(v.w, a3, b3);
    uint32_t hA = ((uint32_t)__bfloat16_as_ushort(a1) << 16) | __bfloat16_as_ushort(a0);
    uint32_t hB = ((uint32_t)__bfloat16_as_ushort(a3) << 16) | __bfloat16_as_ushort(a2);
    uint32_t lA = ((uint32_t)__bfloat16_as_ushort(b1) << 16) | __bfloat16_as_ushort(b0);
    uint32_t lB = ((uint32_t)__bfloat16_as_ushort(b3) << 16) | __bfloat16_as_ushort(b2);
    reinterpret_cast<uint2*>(h)[j] = make_uint2(hA, hB);
    reinterpret_cast<uint2*>(l)[j] = make_uint2(lA, lB);
}

__global__ void cvt_xdbl_kernel(const float* __restrict__ xdbl,
                                bf16* __restrict__ hi, bf16* __restrict__ lo)
{
    int i = blockIdx.x * blockDim.x + threadIdx.x;
    int r = i >> 6, c = i & 63;
    float v = xdbl[r * XDBL_W + c];
    bf16 h, l; split_bf16(v, h, l);
    hi[i] = h; lo[i] = l;
}

// ---------------- fused residual-add + LayerNorm ------------------------------
__global__ void resln_kernel(const float* __restrict__ hin,
                             float* __restrict__ res,
                             bf16* __restrict__ hn_hi, bf16* __restrict__ hn_lo,
                             const float* __restrict__ w,
                             const float* __restrict__ b,
                             int first)
{
    const int l   = blockIdx.x;
    const int tid = threadIdx.x;
    float v[4];
    float s = 0.f, sq = 0.f;
#pragma unroll
    for (int i = 0; i < 4; i++) {
        int c = tid + i * 256;
        float x = hin[l * DMODEL + c];
        if (!first) x += res[l * DMODEL + c];
        res[l * DMODEL + c] = x;
        v[i] = x;
        s  += x;
        sq += x * x;
    }
    __shared__ float shs[8], shq[8];
    const int lane = tid & 31, warp = tid >> 5;
#pragma unroll
    for (int o = 16; o > 0; o >>= 1) {
        s  += __shfl_xor_sync(0xffffffffu, s,  o);
        sq += __shfl_xor_sync(0xffffffffu, sq, o);
    }
    if (lane == 0) { shs[warp] = s; shq[warp] = sq; }
    __syncthreads();
    s = 0.f; sq = 0.f;
#pragma unroll
    for (int i = 0; i < 8; i++) { s += shs[i]; sq += shq[i]; }

    const float inv = 1.f / (float)DMODEL;
    const float mu  = s * inv;
    const float var = sq * inv - mu * mu;
    const float rstd = rsqrtf(var + 1e-5f);
#pragma unroll
    for (int i = 0; i < 4; i++) {
        int c = tid + i * 256;
        float o = (v[i] - mu) * rstd * w[c] + b[c];
        bf16 h, lo; split_bf16(o, h, lo);
        hn_hi[l * DMODEL + c] = h;
        hn_lo[l * DMODEL + c] = lo;
    }
}

// ---------------- conv + SiLU; zeroes xdbl for split-K atomics ---------------
__global__ void conv_silu_kernel(const float* __restrict__ xz,
                                 const float* __restrict__ cw,
                                 const float* __restrict__ cb,
                                 float* __restrict__ xconv,
                                 bf16* __restrict__ xc_hi,
                                 bf16* __restrict__ xc_lo,
                                 float* __restrict__ xdbl_zero)
{
    const int idx = blockIdx.x * blockDim.x + threadIdx.x;
    if (idx >= L_SEQ * DINNER) return;
    const int l = idx >> 11;
    const int d = idx & (DINNER - 1);

    float acc = cb[d];
    const float w0 = cw[d*4+0], w1 = cw[d*4+1], w2 = cw[d*4+2], w3 = cw[d*4+3];
    if (l >= 3) acc = fmaf(w0, xz[(size_t)(l-3) * (2*DINNER) + d], acc);
    if (l >= 2) acc = fmaf(w1, xz[(size_t)(l-2) * (2*DINNER) + d], acc);
    if (l >= 1) acc = fmaf(w2, xz[(size_t)(l-1) * (2*DINNER) + d], acc);
    acc = fmaf(w3, xz[(size_t)l * (2*DINNER) + d], acc);

    acc = acc / (1.f + expf(-acc));
    xconv[idx] = acc;
    bf16 h, lo; split_bf16(acc, h, lo);
    xc_hi[idx] = h;
    xc_lo[idx] = lo;

    if (idx < L_SEQ * XDBL_W) xdbl_zero[idx] = 0.f;
}

// ---------------- 32x32 tiled transpose: delta/xconv/z -> [d][t] -------------
__global__ void transpose3_kernel(const float* __restrict__ dsrc,
                                  const float* __restrict__ xsrc,
                                  const float* __restrict__ zsrc,
                                  float* __restrict__ dT,
                                  float* __restrict__ xT,
                                  float* __restrict__ zT)
{
    __shared__ float tile[32][33];
    const float* src; float* dst; int lds;
    if (blockIdx.z == 0)      { src = dsrc; dst = dT; lds = DINNER; }
    else if (blockIdx.z == 1) { src = xsrc; dst = xT; lds = DINNER; }
    else                      { src = zsrc; dst = zT; lds = 2 * DINNER; }
    const int c0 = blockIdx.x * 32;
    const int r0 = blockIdx.y * 32;
    const int x = threadIdx.x, y0 = threadIdx.y;
#pragma unroll
    for (int i = 0; i < 4; i++) {
        int y = y0 + i * 8;
        tile[y][x] = src[(size_t)(r0 + y) * lds + c0 + x];
    }
    __syncthreads();
#pragma unroll
    for (int i = 0; i < 4; i++) {
        int y = y0 + i * 8;
        dst[(size_t)(c0 + y) * L_SEQ + r0 + x] = tile[x][y];
    }
}

// ---------------- yT [d][t] -> y hi/lo [t][d]; also zeroes out_proj target ----
__global__ void ytr_kernel(const float* __restrict__ yT,
                           bf16* __restrict__ y_hi, bf16* __restrict__ y_lo,
                           float* __restrict__ zero_buf)
{
    // zero the split-K out_proj target: 2048 CTAs x 256 flat threads x 2 floats
    {
        int flat = threadIdx.y * 32 + threadIdx.x;
        int zi = (blockIdx.y * gridDim.x + blockIdx.x) * 256 + flat;
        if (zi * 2 < L_SEQ * DMODEL)
            *reinterpret_cast<float2*>(zero_buf + zi * 2) = make_float2(0.f, 0.f);
    }
    __shared__ float tile[32][33];
    const int c0 = blockIdx.x * 32;   // t
    const int r0 = blockIdx.y * 32;   // d
    const int x = threadIdx.x, y0 = threadIdx.y;
#pragma unroll
    for (int i = 0; i < 4; i++) {
        int y = y0 + i * 8;
        tile[y][x] = yT[(size_t)(r0 + y) * L_SEQ + c0 + x];
    }
    __syncthreads();
#pragma unroll
    for (int i = 0; i < 4; i++) {
        int y = y0 + i * 8;
        float v = tile[x][y];
        bf16 h, l; split_bf16(v, h, l);
        y_hi[(size_t)(c0 + y) * DINNER + r0 + x] = h;
        y_lo[(size_t)(c0 + y) * DINNER + r0 + x] = l;
    }
}

// =============================================================================
// Chunked parallel scan; dA computed once (phase 1) and cached in REGISTERS,
// reused in phase 2 -> half the exp2 count, no smem table, no bank conflicts.
// 256 threads = 16 chunks x 16 states; smem = s_dl/s_xv staging + combine.
// =============================================================================
__global__ void __launch_bounds__(256)
scan_kernel(const float* __restrict__ deltaT,
            const float* __restrict__ xcT,
            const float* __restrict__ zT,
            const float* __restrict__ xdbl,
            const float* __restrict__ A_log,
            const float* __restrict__ Dvec,
            float* __restrict__ yT)
{
    __shared__ float s_dl[L_SEQ];
    __shared__ float s_xv[L_SEQ];
    __shared__ float shP[16][16];
    __shared__ float shS[16][16];

    const int d    = blockIdx.x;
    const int tid  = threadIdx.x;
    const int lane = tid & 31;
    const int wrp  = tid >> 5;
    const int j    = wrp * 2 + (lane >> 4);
    const int s    = lane & 15;
    const int t0   = j * 64;

    for (int i = tid; i < L_SEQ; i += 256) {
        s_dl[i] = deltaT[(size_t)d * L_SEQ + i];
        s_xv[i] = xcT[(size_t)d * L_SEQ + i];
    }
    __syncthreads();

    const float a2 = -expf(A_log[d * DSTATE + s]) * 1.4426950408889634f;

    // ---- phase 1: compute dA once, cache in registers ----
    float dAreg[64];
    float P = 1.f, S = 0.f;
#pragma unroll
    for (int k = 0; k < 64; k++) {
        const int t = t0 + k;
        const float dl = s_dl[t];
        const float Bs = xdbl[t * XDBL_W + DTRANK + s];
        const float dA = exp2f(dl * a2);
        dAreg[k] = dA;
        P *= dA;
        S = fmaf(dA, S, dl * s_xv[t] * Bs);
    }
    shP[j][s] = P;
    shS[j][s] = S;
    __syncthreads();

    // ---- combine: serial prefix over 16 chunks, one thread per state ----
    if (tid < 16) {
        const int ss = tid;
        float run = shS[0][ss];
#pragma unroll
        for (int jj = 1; jj < 16; jj++) {
            run = fmaf(shP[jj][ss], run, shS[jj][ss]);
            shS[jj][ss] = run;
        }
    }
    __syncthreads();

    // ---- phase 2: rescan with corrected h0 reusing cached dA ----
    float h = (j == 0) ? 0.f : shS[j - 1][s];
    const float Dd = Dvec[d];
#pragma unroll
    for (int k = 0; k < 64; k++) {
        const int t = t0 + k;
        const float dl = s_dl[t];
        const float xv = s_xv[t];
        const float Bs = xdbl[t * XDBL_W + DTRANK + s];
        const float Cs = xdbl[t * XDBL_W + DTRANK + DSTATE + s];
        h = fmaf(dAreg[k], h, dl * xv * Bs);

        float acc = h * Cs;
        acc += __shfl_xor_sync(0xffffffffu, acc, 1);
        acc += __shfl_xor_sync(0xffffffffu, acc, 2);
        acc += __shfl_xor_sync(0xffffffffu, acc, 4);
        acc += __shfl_xor_sync(0xffffffffu, acc, 8);

        if (s == 0) {
            const float zv = zT[(size_t)d * L_SEQ + t];
            float yv = acc + xv * Dd;
            yv *= zv / (1.f + expf(-zv));
            yT[(size_t)d * L_SEQ + t] = yv;
        }
    }
}

// ---------------- host orchestration ----------------------------------------
extern "C" void kernel_launch(void* const* d_in, const int* in_sizes, int n_in,
                              void* d_out, int out_size)
{
    const float* input   = (const float*)d_in[0];
    const float* input_w = (const float*)d_in[2];
    const float* norm_w  = (const float*)d_in[3];
    const float* norm_b  = (const float*)d_in[4];
    const float* ipw     = (const float*)d_in[5];
    const float* cw      = (const float*)d_in[6];
    const float* cb      = (const float*)d_in[7];
    const float* xpw     = (const float*)d_in[8];
    const float* dtw     = (const float*)d_in[9];
    const float* dtb     = (const float*)d_in[10];
    const float* A_log   = (const float*)d_in[11];
    const float* ssm_D   = (const float*)d_in[12];
    const float* opw     = (const float*)d_in[13];

    float *res, *h, *xz, *xconv, *xdbl, *delta, *deltaT, *xcT, *zT, *yT;
    cudaGetSymbolAddress((void**)&res,    g_res);
    cudaGetSymbolAddress((void**)&h,      g_h);
    cudaGetSymbolAddress((void**)&xz,     g_xz);
    cudaGetSymbolAddress((void**)&xconv,  g_xconv);
    cudaGetSymbolAddress((void**)&xdbl,   g_xdbl);
    cudaGetSymbolAddress((void**)&delta,  g_delta);
    cudaGetSymbolAddress((void**)&deltaT, g_deltaT);
    cudaGetSymbolAddress((void**)&xcT,    g_xcT);
    cudaGetSymbolAddress((void**)&zT,     g_zT);
    cudaGetSymbolAddress((void**)&yT,     g_yT);

    bf16 *in_hi, *in_lo, *inw_hi, *inw_lo, *ipw_hi, *ipw_lo, *xpw_hi, *xpw_lo;
    bf16 *dtw_hi, *dtw_lo, *opw_hi, *opw_lo, *hn_hi, *hn_lo, *xc_hi, *xc_lo;
    bf16 *xd_hi, *xd_lo, *y_hi, *y_lo;
    cudaGetSymbolAddress((void**)&in_hi,  c_in_hi);  cudaGetSymbolAddress((void**)&in_lo,  c_in_lo);
    cudaGetSymbolAddress((void**)&inw_hi, c_inw_hi); cudaGetSymbolAddress((void**)&inw_lo, c_inw_lo);
    cudaGetSymbolAddress((void**)&ipw_hi, c_ipw_hi); cudaGetSymbolAddress((void**)&ipw_lo, c_ipw_lo);
    cudaGetSymbolAddress((void**)&xpw_hi, c_xpw_hi); cudaGetSymbolAddress((void**)&xpw_lo, c_xpw_lo);
    cudaGetSymbolAddress((void**)&dtw_hi, c_dtw_hi); cudaGetSymbolAddress((void**)&dtw_lo, c_dtw_lo);
    cudaGetSymbolAddress((void**)&opw_hi, c_opw_hi); cudaGetSymbolAddress((void**)&opw_lo, c_opw_lo);
    cudaGetSymbolAddress((void**)&hn_hi,  c_hn_hi);  cudaGetSymbolAddress((void**)&hn_lo,  c_hn_lo);
    cudaGetSymbolAddress((void**)&xc_hi,  c_xc_hi);  cudaGetSymbolAddress((void**)&xc_lo,  c_xc_lo);
    cudaGetSymbolAddress((void**)&xd_hi,  c_xd_hi);  cudaGetSymbolAddress((void**)&xd_lo,  c_xd_lo);
    cudaGetSymbolAddress((void**)&y_hi,   c_y_hi);   cudaGetSymbolAddress((void**)&y_lo,   c_y_lo);

    cudaFuncSetAttribute(mma_gemm, cudaFuncAttributeMaxDynamicSharedMemorySize, G_SMEM);

    // conversions
    cvt_kernel<<<(NLAYERS*2*DINNER*DMODEL/4 + 1023)/1024, 256>>>(
        ipw, ipw_hi, ipw_lo, NLAYERS*2*DINNER*DMODEL/4);
    cvt_kernel<<<(NLAYERS*DMODEL*DINNER/4 + 1023)/1024, 256>>>(
        opw, opw_hi, opw_lo, NLAYERS*DMODEL*DINNER/4);
    cvt4_kernel<<<(589824 + 255)/256, 256>>>(
        input,   in_hi,  in_lo,  L_SEQ*INLEN/4,
        input_w, inw_hi, inw_lo, DMODEL*INLEN/4,
        xpw,     xpw_hi, xpw_lo, NLAYERS*XDBL_W*DINNER/4,
        dtw,     dtw_hi, dtw_lo, NLAYERS*DINNER*DTRANK/4);

    // h = input @ input_w^T
    mma_gemm<<<dim3(DMODEL/128, L_SEQ/64), 256, G_SMEM>>>(
        in_hi, in_lo, INLEN, inw_hi, inw_lo, INLEN, h, DMODEL,
        DMODEL, INLEN, nullptr, 0);

    for (int i = 0; i < NLAYERS; i++) {
        resln_kernel<<<L_SEQ, 256>>>(h, res, hn_hi, hn_lo,
                                     norm_w + i*DMODEL, norm_b + i*DMODEL, i == 0);

        // xz = hn @ in_proj_w^T   (512 CTAs)
        mma_gemm<<<dim3((2*DINNER)/128, L_SEQ/64), 256, G_SMEM>>>(
            hn_hi, hn_lo, DMODEL,
            ipw_hi + (size_t)i*2*DINNER*DMODEL, ipw_lo + (size_t)i*2*DINNER*DMODEL, DMODEL,
            xz, 2*DINNER, 2*DINNER, DMODEL, nullptr, 0);

        conv_silu_kernel<<<(L_SEQ*DINNER)/256, 256>>>(
            xz, cw + (size_t)i*DINNER*4, cb + i*DINNER, xconv, xc_hi, xc_lo, xdbl);

        // x_dbl = xconv @ x_proj_w^T   split-K=8 (128 CTAs), atomic
        mma_gemm<<<dim3(1, L_SEQ/64, 8), 256, G_SMEM>>>(
            xc_hi, xc_lo, DINNER,
            xpw_hi + (size_t)i*XDBL_W*DINNER, xpw_lo + (size_t)i*XDBL_W*DINNER, DINNER,
            xdbl, XDBL_W, XDBL_W, DINNER/8, nullptr, 2);

        cvt_xdbl_kernel<<<(L_SEQ*DTRANK)/256, 256>>>(xdbl, xd_hi, xd_lo);

        // delta = softplus(xd @ dt_proj_w^T + bias)   (256 CTAs)
        mma_gemm<<<dim3(DINNER/128, L_SEQ/64), 256, G_SMEM>>>(
            xd_hi, xd_lo, DTRANK,
            dtw_hi + (size_t)i*DINNER*DTRANK, dtw_lo + (size_t)i*DINNER*DTRANK, DTRANK,
            delta, DINNER, DINNER, DTRANK, dtb + i*DINNER, 1);

        transpose3_kernel<<<dim3(DINNER/32, L_SEQ/32, 3), dim3(32, 8)>>>(
            delta, xconv, xz + DINNER, deltaT, xcT, zT);

        scan_kernel<<<DINNER, 256>>>(deltaT, xcT, zT, xdbl,
                                     A_log + (size_t)i*DINNER*DSTATE,
                                     ssm_D + i*DINNER, yT);

        // yT -> y hi/lo; zero the split-K out_proj target
        float* outp = (i == NLAYERS-1) ? (float*)d_out : h;
        ytr_kernel<<<dim3(L_SEQ/32, DINNER/32), dim3(32, 8)>>>(yT, y_hi, y_lo, outp);

        // h(next) = y @ out_proj_w^T   split-K=2 (256 CTAs), atomic
        mma_gemm<<<dim3(DMODEL/128, L_SEQ/64, 2), 256, G_SMEM>>>(
            y_hi, y_lo, DINNER,
            opw_hi + (size_t)i*DMODEL*DINNER, opw_lo + (size_t)i*DMODEL*DINNER, DINNER,
            outp, DMODEL, DMODEL, DINNER/2, nullptr, 2);
    }
}

// round 12
// speedup vs baseline: 1.3035x; 1.3035x over previous
#include <cuda_runtime.h>
#include <cuda_bf16.h>
#include <math.h>
#include <stdint.h>

#define L_SEQ   1024
#define INLEN   512
#define DMODEL  1024
#define NLAYERS 4
#define DINNER  2048
#define DSTATE  16
#define DTRANK  64
#define XDBL_W  96   // DT_RANK + 2*D_STATE

typedef __nv_bfloat16 bf16;

// ---------------- fp32 scratch ----------------------------------------------
__device__ float g_res   [L_SEQ * DMODEL];
__device__ float g_h     [L_SEQ * DMODEL];
__device__ float g_xz    [L_SEQ * 2 * DINNER];
__device__ float g_xconv [L_SEQ * DINNER];
__device__ float g_xdbl  [L_SEQ * XDBL_W];
__device__ float g_delta [L_SEQ * DINNER];
__device__ float g_deltaT[DINNER * L_SEQ];
__device__ float g_xcT   [DINNER * L_SEQ];
__device__ float g_zT    [DINNER * L_SEQ];
__device__ float g_yT    [DINNER * L_SEQ];

// ---------------- bf16 hi/lo scratch -----------------------------------------
__device__ bf16 c_in_hi [L_SEQ * INLEN],        c_in_lo [L_SEQ * INLEN];
__device__ bf16 c_inw_hi[DMODEL * INLEN],       c_inw_lo[DMODEL * INLEN];
__device__ bf16 c_ipw_hi[NLAYERS * 2*DINNER * DMODEL], c_ipw_lo[NLAYERS * 2*DINNER * DMODEL];
__device__ bf16 c_xpw_hi[NLAYERS * XDBL_W * DINNER],   c_xpw_lo[NLAYERS * XDBL_W * DINNER];
__device__ bf16 c_dtw_hi[NLAYERS * DINNER * DTRANK],   c_dtw_lo[NLAYERS * DINNER * DTRANK];
__device__ bf16 c_opw_hi[NLAYERS * DMODEL * DINNER],   c_opw_lo[NLAYERS * DMODEL * DINNER];
__device__ bf16 c_hn_hi [L_SEQ * DMODEL],       c_hn_lo [L_SEQ * DMODEL];
__device__ bf16 c_xc_hi [L_SEQ * DINNER],       c_xc_lo [L_SEQ * DINNER];
__device__ bf16 c_xd_hi [L_SEQ * DTRANK],       c_xd_lo [L_SEQ * DTRANK];
__device__ bf16 c_y_hi  [L_SEQ * DINNER],       c_y_lo  [L_SEQ * DINNER];

// ============================ PTX helpers ====================================
__device__ __forceinline__ uint32_t smem_u32(const void* p) {
    uint32_t a;
    asm("{ .reg .u64 t; cvta.to.shared.u64 t, %1; cvt.u32.u64 %0, t; }"
        : "=r"(a) : "l"(p));
    return a;
}
#define CP_ASYNC16(dst, src, sz) \
    asm volatile("cp.async.cg.shared.global [%0], [%1], 16, %2;" \
                 :: "r"(dst), "l"(src), "r"(sz))
#define CP_COMMIT() asm volatile("cp.async.commit_group;" ::: "memory")
#define CP_WAIT0()  asm volatile("cp.async.wait_group 0;" ::: "memory")

#define LDM4(r0, r1, r2, r3, addr) \
    asm volatile("ldmatrix.sync.aligned.m8n8.x4.shared.b16 {%0,%1,%2,%3}, [%4];" \
                 : "=r"(r0), "=r"(r1), "=r"(r2), "=r"(r3) : "r"(addr))

#define MMA_BF16(c, a, b)                                                      \
    asm volatile(                                                              \
        "mma.sync.aligned.m16n8k16.row.col.f32.bf16.bf16.f32 "                 \
        "{%0,%1,%2,%3}, {%4,%5,%6,%7}, {%8,%9}, {%0,%1,%2,%3};"                \
        : "+f"((c)[0]), "+f"((c)[1]), "+f"((c)[2]), "+f"((c)[3])               \
        : "r"((a)[0]), "r"((a)[1]), "r"((a)[2]), "r"((a)[3]),                  \
          "r"((b)[0]), "r"((b)[1]))

__device__ __forceinline__ uint32_t swz(uint32_t off) {
    return off ^ ((off >> 3) & 0x70);
}
__device__ __forceinline__ void split_bf16(float v, bf16& hi, bf16& lo) {
    hi = __float2bfloat16(v);
    lo = __float2bfloat16(v - __bfloat162float(hi));
}

// =============================================================================
// bf16 hi/lo split NT GEMM (3 MMAs per k16), 64x128 tile, 2-stage cp.async,
// 2 CTAs/SM.  C[m,n] = sum_k A[m,k]*B[n,k]
//   Ksplit = K per z-slice.  mode 0: store; 1: softplus(acc+bias); 2: atomicAdd
// =============================================================================
#define G_ABYTES 8192
#define G_BBYTES 16384
#define G_STAGE  (2*G_ABYTES + 2*G_BBYTES)   // 48 KB
#define G_SMEM   (2 * G_STAGE)               // 96 KB

__global__ void __launch_bounds__(256, 2)
mma_gemm(const bf16* __restrict__ Ahi, const bf16* __restrict__ Alo, int lda,
         const bf16* __restrict__ Bhi, const bf16* __restrict__ Blo, int ldb,
         float* __restrict__ C, int ldc,
         int Nvalid, int Ksplit,
         const float* __restrict__ bias, int mode)
{
    extern __shared__ char smem[];
    const uint32_t sb = smem_u32(smem);

    const int tid  = threadIdx.x;
    const int wid  = tid >> 5;
    const int lane = tid & 31;
    const int m0   = blockIdx.y * 64;
    const int n0   = blockIdx.x * 128;
    const int kbase = blockIdx.z * Ksplit;

    const int warp_m = (wid & 1) * 32;
    const int warp_n = (wid >> 1) * 32;

    float acc[2][4][4];
#pragma unroll
    for (int mt = 0; mt < 2; mt++)
#pragma unroll
        for (int nt = 0; nt < 4; nt++)
#pragma unroll
            for (int i = 0; i < 4; i++) acc[mt][nt][i] = 0.f;

    auto stage_load = [&](int c, int buf) {
        const int k0 = kbase + (c << 6);
        const uint32_t st = sb + buf * G_STAGE;
#pragma unroll
        for (int i = 0; i < 2; i++) {
            int j = tid + i * 256;
            int r = j >> 3, u = j & 7;
            uint32_t so = swz((uint32_t)(r * 128 + u * 16));
            const char* ga = (const char*)(Ahi + (size_t)(m0 + r) * lda + k0 + u * 8);
            const char* gl = (const char*)(Alo + (size_t)(m0 + r) * lda + k0 + u * 8);
            CP_ASYNC16(st + so, ga, 16);
            CP_ASYNC16(st + G_ABYTES + so, gl, 16);
        }
#pragma unroll
        for (int i = 0; i < 4; i++) {
            int j = tid + i * 256;
            int r = j >> 3, u = j & 7;
            int gn = n0 + r;
            int sz = (gn < Nvalid) ? 16 : 0;
            int gc = (gn < Nvalid) ? gn : 0;
            uint32_t so = swz((uint32_t)(r * 128 + u * 16));
            const char* gb = (const char*)(Bhi + (size_t)gc * ldb + k0 + u * 8);
            const char* gl = (const char*)(Blo + (size_t)gc * ldb + k0 + u * 8);
            CP_ASYNC16(st + 2 * G_ABYTES + so, gb, sz);
            CP_ASYNC16(st + 2 * G_ABYTES + G_BBYTES + so, gl, sz);
        }
        CP_COMMIT();
    };

    auto mma_chunk = [&](int buf) {
        const uint32_t st  = sb + buf * G_STAGE;
        const uint32_t sAh = st;
        const uint32_t sAl = st + G_ABYTES;
        const uint32_t sBh = st + 2 * G_ABYTES;
        const uint32_t sBl = sBh + G_BBYTES;
#pragma unroll
        for (int ks = 0; ks < 4; ks++) {
            const int kb = ks * 32;
            uint32_t bh[4][2], bl[4][2];
#pragma unroll
            for (int p = 0; p < 2; p++) {
                int row = warp_n + p * 16 + ((lane >> 4) << 3) + (lane & 7);
                int kbyte = kb + ((lane >> 3) & 1) * 16;
                uint32_t off = swz((uint32_t)(row * 128 + kbyte));
                LDM4(bh[2*p][0], bh[2*p][1], bh[2*p+1][0], bh[2*p+1][1], sBh + off);
                LDM4(bl[2*p][0], bl[2*p][1], bl[2*p+1][0], bl[2*p+1][1], sBl + off);
            }
#pragma unroll
            for (int mt = 0; mt < 2; mt++) {
                int row = warp_m + mt * 16 + (lane & 15);
                int kbyte = kb + (lane >> 4) * 16;
                uint32_t off = swz((uint32_t)(row * 128 + kbyte));
                uint32_t ah[4], al[4];
                LDM4(ah[0], ah[1], ah[2], ah[3], sAh + off);
                LDM4(al[0], al[1], al[2], al[3], sAl + off);
#pragma unroll
                for (int nt = 0; nt < 4; nt++) MMA_BF16(acc[mt][nt], ah, bh[nt]);
#pragma unroll
                for (int nt = 0; nt < 4; nt++) MMA_BF16(acc[mt][nt], ah, bl[nt]);
#pragma unroll
                for (int nt = 0; nt < 4; nt++) MMA_BF16(acc[mt][nt], al, bh[nt]);
            }
        }
    };

    const int NC = Ksplit >> 6;
    stage_load(0, 0);
    for (int c = 0; c < NC; c++) {
        CP_WAIT0();
        __syncthreads();
        if (c + 1 < NC) stage_load(c + 1, (c + 1) & 1);
        mma_chunk(c & 1);
    }

    // ---- epilogue ----
    const int qrow = lane >> 2;
    const int qcol = (lane & 3) * 2;
#pragma unroll
    for (int mt = 0; mt < 2; mt++) {
        int row0 = m0 + warp_m + mt * 16 + qrow;
        int row1 = row0 + 8;
#pragma unroll
        for (int nt = 0; nt < 4; nt++) {
            int gn = n0 + warp_n + nt * 8 + qcol;
            if (gn >= Nvalid) continue;
            float2 v0 = make_float2(acc[mt][nt][0], acc[mt][nt][1]);
            float2 v1 = make_float2(acc[mt][nt][2], acc[mt][nt][3]);
            if (mode == 1) {
                float b0 = bias[gn], b1 = bias[gn + 1];
                v0.x += b0; v0.y += b1; v1.x += b0; v1.y += b1;
                v0.x = (v0.x > 20.f) ? v0.x : log1pf(expf(v0.x));
                v0.y = (v0.y > 20.f) ? v0.y : log1pf(expf(v0.y));
                v1.x = (v1.x > 20.f) ? v1.x : log1pf(expf(v1.x));
                v1.y = (v1.y > 20.f) ? v1.y : log1pf(expf(v1.y));
            }
            if (mode == 2) {
                atomicAdd(&C[(size_t)row0 * ldc + gn],     v0.x);
                atomicAdd(&C[(size_t)row0 * ldc + gn + 1], v0.y);
                atomicAdd(&C[(size_t)row1 * ldc + gn],     v1.x);
                atomicAdd(&C[(size_t)row1 * ldc + gn + 1], v1.y);
            } else {
                *reinterpret_cast<float2*>(C + (size_t)row0 * ldc + gn) = v0;
                *reinterpret_cast<float2*>(C + (size_t)row1 * ldc + gn) = v1;
            }
        }
    }
}

// ---------------- fp32 -> bf16 hi/lo converters (MLP=4) ----------------------
__global__ void cvt_kernel(const float* __restrict__ src,
                           bf16* __restrict__ hi, bf16* __restrict__ lo, int n4)
{
    int base = blockIdx.x * blockDim.x * 4 + threadIdx.x;
    float4 v[4];
    int idx[4];
#pragma unroll
    for (int u = 0; u < 4; u++) {
        idx[u] = base + u * 256;
        if (idx[u] < n4) v[u] = reinterpret_cast<const float4*>(src)[idx[u]];
    }
#pragma unroll
    for (int u = 0; u < 4; u++) {
        if (idx[u] >= n4) continue;
        bf16 h0, h1, h2, h3, l0, l1, l2, l3;
        split_bf16(v[u].x, h0, l0); split_bf16(v[u].y, h1, l1);
        split_bf16(v[u].z, h2, l2); split_bf16(v[u].w, h3, l3);
        uint32_t hA = ((uint32_t)__bfloat16_as_ushort(h1) << 16) | __bfloat16_as_ushort(h0);
        uint32_t hB = ((uint32_t)__bfloat16_as_ushort(h3) << 16) | __bfloat16_as_ushort(h2);
        uint32_t lA = ((uint32_t)__bfloat16_as_ushort(l1) << 16) | __bfloat16_as_ushort(l0);
        uint32_t lB = ((uint32_t)__bfloat16_as_ushort(l3) << 16) | __bfloat16_as_ushort(l2);
        reinterpret_cast<uint2*>(hi)[idx[u]] = make_uint2(hA, hB);
        reinterpret_cast<uint2*>(lo)[idx[u]] = make_uint2(lA, lB);
    }
}

__global__ void cvt4_kernel(const float* s0, bf16* h0, bf16* l0, int n0,
                            const float* s1, bf16* h1, bf16* l1, int n1,
                            const float* s2, bf16* h2, bf16* l2, int n2,
                            const float* s3, bf16* h3, bf16* l3, int n3)
{
    int i = blockIdx.x * blockDim.x + threadIdx.x;
    const float* s; bf16 *h, *l; int j = i;
    if (j < n0)      { s = s0; h = h0; l = l0; }
    else { j -= n0;
    if (j < n1)      { s = s1; h = h1; l = l1; }
    else { j -= n1;
    if (j < n2)      { s = s2; h = h2; l = l2; }
    else { j -= n2;
    if (j < n3)      { s = s3; h = h3; l = l3; }
    else return; } } }
    float4 v = reinterpret_cast<const float4*>(s)[j];
    bf16 a0, a1, a2, a3, b0, b1, b2, b3;
    split_bf16(v.x, a0, b0); split_bf16(v.y, a1, b1);
    split_bf16(v.z, a2, b2); split_bf16(v.w, a3, b3);
    uint32_t hA = ((uint32_t)__bfloat16_as_ushort(a1) << 16) | __bfloat16_as_ushort(a0);
    uint32_t hB = ((uint32_t)__bfloat16_as_ushort(a3) << 16) | __bfloat16_as_ushort(a2);
    uint32_t lA = ((uint32_t)__bfloat16_as_ushort(b1) << 16) | __bfloat16_as_ushort(b0);
    uint32_t lB = ((uint32_t)__bfloat16_as_ushort(b3) << 16) | __bfloat16_as_ushort(b2);
    reinterpret_cast<uint2*>(h)[j] = make_uint2(hA, hB);
    reinterpret_cast<uint2*>(l)[j] = make_uint2(lA, lB);
}

__global__ void cvt_xdbl_kernel(const float* __restrict__ xdbl,
                                bf16* __restrict__ hi, bf16* __restrict__ lo)
{
    int i = blockIdx.x * blockDim.x + threadIdx.x;
    int r = i >> 6, c = i & 63;
    float v = xdbl[r * XDBL_W + c];
    bf16 h, l; split_bf16(v, h, l);
    hi[i] = h; lo[i] = l;
}

// ---------------- fused residual-add + LayerNorm ------------------------------
__global__ void resln_kernel(const float* __restrict__ hin,
                             float* __restrict__ res,
                             bf16* __restrict__ hn_hi, bf16* __restrict__ hn_lo,
                             const float* __restrict__ w,
                             const float* __restrict__ b,
                             int first)
{
    const int l   = blockIdx.x;
    const int tid = threadIdx.x;
    float v[4];
    float s = 0.f, sq = 0.f;
#pragma unroll
    for (int i = 0; i < 4; i++) {
        int c = tid + i * 256;
        float x = hin[l * DMODEL + c];
        if (!first) x += res[l * DMODEL + c];
        res[l * DMODEL + c] = x;
        v[i] = x;
        s  += x;
        sq += x * x;
    }
    __shared__ float shs[8], shq[8];
    const int lane = tid & 31, warp = tid >> 5;
#pragma unroll
    for (int o = 16; o > 0; o >>= 1) {
        s  += __shfl_xor_sync(0xffffffffu, s,  o);
        sq += __shfl_xor_sync(0xffffffffu, sq, o);
    }
    if (lane == 0) { shs[warp] = s; shq[warp] = sq; }
    __syncthreads();
    s = 0.f; sq = 0.f;
#pragma unroll
    for (int i = 0; i < 8; i++) { s += shs[i]; sq += shq[i]; }

    const float inv = 1.f / (float)DMODEL;
    const float mu  = s * inv;
    const float var = sq * inv - mu * mu;
    const float rstd = rsqrtf(var + 1e-5f);
#pragma unroll
    for (int i = 0; i < 4; i++) {
        int c = tid + i * 256;
        float o = (v[i] - mu) * rstd * w[c] + b[c];
        bf16 h, lo; split_bf16(o, h, lo);
        hn_hi[l * DMODEL + c] = h;
        hn_lo[l * DMODEL + c] = lo;
    }
}

// ---------------- conv + SiLU; zeroes xdbl for split-K atomics ---------------
__global__ void conv_silu_kernel(const float* __restrict__ xz,
                                 const float* __restrict__ cw,
                                 const float* __restrict__ cb,
                                 float* __restrict__ xconv,
                                 bf16* __restrict__ xc_hi,
                                 bf16* __restrict__ xc_lo,
                                 float* __restrict__ xdbl_zero)
{
    const int idx = blockIdx.x * blockDim.x + threadIdx.x;
    if (idx >= L_SEQ * DINNER) return;
    const int l = idx >> 11;
    const int d = idx & (DINNER - 1);

    float acc = cb[d];
    const float w0 = cw[d*4+0], w1 = cw[d*4+1], w2 = cw[d*4+2], w3 = cw[d*4+3];
    if (l >= 3) acc = fmaf(w0, xz[(size_t)(l-3) * (2*DINNER) + d], acc);
    if (l >= 2) acc = fmaf(w1, xz[(size_t)(l-2) * (2*DINNER) + d], acc);
    if (l >= 1) acc = fmaf(w2, xz[(size_t)(l-1) * (2*DINNER) + d], acc);
    acc = fmaf(w3, xz[(size_t)l * (2*DINNER) + d], acc);

    acc = acc / (1.f + expf(-acc));
    xconv[idx] = acc;
    bf16 h, lo; split_bf16(acc, h, lo);
    xc_hi[idx] = h;
    xc_lo[idx] = lo;

    if (idx < L_SEQ * XDBL_W) xdbl_zero[idx] = 0.f;
}

// ---------------- 32x32 tiled transpose: delta/xconv/z -> [d][t] -------------
__global__ void transpose3_kernel(const float* __restrict__ dsrc,
                                  const float* __restrict__ xsrc,
                                  const float* __restrict__ zsrc,
                                  float* __restrict__ dT,
                                  float* __restrict__ xT,
                                  float* __restrict__ zT)
{
    __shared__ float tile[32][33];
    const float* src; float* dst; int lds;
    if (blockIdx.z == 0)      { src = dsrc; dst = dT; lds = DINNER; }
    else if (blockIdx.z == 1) { src = xsrc; dst = xT; lds = DINNER; }
    else                      { src = zsrc; dst = zT; lds = 2 * DINNER; }
    const int c0 = blockIdx.x * 32;
    const int r0 = blockIdx.y * 32;
    const int x = threadIdx.x, y0 = threadIdx.y;
#pragma unroll
    for (int i = 0; i < 4; i++) {
        int y = y0 + i * 8;
        tile[y][x] = src[(size_t)(r0 + y) * lds + c0 + x];
    }
    __syncthreads();
#pragma unroll
    for (int i = 0; i < 4; i++) {
        int y = y0 + i * 8;
        dst[(size_t)(c0 + y) * L_SEQ + r0 + x] = tile[x][y];
    }
}

// ---------------- yT [d][t] fp32 -> y hi/lo [t][d] bf16 ----------------------
__global__ void ytr_kernel(const float* __restrict__ yT,
                           bf16* __restrict__ y_hi, bf16* __restrict__ y_lo)
{
    __shared__ float tile[32][33];
    const int c0 = blockIdx.x * 32;   // t
    const int r0 = blockIdx.y * 32;   // d
    const int x = threadIdx.x, y0 = threadIdx.y;
#pragma unroll
    for (int i = 0; i < 4; i++) {
        int y = y0 + i * 8;
        tile[y][x] = yT[(size_t)(r0 + y) * L_SEQ + c0 + x];
    }
    __syncthreads();
#pragma unroll
    for (int i = 0; i < 4; i++) {
        int y = y0 + i * 8;
        float v = tile[x][y];
        bf16 h, l; split_bf16(v, h, l);
        y_hi[(size_t)(c0 + y) * DINNER + r0 + x] = h;
        y_lo[(size_t)(c0 + y) * DINNER + r0 + x] = l;
    }
}

// =============================================================================
// Chunked parallel scan (round-8 skeleton) + smem dA cache.
// 256 threads = 16 chunks (j) x 16 states (s). Phase 1 computes dA once and
// stores it at s_dA[t*16+s]: within a warp, lanes 0-15 hit 16 consecutive
// banks, lanes 16-31 alias them (t+64 -> same bank set) => 2-way conflict,
// far cheaper than recomputing 64 exp2/thread in phase 2. Each thread reads
// back only its own entries (manual spill; no cross-thread deps).
// Dynamic smem: s_dl 4K | s_xv 4K | shP 1K | shS 1K | s_dA 64K = 74 KB
// =============================================================================
#define SCAN_SMEM ((1024 + 1024 + 256 + 256 + 16384) * 4)

__global__ void __launch_bounds__(256)
scan_kernel(const float* __restrict__ deltaT,
            const float* __restrict__ xcT,
            const float* __restrict__ zT,
            const float* __restrict__ xdbl,
            const float* __restrict__ A_log,
            const float* __restrict__ Dvec,
            float* __restrict__ yT)
{
    extern __shared__ float sm[];
    float* s_dl = sm;                    // [1024]
    float* s_xv = sm + 1024;             // [1024]
    float* shP  = sm + 2048;             // [16][16]
    float* shS  = sm + 2304;             // [16][16]
    float* s_dA = sm + 2560;             // [1024][16]

    const int d    = blockIdx.x;
    const int tid  = threadIdx.x;
    const int lane = tid & 31;
    const int wrp  = tid >> 5;
    const int j    = wrp * 2 + (lane >> 4);
    const int s    = lane & 15;
    const int t0   = j * 64;

    for (int i = tid; i < L_SEQ; i += 256) {
        s_dl[i] = deltaT[(size_t)d * L_SEQ + i];
        s_xv[i] = xcT[(size_t)d * L_SEQ + i];
    }
    __syncthreads();

    const float a2 = -expf(A_log[d * DSTATE + s]) * 1.4426950408889634f;

    // ---- phase 1: compute dA once, cache in smem (2-way conflict layout) ----
    float P = 1.f, S = 0.f;
#pragma unroll 4
    for (int k = 0; k < 64; k++) {
        const int t = t0 + k;
        const float dl = s_dl[t];
        const float Bs = xdbl[t * XDBL_W + DTRANK + s];
        const float dA = exp2f(dl * a2);
        s_dA[t * 16 + s] = dA;
        P *= dA;
        S = fmaf(dA, S, dl * s_xv[t] * Bs);
    }
    shP[j * 16 + s] = P;
    shS[j * 16 + s] = S;
    __syncthreads();

    // ---- combine: serial prefix over 16 chunks, one thread per state ----
    if (tid < 16) {
        const int ss = tid;
        float run = shS[ss];
#pragma unroll
        for (int jj = 1; jj < 16; jj++) {
            run = fmaf(shP[jj * 16 + ss], run, shS[jj * 16 + ss]);
            shS[jj * 16 + ss] = run;
        }
    }
    __syncthreads();

    // ---- phase 2: rescan with corrected h0, reusing cached dA ----
    float h = (j == 0) ? 0.f : shS[(j - 1) * 16 + s];
    const float Dd = Dvec[d];
#pragma unroll 4
    for (int k = 0; k < 64; k++) {
        const int t = t0 + k;
        const float dl = s_dl[t];
        const float xv = s_xv[t];
        const float Bs = xdbl[t * XDBL_W + DTRANK + s];
        const float Cs = xdbl[t * XDBL_W + DTRANK + DSTATE + s];
        h = fmaf(s_dA[t * 16 + s], h, dl * xv * Bs);

        float acc = h * Cs;
        acc += __shfl_xor_sync(0xffffffffu, acc, 1);
        acc += __shfl_xor_sync(0xffffffffu, acc, 2);
        acc += __shfl_xor_sync(0xffffffffu, acc, 4);
        acc += __shfl_xor_sync(0xffffffffu, acc, 8);

        if (s == 0) {
            const float zv = zT[(size_t)d * L_SEQ + t];
            float yv = acc + xv * Dd;
            yv *= zv / (1.f + expf(-zv));
            yT[(size_t)d * L_SEQ + t] = yv;
        }
    }
}

// ---------------- host orchestration ----------------------------------------
extern "C" void kernel_launch(void* const* d_in, const int* in_sizes, int n_in,
                              void* d_out, int out_size)
{
    const float* input   = (const float*)d_in[0];
    const float* input_w = (const float*)d_in[2];
    const float* norm_w  = (const float*)d_in[3];
    const float* norm_b  = (const float*)d_in[4];
    const float* ipw     = (const float*)d_in[5];
    const float* cw      = (const float*)d_in[6];
    const float* cb      = (const float*)d_in[7];
    const float* xpw     = (const float*)d_in[8];
    const float* dtw     = (const float*)d_in[9];
    const float* dtb     = (const float*)d_in[10];
    const float* A_log   = (const float*)d_in[11];
    const float* ssm_D   = (const float*)d_in[12];
    const float* opw     = (const float*)d_in[13];

    float *res, *h, *xz, *xconv, *xdbl, *delta, *deltaT, *xcT, *zT, *yT;
    cudaGetSymbolAddress((void**)&res,    g_res);
    cudaGetSymbolAddress((void**)&h,      g_h);
    cudaGetSymbolAddress((void**)&xz,     g_xz);
    cudaGetSymbolAddress((void**)&xconv,  g_xconv);
    cudaGetSymbolAddress((void**)&xdbl,   g_xdbl);
    cudaGetSymbolAddress((void**)&delta,  g_delta);
    cudaGetSymbolAddress((void**)&deltaT, g_deltaT);
    cudaGetSymbolAddress((void**)&xcT,    g_xcT);
    cudaGetSymbolAddress((void**)&zT,     g_zT);
    cudaGetSymbolAddress((void**)&yT,     g_yT);

    bf16 *in_hi, *in_lo, *inw_hi, *inw_lo, *ipw_hi, *ipw_lo, *xpw_hi, *xpw_lo;
    bf16 *dtw_hi, *dtw_lo, *opw_hi, *opw_lo, *hn_hi, *hn_lo, *xc_hi, *xc_lo;
    bf16 *xd_hi, *xd_lo, *y_hi, *y_lo;
    cudaGetSymbolAddress((void**)&in_hi,  c_in_hi);  cudaGetSymbolAddress((void**)&in_lo,  c_in_lo);
    cudaGetSymbolAddress((void**)&inw_hi, c_inw_hi); cudaGetSymbolAddress((void**)&inw_lo, c_inw_lo);
    cudaGetSymbolAddress((void**)&ipw_hi, c_ipw_hi); cudaGetSymbolAddress((void**)&ipw_lo, c_ipw_lo);
    cudaGetSymbolAddress((void**)&xpw_hi, c_xpw_hi); cudaGetSymbolAddress((void**)&xpw_lo, c_xpw_lo);
    cudaGetSymbolAddress((void**)&dtw_hi, c_dtw_hi); cudaGetSymbolAddress((void**)&dtw_lo, c_dtw_lo);
    cudaGetSymbolAddress((void**)&opw_hi, c_opw_hi); cudaGetSymbolAddress((void**)&opw_lo, c_opw_lo);
    cudaGetSymbolAddress((void**)&hn_hi,  c_hn_hi);  cudaGetSymbolAddress((void**)&hn_lo,  c_hn_lo);
    cudaGetSymbolAddress((void**)&xc_hi,  c_xc_hi);  cudaGetSymbolAddress((void**)&xc_lo,  c_xc_lo);
    cudaGetSymbolAddress((void**)&xd_hi,  c_xd_hi);  cudaGetSymbolAddress((void**)&xd_lo,  c_xd_lo);
    cudaGetSymbolAddress((void**)&y_hi,   c_y_hi);   cudaGetSymbolAddress((void**)&y_lo,   c_y_lo);

    cudaFuncSetAttribute(mma_gemm, cudaFuncAttributeMaxDynamicSharedMemorySize, G_SMEM);
    cudaFuncSetAttribute(scan_kernel, cudaFuncAttributeMaxDynamicSharedMemorySize, SCAN_SMEM);

    // conversions
    cvt_kernel<<<(NLAYERS*2*DINNER*DMODEL/4 + 1023)/1024, 256>>>(
        ipw, ipw_hi, ipw_lo, NLAYERS*2*DINNER*DMODEL/4);
    cvt_kernel<<<(NLAYERS*DMODEL*DINNER/4 + 1023)/1024, 256>>>(
        opw, opw_hi, opw_lo, NLAYERS*DMODEL*DINNER/4);
    cvt4_kernel<<<(589824 + 255)/256, 256>>>(
        input,   in_hi,  in_lo,  L_SEQ*INLEN/4,
        input_w, inw_hi, inw_lo, DMODEL*INLEN/4,
        xpw,     xpw_hi, xpw_lo, NLAYERS*XDBL_W*DINNER/4,
        dtw,     dtw_hi, dtw_lo, NLAYERS*DINNER*DTRANK/4);

    // h = input @ input_w^T
    mma_gemm<<<dim3(DMODEL/128, L_SEQ/64), 256, G_SMEM>>>(
        in_hi, in_lo, INLEN, inw_hi, inw_lo, INLEN, h, DMODEL,
        DMODEL, INLEN, nullptr, 0);

    for (int i = 0; i < NLAYERS; i++) {
        resln_kernel<<<L_SEQ, 256>>>(h, res, hn_hi, hn_lo,
                                     norm_w + i*DMODEL, norm_b + i*DMODEL, i == 0);

        // xz = hn @ in_proj_w^T   (512 CTAs)
        mma_gemm<<<dim3((2*DINNER)/128, L_SEQ/64), 256, G_SMEM>>>(
            hn_hi, hn_lo, DMODEL,
            ipw_hi + (size_t)i*2*DINNER*DMODEL, ipw_lo + (size_t)i*2*DINNER*DMODEL, DMODEL,
            xz, 2*DINNER, 2*DINNER, DMODEL, nullptr, 0);

        conv_silu_kernel<<<(L_SEQ*DINNER)/256, 256>>>(
            xz, cw + (size_t)i*DINNER*4, cb + i*DINNER, xconv, xc_hi, xc_lo, xdbl);

        // x_dbl = xconv @ x_proj_w^T   split-K=8 (128 CTAs), atomic
        mma_gemm<<<dim3(1, L_SEQ/64, 8), 256, G_SMEM>>>(
            xc_hi, xc_lo, DINNER,
            xpw_hi + (size_t)i*XDBL_W*DINNER, xpw_lo + (size_t)i*XDBL_W*DINNER, DINNER,
            xdbl, XDBL_W, XDBL_W, DINNER/8, nullptr, 2);

        cvt_xdbl_kernel<<<(L_SEQ*DTRANK)/256, 256>>>(xdbl, xd_hi, xd_lo);

        // delta = softplus(xd @ dt_proj_w^T + bias)   (256 CTAs)
        mma_gemm<<<dim3(DINNER/128, L_SEQ/64), 256, G_SMEM>>>(
            xd_hi, xd_lo, DTRANK,
            dtw_hi + (size_t)i*DINNER*DTRANK, dtw_lo + (size_t)i*DINNER*DTRANK, DTRANK,
            delta, DINNER, DINNER, DTRANK, dtb + i*DINNER, 1);

        transpose3_kernel<<<dim3(DINNER/32, L_SEQ/32, 3), dim3(32, 8)>>>(
            delta, xconv, xz + DINNER, deltaT, xcT, zT);

        scan_kernel<<<DINNER, 256, SCAN_SMEM>>>(deltaT, xcT, zT, xdbl,
                                                A_log + (size_t)i*DINNER*DSTATE,
                                                ssm_D + i*DINNER, yT);

        ytr_kernel<<<dim3(L_SEQ/32, DINNER/32), dim3(32, 8)>>>(yT, y_hi, y_lo);

        // h(next) = y @ out_proj_w^T   (128 CTAs, direct store — round-8 form)
        float* outp = (i == NLAYERS-1) ? (float*)d_out : h;
        mma_gemm<<<dim3(DMODEL/128, L_SEQ/64), 256, G_SMEM>>>(
            y_hi, y_lo, DINNER,
            opw_hi + (size_t)i*DMODEL*DINNER, opw_lo + (size_t)i*DMODEL*DINNER, DINNER,
            outp, DMODEL, DMODEL, DINNER, nullptr, 0);
    }
}

// round 13
// speedup vs baseline: 1.6779x; 1.2872x over previous
#include <cuda_runtime.h>
#include <cuda_bf16.h>
#include <math.h>
#include <stdint.h>

#define L_SEQ   1024
#define INLEN   512
#define DMODEL  1024
#define NLAYERS 4
#define DINNER  2048
#define DSTATE  16
#define DTRANK  64
#define XDBL_W  96   // DT_RANK + 2*D_STATE

typedef __nv_bfloat16 bf16;

// ---------------- fp32 scratch ----------------------------------------------
__device__ float g_res   [L_SEQ * DMODEL];
__device__ float g_h     [L_SEQ * DMODEL];
__device__ float g_xz    [L_SEQ * 2 * DINNER];
__device__ float g_xconv [L_SEQ * DINNER];
__device__ float g_xdbl  [L_SEQ * XDBL_W];
__device__ float g_delta [L_SEQ * DINNER];
__device__ float g_deltaT[DINNER * L_SEQ];
__device__ float g_xcT   [DINNER * L_SEQ];
__device__ float g_zT    [DINNER * L_SEQ];
__device__ float g_yT    [DINNER * L_SEQ];

// ---------------- bf16 hi/lo scratch -----------------------------------------
__device__ bf16 c_in_hi [L_SEQ * INLEN],        c_in_lo [L_SEQ * INLEN];
__device__ bf16 c_inw_hi[DMODEL * INLEN],       c_inw_lo[DMODEL * INLEN];
__device__ bf16 c_ipw_hi[NLAYERS * 2*DINNER * DMODEL], c_ipw_lo[NLAYERS * 2*DINNER * DMODEL];
__device__ bf16 c_xpw_hi[NLAYERS * XDBL_W * DINNER],   c_xpw_lo[NLAYERS * XDBL_W * DINNER];
__device__ bf16 c_dtw_hi[NLAYERS * DINNER * DTRANK],   c_dtw_lo[NLAYERS * DINNER * DTRANK];
__device__ bf16 c_opw_hi[NLAYERS * DMODEL * DINNER],   c_opw_lo[NLAYERS * DMODEL * DINNER];
__device__ bf16 c_hn_hi [L_SEQ * DMODEL],       c_hn_lo [L_SEQ * DMODEL];
__device__ bf16 c_xc_hi [L_SEQ * DINNER],       c_xc_lo [L_SEQ * DINNER];
__device__ bf16 c_xd_hi [L_SEQ * DTRANK],       c_xd_lo [L_SEQ * DTRANK];
__device__ bf16 c_y_hi  [L_SEQ * DINNER],       c_y_lo  [L_SEQ * DINNER];

// ============================ PTX helpers ====================================
__device__ __forceinline__ uint32_t smem_u32(const void* p) {
    uint32_t a;
    asm("{ .reg .u64 t; cvta.to.shared.u64 t, %1; cvt.u32.u64 %0, t; }"
        : "=r"(a) : "l"(p));
    return a;
}
#define CP_ASYNC16(dst, src, sz) \
    asm volatile("cp.async.cg.shared.global [%0], [%1], 16, %2;" \
                 :: "r"(dst), "l"(src), "r"(sz))
#define CP_COMMIT() asm volatile("cp.async.commit_group;" ::: "memory")
#define CP_WAIT0()  asm volatile("cp.async.wait_group 0;" ::: "memory")

#define LDM4(r0, r1, r2, r3, addr) \
    asm volatile("ldmatrix.sync.aligned.m8n8.x4.shared.b16 {%0,%1,%2,%3}, [%4];" \
                 : "=r"(r0), "=r"(r1), "=r"(r2), "=r"(r3) : "r"(addr))

#define MMA_BF16(c, a, b)                                                      \
    asm volatile(                                                              \
        "mma.sync.aligned.m16n8k16.row.col.f32.bf16.bf16.f32 "                 \
        "{%0,%1,%2,%3}, {%4,%5,%6,%7}, {%8,%9}, {%0,%1,%2,%3};"                \
        : "+f"((c)[0]), "+f"((c)[1]), "+f"((c)[2]), "+f"((c)[3])               \
        : "r"((a)[0]), "r"((a)[1]), "r"((a)[2]), "r"((a)[3]),                  \
          "r"((b)[0]), "r"((b)[1]))

__device__ __forceinline__ uint32_t swz(uint32_t off) {
    return off ^ ((off >> 3) & 0x70);
}
__device__ __forceinline__ void split_bf16(float v, bf16& hi, bf16& lo) {
    hi = __float2bfloat16(v);
    lo = __float2bfloat16(v - __bfloat162float(hi));
}

// =============================================================================
// bf16 hi/lo split NT GEMM (3 MMAs per k16), 64x128 tile, 2-stage cp.async,
// 2 CTAs/SM.  C[m,n] = sum_k A[m,k]*B[n,k]
//   Ksplit = K per z-slice.  mode 0: store; 1: softplus(acc+bias); 2: atomicAdd
// =============================================================================
#define G_ABYTES 8192
#define G_BBYTES 16384
#define G_STAGE  (2*G_ABYTES + 2*G_BBYTES)   // 48 KB
#define G_SMEM   (2 * G_STAGE)               // 96 KB

__global__ void __launch_bounds__(256, 2)
mma_gemm(const bf16* __restrict__ Ahi, const bf16* __restrict__ Alo, int lda,
         const bf16* __restrict__ Bhi, const bf16* __restrict__ Blo, int ldb,
         float* __restrict__ C, int ldc,
         int Nvalid, int Ksplit,
         const float* __restrict__ bias, int mode)
{
    extern __shared__ char smem[];
    const uint32_t sb = smem_u32(smem);

    const int tid  = threadIdx.x;
    const int wid  = tid >> 5;
    const int lane = tid & 31;
    const int m0   = blockIdx.y * 64;
    const int n0   = blockIdx.x * 128;
    const int kbase = blockIdx.z * Ksplit;

    const int warp_m = (wid & 1) * 32;
    const int warp_n = (wid >> 1) * 32;

    float acc[2][4][4];
#pragma unroll
    for (int mt = 0; mt < 2; mt++)
#pragma unroll
        for (int nt = 0; nt < 4; nt++)
#pragma unroll
            for (int i = 0; i < 4; i++) acc[mt][nt][i] = 0.f;

    auto stage_load = [&](int c, int buf) {
        const int k0 = kbase + (c << 6);
        const uint32_t st = sb + buf * G_STAGE;
#pragma unroll
        for (int i = 0; i < 2; i++) {
            int j = tid + i * 256;
            int r = j >> 3, u = j & 7;
            uint32_t so = swz((uint32_t)(r * 128 + u * 16));
            const char* ga = (const char*)(Ahi + (size_t)(m0 + r) * lda + k0 + u * 8);
            const char* gl = (const char*)(Alo + (size_t)(m0 + r) * lda + k0 + u * 8);
            CP_ASYNC16(st + so, ga, 16);
            CP_ASYNC16(st + G_ABYTES + so, gl, 16);
        }
#pragma unroll
        for (int i = 0; i < 4; i++) {
            int j = tid + i * 256;
            int r = j >> 3, u = j & 7;
            int gn = n0 + r;
            int sz = (gn < Nvalid) ? 16 : 0;
            int gc = (gn < Nvalid) ? gn : 0;
            uint32_t so = swz((uint32_t)(r * 128 + u * 16));
            const char* gb = (const char*)(Bhi + (size_t)gc * ldb + k0 + u * 8);
            const char* gl = (const char*)(Blo + (size_t)gc * ldb + k0 + u * 8);
            CP_ASYNC16(st + 2 * G_ABYTES + so, gb, sz);
            CP_ASYNC16(st + 2 * G_ABYTES + G_BBYTES + so, gl, sz);
        }
        CP_COMMIT();
    };

    auto mma_chunk = [&](int buf) {
        const uint32_t st  = sb + buf * G_STAGE;
        const uint32_t sAh = st;
        const uint32_t sAl = st + G_ABYTES;
        const uint32_t sBh = st + 2 * G_ABYTES;
        const uint32_t sBl = sBh + G_BBYTES;
#pragma unroll
        for (int ks = 0; ks < 4; ks++) {
            const int kb = ks * 32;
            uint32_t bh[4][2], bl[4][2];
#pragma unroll
            for (int p = 0; p < 2; p++) {
                int row = warp_n + p * 16 + ((lane >> 4) << 3) + (lane & 7);
                int kbyte = kb + ((lane >> 3) & 1) * 16;
                uint32_t off = swz((uint32_t)(row * 128 + kbyte));
                LDM4(bh[2*p][0], bh[2*p][1], bh[2*p+1][0], bh[2*p+1][1], sBh + off);
                LDM4(bl[2*p][0], bl[2*p][1], bl[2*p+1][0], bl[2*p+1][1], sBl + off);
            }
#pragma unroll
            for (int mt = 0; mt < 2; mt++) {
                int row = warp_m + mt * 16 + (lane & 15);
                int kbyte = kb + (lane >> 4) * 16;
                uint32_t off = swz((uint32_t)(row * 128 + kbyte));
                uint32_t ah[4], al[4];
                LDM4(ah[0], ah[1], ah[2], ah[3], sAh + off);
                LDM4(al[0], al[1], al[2], al[3], sAl + off);
#pragma unroll
                for (int nt = 0; nt < 4; nt++) MMA_BF16(acc[mt][nt], ah, bh[nt]);
#pragma unroll
                for (int nt = 0; nt < 4; nt++) MMA_BF16(acc[mt][nt], ah, bl[nt]);
#pragma unroll
                for (int nt = 0; nt < 4; nt++) MMA_BF16(acc[mt][nt], al, bh[nt]);
            }
        }
    };

    const int NC = Ksplit >> 6;
    stage_load(0, 0);
    for (int c = 0; c < NC; c++) {
        CP_WAIT0();
        __syncthreads();
        if (c + 1 < NC) stage_load(c + 1, (c + 1) & 1);
        mma_chunk(c & 1);
    }

    // ---- epilogue ----
    const int qrow = lane >> 2;
    const int qcol = (lane & 3) * 2;
#pragma unroll
    for (int mt = 0; mt < 2; mt++) {
        int row0 = m0 + warp_m + mt * 16 + qrow;
        int row1 = row0 + 8;
#pragma unroll
        for (int nt = 0; nt < 4; nt++) {
            int gn = n0 + warp_n + nt * 8 + qcol;
            if (gn >= Nvalid) continue;
            float2 v0 = make_float2(acc[mt][nt][0], acc[mt][nt][1]);
            float2 v1 = make_float2(acc[mt][nt][2], acc[mt][nt][3]);
            if (mode == 1) {
                float b0 = bias[gn], b1 = bias[gn + 1];
                v0.x += b0; v0.y += b1; v1.x += b0; v1.y += b1;
                v0.x = (v0.x > 20.f) ? v0.x : log1pf(expf(v0.x));
                v0.y = (v0.y > 20.f) ? v0.y : log1pf(expf(v0.y));
                v1.x = (v1.x > 20.f) ? v1.x : log1pf(expf(v1.x));
                v1.y = (v1.y > 20.f) ? v1.y : log1pf(expf(v1.y));
            }
            if (mode == 2) {
                atomicAdd(&C[(size_t)row0 * ldc + gn],     v0.x);
                atomicAdd(&C[(size_t)row0 * ldc + gn + 1], v0.y);
                atomicAdd(&C[(size_t)row1 * ldc + gn],     v1.x);
                atomicAdd(&C[(size_t)row1 * ldc + gn + 1], v1.y);
            } else {
                *reinterpret_cast<float2*>(C + (size_t)row0 * ldc + gn) = v0;
                *reinterpret_cast<float2*>(C + (size_t)row1 * ldc + gn) = v1;
            }
        }
    }
}

// ---------------- fp32 -> bf16 hi/lo converters (MLP=4) ----------------------
__global__ void cvt_kernel(const float* __restrict__ src,
                           bf16* __restrict__ hi, bf16* __restrict__ lo, int n4)
{
    int base = blockIdx.x * blockDim.x * 4 + threadIdx.x;
    float4 v[4];
    int idx[4];
#pragma unroll
    for (int u = 0; u < 4; u++) {
        idx[u] = base + u * 256;
        if (idx[u] < n4) v[u] = reinterpret_cast<const float4*>(src)[idx[u]];
    }
#pragma unroll
    for (int u = 0; u < 4; u++) {
        if (idx[u] >= n4) continue;
        bf16 h0, h1, h2, h3, l0, l1, l2, l3;
        split_bf16(v[u].x, h0, l0); split_bf16(v[u].y, h1, l1);
        split_bf16(v[u].z, h2, l2); split_bf16(v[u].w, h3, l3);
        uint32_t hA = ((uint32_t)__bfloat16_as_ushort(h1) << 16) | __bfloat16_as_ushort(h0);
        uint32_t hB = ((uint32_t)__bfloat16_as_ushort(h3) << 16) | __bfloat16_as_ushort(h2);
        uint32_t lA = ((uint32_t)__bfloat16_as_ushort(l1) << 16) | __bfloat16_as_ushort(l0);
        uint32_t lB = ((uint32_t)__bfloat16_as_ushort(l3) << 16) | __bfloat16_as_ushort(l2);
        reinterpret_cast<uint2*>(hi)[idx[u]] = make_uint2(hA, hB);
        reinterpret_cast<uint2*>(lo)[idx[u]] = make_uint2(lA, lB);
    }
}

__global__ void cvt4_kernel(const float* s0, bf16* h0, bf16* l0, int n0,
                            const float* s1, bf16* h1, bf16* l1, int n1,
                            const float* s2, bf16* h2, bf16* l2, int n2,
                            const float* s3, bf16* h3, bf16* l3, int n3)
{
    int i = blockIdx.x * blockDim.x + threadIdx.x;
    const float* s; bf16 *h, *l; int j = i;
    if (j < n0)      { s = s0; h = h0; l = l0; }
    else { j -= n0;
    if (j < n1)      { s = s1; h = h1; l = l1; }
    else { j -= n1;
    if (j < n2)      { s = s2; h = h2; l = l2; }
    else { j -= n2;
    if (j < n3)      { s = s3; h = h3; l = l3; }
    else return; } } }
    float4 v = reinterpret_cast<const float4*>(s)[j];
    bf16 a0, a1, a2, a3, b0, b1, b2, b3;
    split_bf16(v.x, a0, b0); split_bf16(v.y, a1, b1);
    split_bf16(v.z, a2, b2); split_bf16(v.w, a3, b3);
    uint32_t hA = ((uint32_t)__bfloat16_as_ushort(a1) << 16) | __bfloat16_as_ushort(a0);
    uint32_t hB = ((uint32_t)__bfloat16_as_ushort(a3) << 16) | __bfloat16_as_ushort(a2);
    uint32_t lA = ((uint32_t)__bfloat16_as_ushort(b1) << 16) | __bfloat16_as_ushort(b0);
    uint32_t lB = ((uint32_t)__bfloat16_as_ushort(b3) << 16) | __bfloat16_as_ushort(b2);
    reinterpret_cast<uint2*>(h)[j] = make_uint2(hA, hB);
    reinterpret_cast<uint2*>(l)[j] = make_uint2(lA, lB);
}

__global__ void cvt_xdbl_kernel(const float* __restrict__ xdbl,
                                bf16* __restrict__ hi, bf16* __restrict__ lo)
{
    int i = blockIdx.x * blockDim.x + threadIdx.x;
    int r = i >> 6, c = i & 63;
    float v = xdbl[r * XDBL_W + c];
    bf16 h, l; split_bf16(v, h, l);
    hi[i] = h; lo[i] = l;
}

// ---------------- fused residual-add + LayerNorm ------------------------------
__global__ void resln_kernel(const float* __restrict__ hin,
                             float* __restrict__ res,
                             bf16* __restrict__ hn_hi, bf16* __restrict__ hn_lo,
                             const float* __restrict__ w,
                             const float* __restrict__ b,
                             int first)
{
    const int l   = blockIdx.x;
    const int tid = threadIdx.x;
    float v[4];
    float s = 0.f, sq = 0.f;
#pragma unroll
    for (int i = 0; i < 4; i++) {
        int c = tid + i * 256;
        float x = hin[l * DMODEL + c];
        if (!first) x += res[l * DMODEL + c];
        res[l * DMODEL + c] = x;
        v[i] = x;
        s  += x;
        sq += x * x;
    }
    __shared__ float shs[8], shq[8];
    const int lane = tid & 31, warp = tid >> 5;
#pragma unroll
    for (int o = 16; o > 0; o >>= 1) {
        s  += __shfl_xor_sync(0xffffffffu, s,  o);
        sq += __shfl_xor_sync(0xffffffffu, sq, o);
    }
    if (lane == 0) { shs[warp] = s; shq[warp] = sq; }
    __syncthreads();
    s = 0.f; sq = 0.f;
#pragma unroll
    for (int i = 0; i < 8; i++) { s += shs[i]; sq += shq[i]; }

    const float inv = 1.f / (float)DMODEL;
    const float mu  = s * inv;
    const float var = sq * inv - mu * mu;
    const float rstd = rsqrtf(var + 1e-5f);
#pragma unroll
    for (int i = 0; i < 4; i++) {
        int c = tid + i * 256;
        float o = (v[i] - mu) * rstd * w[c] + b[c];
        bf16 h, lo; split_bf16(o, h, lo);
        hn_hi[l * DMODEL + c] = h;
        hn_lo[l * DMODEL + c] = lo;
    }
}

// ---------------- conv + SiLU; zeroes xdbl for split-K atomics ---------------
__global__ void conv_silu_kernel(const float* __restrict__ xz,
                                 const float* __restrict__ cw,
                                 const float* __restrict__ cb,
                                 float* __restrict__ xconv,
                                 bf16* __restrict__ xc_hi,
                                 bf16* __restrict__ xc_lo,
                                 float* __restrict__ xdbl_zero)
{
    const int idx = blockIdx.x * blockDim.x + threadIdx.x;
    if (idx >= L_SEQ * DINNER) return;
    const int l = idx >> 11;
    const int d = idx & (DINNER - 1);

    float acc = cb[d];
    const float w0 = cw[d*4+0], w1 = cw[d*4+1], w2 = cw[d*4+2], w3 = cw[d*4+3];
    if (l >= 3) acc = fmaf(w0, xz[(size_t)(l-3) * (2*DINNER) + d], acc);
    if (l >= 2) acc = fmaf(w1, xz[(size_t)(l-2) * (2*DINNER) + d], acc);
    if (l >= 1) acc = fmaf(w2, xz[(size_t)(l-1) * (2*DINNER) + d], acc);
    acc = fmaf(w3, xz[(size_t)l * (2*DINNER) + d], acc);

    acc = acc / (1.f + expf(-acc));
    xconv[idx] = acc;
    bf16 h, lo; split_bf16(acc, h, lo);
    xc_hi[idx] = h;
    xc_lo[idx] = lo;

    if (idx < L_SEQ * XDBL_W) xdbl_zero[idx] = 0.f;
}

// ---------------- 32x32 tiled transpose: delta/xconv/z -> [d][t] -------------
__global__ void transpose3_kernel(const float* __restrict__ dsrc,
                                  const float* __restrict__ xsrc,
                                  const float* __restrict__ zsrc,
                                  float* __restrict__ dT,
                                  float* __restrict__ xT,
                                  float* __restrict__ zT)
{
    __shared__ float tile[32][33];
    const float* src; float* dst; int lds;
    if (blockIdx.z == 0)      { src = dsrc; dst = dT; lds = DINNER; }
    else if (blockIdx.z == 1) { src = xsrc; dst = xT; lds = DINNER; }
    else                      { src = zsrc; dst = zT; lds = 2 * DINNER; }
    const int c0 = blockIdx.x * 32;
    const int r0 = blockIdx.y * 32;
    const int x = threadIdx.x, y0 = threadIdx.y;
#pragma unroll
    for (int i = 0; i < 4; i++) {
        int y = y0 + i * 8;
        tile[y][x] = src[(size_t)(r0 + y) * lds + c0 + x];
    }
    __syncthreads();
#pragma unroll
    for (int i = 0; i < 4; i++) {
        int y = y0 + i * 8;
        dst[(size_t)(c0 + y) * L_SEQ + r0 + x] = tile[x][y];
    }
}

// ---------------- yT [d][t] -> y hi/lo [t][d]; zeroes out_proj target --------
__global__ void ytr_kernel(const float* __restrict__ yT,
                           bf16* __restrict__ y_hi, bf16* __restrict__ y_lo,
                           float* __restrict__ zero_buf)
{
    // zero split-K out_proj target: 2048 CTAs x 256 flat threads x 2 floats
    {
        int flat = threadIdx.y * 32 + threadIdx.x;
        int zi = (blockIdx.y * gridDim.x + blockIdx.x) * 256 + flat;
        if (zi * 2 < L_SEQ * DMODEL)
            *reinterpret_cast<float2*>(zero_buf + zi * 2) = make_float2(0.f, 0.f);
    }
    __shared__ float tile[32][33];
    const int c0 = blockIdx.x * 32;   // t
    const int r0 = blockIdx.y * 32;   // d
    const int x = threadIdx.x, y0 = threadIdx.y;
#pragma unroll
    for (int i = 0; i < 4; i++) {
        int y = y0 + i * 8;
        tile[y][x] = yT[(size_t)(r0 + y) * L_SEQ + c0 + x];
    }
    __syncthreads();
#pragma unroll
    for (int i = 0; i < 4; i++) {
        int y = y0 + i * 8;
        float v = tile[x][y];
        bf16 h, l; split_bf16(v, h, l);
        y_hi[(size_t)(c0 + y) * DINNER + r0 + x] = h;
        y_lo[(size_t)(c0 + y) * DINNER + r0 + x] = l;
    }
}

// =============================================================================
// Chunked parallel scan — ROUND-8 FORM (static 10 KB smem, high occupancy;
// exp2 recomputed in phase 2: occupancy hides it, caches never paid off).
// 256 threads = 16 chunks (j) x 16 states (s).
// =============================================================================
__global__ void __launch_bounds__(256)
scan_kernel(const float* __restrict__ deltaT,
            const float* __restrict__ xcT,
            const float* __restrict__ zT,
            const float* __restrict__ xdbl,
            const float* __restrict__ A_log,
            const float* __restrict__ Dvec,
            float* __restrict__ yT)
{
    __shared__ float s_dl[L_SEQ];
    __shared__ float s_xv[L_SEQ];
    __shared__ float shP[16][16];
    __shared__ float shS[16][16];

    const int d    = blockIdx.x;
    const int tid  = threadIdx.x;
    const int lane = tid & 31;
    const int wrp  = tid >> 5;
    const int j    = wrp * 2 + (lane >> 4);
    const int s    = lane & 15;
    const int t0   = j * 64;

    for (int i = tid; i < L_SEQ; i += 256) {
        s_dl[i] = deltaT[(size_t)d * L_SEQ + i];
        s_xv[i] = xcT[(size_t)d * L_SEQ + i];
    }
    __syncthreads();

    const float a2 = -expf(A_log[d * DSTATE + s]) * 1.4426950408889634f;

    // ---- phase 1 ----
    float P = 1.f, S = 0.f;
#pragma unroll 4
    for (int k = 0; k < 64; k++) {
        const int t = t0 + k;
        const float dl = s_dl[t];
        const float Bs = xdbl[t * XDBL_W + DTRANK + s];
        const float dA = exp2f(dl * a2);
        P *= dA;
        S = fmaf(dA, S, dl * s_xv[t] * Bs);
    }
    shP[j][s] = P;
    shS[j][s] = S;
    __syncthreads();

    // ---- combine ----
    if (tid < 16) {
        const int ss = tid;
        float run = shS[0][ss];
#pragma unroll
        for (int jj = 1; jj < 16; jj++) {
            run = fmaf(shP[jj][ss], run, shS[jj][ss]);
            shS[jj][ss] = run;
        }
    }
    __syncthreads();

    // ---- phase 2 ----
    float h = (j == 0) ? 0.f : shS[j - 1][s];
    const float Dd = Dvec[d];
#pragma unroll 4
    for (int k = 0; k < 64; k++) {
        const int t = t0 + k;
        const float dl = s_dl[t];
        const float xv = s_xv[t];
        const float Bs = xdbl[t * XDBL_W + DTRANK + s];
        const float Cs = xdbl[t * XDBL_W + DTRANK + DSTATE + s];
        const float dA = exp2f(dl * a2);
        h = fmaf(dA, h, dl * xv * Bs);

        float acc = h * Cs;
        acc += __shfl_xor_sync(0xffffffffu, acc, 1);
        acc += __shfl_xor_sync(0xffffffffu, acc, 2);
        acc += __shfl_xor_sync(0xffffffffu, acc, 4);
        acc += __shfl_xor_sync(0xffffffffu, acc, 8);

        if (s == 0) {
            const float zv = zT[(size_t)d * L_SEQ + t];
            float yv = acc + xv * Dd;
            yv *= zv / (1.f + expf(-zv));
            yT[(size_t)d * L_SEQ + t] = yv;
        }
    }
}

// ---------------- host orchestration ----------------------------------------
extern "C" void kernel_launch(void* const* d_in, const int* in_sizes, int n_in,
                              void* d_out, int out_size)
{
    const float* input   = (const float*)d_in[0];
    const float* input_w = (const float*)d_in[2];
    const float* norm_w  = (const float*)d_in[3];
    const float* norm_b  = (const float*)d_in[4];
    const float* ipw     = (const float*)d_in[5];
    const float* cw      = (const float*)d_in[6];
    const float* cb      = (const float*)d_in[7];
    const float* xpw     = (const float*)d_in[8];
    const float* dtw     = (const float*)d_in[9];
    const float* dtb     = (const float*)d_in[10];
    const float* A_log   = (const float*)d_in[11];
    const float* ssm_D   = (const float*)d_in[12];
    const float* opw     = (const float*)d_in[13];

    float *res, *h, *xz, *xconv, *xdbl, *delta, *deltaT, *xcT, *zT, *yT;
    cudaGetSymbolAddress((void**)&res,    g_res);
    cudaGetSymbolAddress((void**)&h,      g_h);
    cudaGetSymbolAddress((void**)&xz,     g_xz);
    cudaGetSymbolAddress((void**)&xconv,  g_xconv);
    cudaGetSymbolAddress((void**)&xdbl,   g_xdbl);
    cudaGetSymbolAddress((void**)&delta,  g_delta);
    cudaGetSymbolAddress((void**)&deltaT, g_deltaT);
    cudaGetSymbolAddress((void**)&xcT,    g_xcT);
    cudaGetSymbolAddress((void**)&zT,     g_zT);
    cudaGetSymbolAddress((void**)&yT,     g_yT);

    bf16 *in_hi, *in_lo, *inw_hi, *inw_lo, *ipw_hi, *ipw_lo, *xpw_hi, *xpw_lo;
    bf16 *dtw_hi, *dtw_lo, *opw_hi, *opw_lo, *hn_hi, *hn_lo, *xc_hi, *xc_lo;
    bf16 *xd_hi, *xd_lo, *y_hi, *y_lo;
    cudaGetSymbolAddress((void**)&in_hi,  c_in_hi);  cudaGetSymbolAddress((void**)&in_lo,  c_in_lo);
    cudaGetSymbolAddress((void**)&inw_hi, c_inw_hi); cudaGetSymbolAddress((void**)&inw_lo, c_inw_lo);
    cudaGetSymbolAddress((void**)&ipw_hi, c_ipw_hi); cudaGetSymbolAddress((void**)&ipw_lo, c_ipw_lo);
    cudaGetSymbolAddress((void**)&xpw_hi, c_xpw_hi); cudaGetSymbolAddress((void**)&xpw_lo, c_xpw_lo);
    cudaGetSymbolAddress((void**)&dtw_hi, c_dtw_hi); cudaGetSymbolAddress((void**)&dtw_lo, c_dtw_lo);
    cudaGetSymbolAddress((void**)&opw_hi, c_opw_hi); cudaGetSymbolAddress((void**)&opw_lo, c_opw_lo);
    cudaGetSymbolAddress((void**)&hn_hi,  c_hn_hi);  cudaGetSymbolAddress((void**)&hn_lo,  c_hn_lo);
    cudaGetSymbolAddress((void**)&xc_hi,  c_xc_hi);  cudaGetSymbolAddress((void**)&xc_lo,  c_xc_lo);
    cudaGetSymbolAddress((void**)&xd_hi,  c_xd_hi);  cudaGetSymbolAddress((void**)&xd_lo,  c_xd_lo);
    cudaGetSymbolAddress((void**)&y_hi,   c_y_hi);   cudaGetSymbolAddress((void**)&y_lo,   c_y_lo);

    cudaFuncSetAttribute(mma_gemm, cudaFuncAttributeMaxDynamicSharedMemorySize, G_SMEM);

    // conversions
    cvt_kernel<<<(NLAYERS*2*DINNER*DMODEL/4 + 1023)/1024, 256>>>(
        ipw, ipw_hi, ipw_lo, NLAYERS*2*DINNER*DMODEL/4);
    cvt_kernel<<<(NLAYERS*DMODEL*DINNER/4 + 1023)/1024, 256>>>(
        opw, opw_hi, opw_lo, NLAYERS*DMODEL*DINNER/4);
    cvt4_kernel<<<(589824 + 255)/256, 256>>>(
        input,   in_hi,  in_lo,  L_SEQ*INLEN/4,
        input_w, inw_hi, inw_lo, DMODEL*INLEN/4,
        xpw,     xpw_hi, xpw_lo, NLAYERS*XDBL_W*DINNER/4,
        dtw,     dtw_hi, dtw_lo, NLAYERS*DINNER*DTRANK/4);

    // h = input @ input_w^T
    mma_gemm<<<dim3(DMODEL/128, L_SEQ/64), 256, G_SMEM>>>(
        in_hi, in_lo, INLEN, inw_hi, inw_lo, INLEN, h, DMODEL,
        DMODEL, INLEN, nullptr, 0);

    for (int i = 0; i < NLAYERS; i++) {
        resln_kernel<<<L_SEQ, 256>>>(h, res, hn_hi, hn_lo,
                                     norm_w + i*DMODEL, norm_b + i*DMODEL, i == 0);

        // xz = hn @ in_proj_w^T   (512 CTAs)
        mma_gemm<<<dim3((2*DINNER)/128, L_SEQ/64), 256, G_SMEM>>>(
            hn_hi, hn_lo, DMODEL,
            ipw_hi + (size_t)i*2*DINNER*DMODEL, ipw_lo + (size_t)i*2*DINNER*DMODEL, DMODEL,
            xz, 2*DINNER, 2*DINNER, DMODEL, nullptr, 0);

        conv_silu_kernel<<<(L_SEQ*DINNER)/256, 256>>>(
            xz, cw + (size_t)i*DINNER*4, cb + i*DINNER, xconv, xc_hi, xc_lo, xdbl);

        // x_dbl = xconv @ x_proj_w^T   split-K=8 (128 CTAs), atomic
        mma_gemm<<<dim3(1, L_SEQ/64, 8), 256, G_SMEM>>>(
            xc_hi, xc_lo, DINNER,
            xpw_hi + (size_t)i*XDBL_W*DINNER, xpw_lo + (size_t)i*XDBL_W*DINNER, DINNER,
            xdbl, XDBL_W, XDBL_W, DINNER/8, nullptr, 2);

        cvt_xdbl_kernel<<<(L_SEQ*DTRANK)/256, 256>>>(xdbl, xd_hi, xd_lo);

        // delta = softplus(xd @ dt_proj_w^T + bias)   (256 CTAs)
        mma_gemm<<<dim3(DINNER/128, L_SEQ/64), 256, G_SMEM>>>(
            xd_hi, xd_lo, DTRANK,
            dtw_hi + (size_t)i*DINNER*DTRANK, dtw_lo + (size_t)i*DINNER*DTRANK, DTRANK,
            delta, DINNER, DINNER, DTRANK, dtb + i*DINNER, 1);

        transpose3_kernel<<<dim3(DINNER/32, L_SEQ/32, 3), dim3(32, 8)>>>(
            delta, xconv, xz + DINNER, deltaT, xcT, zT);

        // chunked parallel scan (round-8 form, high occupancy)
        scan_kernel<<<DINNER, 256>>>(deltaT, xcT, zT, xdbl,
                                     A_log + (size_t)i*DINNER*DSTATE,
                                     ssm_D + i*DINNER, yT);

        // yT -> y hi/lo; zero the split-K out_proj target
        float* outp = (i == NLAYERS-1) ? (float*)d_out : h;
        ytr_kernel<<<dim3(L_SEQ/32, DINNER/32), dim3(32, 8)>>>(yT, y_hi, y_lo, outp);

        // h(next) = y @ out_proj_w^T   split-K=2 (256 CTAs), atomic
        mma_gemm<<<dim3(DMODEL/128, L_SEQ/64, 2), 256, G_SMEM>>>(
            y_hi, y_lo, DINNER,
            opw_hi + (size_t)i*DMODEL*DINNER, opw_lo + (size_t)i*DMODEL*DINNER, DINNER,
            outp, DMODEL, DMODEL, DINNER/2, nullptr, 2);
    }
}

// round 14
// speedup vs baseline: 1.7014x; 1.0140x over previous
#include <cuda_runtime.h>
#include <cuda_bf16.h>
#include <math.h>
#include <stdint.h>

#define L_SEQ   1024
#define INLEN   512
#define DMODEL  1024
#define NLAYERS 4
#define DINNER  2048
#define DSTATE  16
#define DTRANK  64
#define XDBL_W  96   // DT_RANK + 2*D_STATE

typedef __nv_bfloat16 bf16;

// ---------------- fp32 scratch ----------------------------------------------
__device__ float g_res   [L_SEQ * DMODEL];
__device__ float g_h     [L_SEQ * DMODEL];
__device__ float g_xz    [L_SEQ * 2 * DINNER];
__device__ float g_xconv [L_SEQ * DINNER];
__device__ float g_xdbl  [L_SEQ * XDBL_W];
__device__ float g_delta [L_SEQ * DINNER];
__device__ float g_deltaT[DINNER * L_SEQ];
__device__ float g_xcT   [DINNER * L_SEQ];
__device__ float g_zT    [DINNER * L_SEQ];
__device__ float g_yT    [DINNER * L_SEQ];

// ---------------- bf16 hi/lo scratch -----------------------------------------
__device__ bf16 c_in_hi [L_SEQ * INLEN],        c_in_lo [L_SEQ * INLEN];
__device__ bf16 c_inw_hi[DMODEL * INLEN],       c_inw_lo[DMODEL * INLEN];
__device__ bf16 c_ipw_hi[NLAYERS * 2*DINNER * DMODEL], c_ipw_lo[NLAYERS * 2*DINNER * DMODEL];
__device__ bf16 c_xpw_hi[NLAYERS * XDBL_W * DINNER],   c_xpw_lo[NLAYERS * XDBL_W * DINNER];
__device__ bf16 c_dtw_hi[NLAYERS * DINNER * DTRANK],   c_dtw_lo[NLAYERS * DINNER * DTRANK];
__device__ bf16 c_opw_hi[NLAYERS * DMODEL * DINNER],   c_opw_lo[NLAYERS * DMODEL * DINNER];
__device__ bf16 c_hn_hi [L_SEQ * DMODEL],       c_hn_lo [L_SEQ * DMODEL];
__device__ bf16 c_xc_hi [L_SEQ * DINNER],       c_xc_lo [L_SEQ * DINNER];
__device__ bf16 c_xd_hi [L_SEQ * DTRANK],       c_xd_lo [L_SEQ * DTRANK];
__device__ bf16 c_y_hi  [L_SEQ * DINNER],       c_y_lo  [L_SEQ * DINNER];

// ============================ PTX helpers ====================================
__device__ __forceinline__ uint32_t smem_u32(const void* p) {
    uint32_t a;
    asm("{ .reg .u64 t; cvta.to.shared.u64 t, %1; cvt.u32.u64 %0, t; }"
        : "=r"(a) : "l"(p));
    return a;
}
#define CP_ASYNC16(dst, src, sz) \
    asm volatile("cp.async.cg.shared.global [%0], [%1], 16, %2;" \
                 :: "r"(dst), "l"(src), "r"(sz))
#define CP_COMMIT() asm volatile("cp.async.commit_group;" ::: "memory")
#define CP_WAIT0()  asm volatile("cp.async.wait_group 0;" ::: "memory")

#define LDM4(r0, r1, r2, r3, addr) \
    asm volatile("ldmatrix.sync.aligned.m8n8.x4.shared.b16 {%0,%1,%2,%3}, [%4];" \
                 : "=r"(r0), "=r"(r1), "=r"(r2), "=r"(r3) : "r"(addr))

#define MMA_BF16(c, a, b)                                                      \
    asm volatile(                                                              \
        "mma.sync.aligned.m16n8k16.row.col.f32.bf16.bf16.f32 "                 \
        "{%0,%1,%2,%3}, {%4,%5,%6,%7}, {%8,%9}, {%0,%1,%2,%3};"                \
        : "+f"((c)[0]), "+f"((c)[1]), "+f"((c)[2]), "+f"((c)[3])               \
        : "r"((a)[0]), "r"((a)[1]), "r"((a)[2]), "r"((a)[3]),                  \
          "r"((b)[0]), "r"((b)[1]))

__device__ __forceinline__ uint32_t swz(uint32_t off) {
    return off ^ ((off >> 3) & 0x70);
}
__device__ __forceinline__ void split_bf16(float v, bf16& hi, bf16& lo) {
    hi = __float2bfloat16(v);
    lo = __float2bfloat16(v - __bfloat162float(hi));
}

// =============================================================================
// bf16 hi/lo split NT GEMM (3 MMAs per k16), 64x128 tile, 2-stage cp.async,
// 2 CTAs/SM.  C[m,n] = sum_k A[m,k]*B[n,k]
//   Ksplit = K per z-slice.  mode 0: store; 1: softplus(acc+bias); 2: atomicAdd
// =============================================================================
#define G_ABYTES 8192
#define G_BBYTES 16384
#define G_STAGE  (2*G_ABYTES + 2*G_BBYTES)   // 48 KB
#define G_SMEM   (2 * G_STAGE)               // 96 KB

__global__ void __launch_bounds__(256, 2)
mma_gemm(const bf16* __restrict__ Ahi, const bf16* __restrict__ Alo, int lda,
         const bf16* __restrict__ Bhi, const bf16* __restrict__ Blo, int ldb,
         float* __restrict__ C, int ldc,
         int Nvalid, int Ksplit,
         const float* __restrict__ bias, int mode)
{
    extern __shared__ char smem[];
    const uint32_t sb = smem_u32(smem);

    const int tid  = threadIdx.x;
    const int wid  = tid >> 5;
    const int lane = tid & 31;
    const int m0   = blockIdx.y * 64;
    const int n0   = blockIdx.x * 128;
    const int kbase = blockIdx.z * Ksplit;

    const int warp_m = (wid & 1) * 32;
    const int warp_n = (wid >> 1) * 32;

    float acc[2][4][4];
#pragma unroll
    for (int mt = 0; mt < 2; mt++)
#pragma unroll
        for (int nt = 0; nt < 4; nt++)
#pragma unroll
            for (int i = 0; i < 4; i++) acc[mt][nt][i] = 0.f;

    auto stage_load = [&](int c, int buf) {
        const int k0 = kbase + (c << 6);
        const uint32_t st = sb + buf * G_STAGE;
#pragma unroll
        for (int i = 0; i < 2; i++) {
            int j = tid + i * 256;
            int r = j >> 3, u = j & 7;
            uint32_t so = swz((uint32_t)(r * 128 + u * 16));
            const char* ga = (const char*)(Ahi + (size_t)(m0 + r) * lda + k0 + u * 8);
            const char* gl = (const char*)(Alo + (size_t)(m0 + r) * lda + k0 + u * 8);
            CP_ASYNC16(st + so, ga, 16);
            CP_ASYNC16(st + G_ABYTES + so, gl, 16);
        }
#pragma unroll
        for (int i = 0; i < 4; i++) {
            int j = tid + i * 256;
            int r = j >> 3, u = j & 7;
            int gn = n0 + r;
            int sz = (gn < Nvalid) ? 16 : 0;
            int gc = (gn < Nvalid) ? gn : 0;
            uint32_t so = swz((uint32_t)(r * 128 + u * 16));
            const char* gb = (const char*)(Bhi + (size_t)gc * ldb + k0 + u * 8);
            const char* gl = (const char*)(Blo + (size_t)gc * ldb + k0 + u * 8);
            CP_ASYNC16(st + 2 * G_ABYTES + so, gb, sz);
            CP_ASYNC16(st + 2 * G_ABYTES + G_BBYTES + so, gl, sz);
        }
        CP_COMMIT();
    };

    auto mma_chunk = [&](int buf) {
        const uint32_t st  = sb + buf * G_STAGE;
        const uint32_t sAh = st;
        const uint32_t sAl = st + G_ABYTES;
        const uint32_t sBh = st + 2 * G_ABYTES;
        const uint32_t sBl = sBh + G_BBYTES;
#pragma unroll
        for (int ks = 0; ks < 4; ks++) {
            const int kb = ks * 32;
            uint32_t bh[4][2], bl[4][2];
#pragma unroll
            for (int p = 0; p < 2; p++) {
                int row = warp_n + p * 16 + ((lane >> 4) << 3) + (lane & 7);
                int kbyte = kb + ((lane >> 3) & 1) * 16;
                uint32_t off = swz((uint32_t)(row * 128 + kbyte));
                LDM4(bh[2*p][0], bh[2*p][1], bh[2*p+1][0], bh[2*p+1][1], sBh + off);
                LDM4(bl[2*p][0], bl[2*p][1], bl[2*p+1][0], bl[2*p+1][1], sBl + off);
            }
#pragma unroll
            for (int mt = 0; mt < 2; mt++) {
                int row = warp_m + mt * 16 + (lane & 15);
                int kbyte = kb + (lane >> 4) * 16;
                uint32_t off = swz((uint32_t)(row * 128 + kbyte));
                uint32_t ah[4], al[4];
                LDM4(ah[0], ah[1], ah[2], ah[3], sAh + off);
                LDM4(al[0], al[1], al[2], al[3], sAl + off);
#pragma unroll
                for (int nt = 0; nt < 4; nt++) MMA_BF16(acc[mt][nt], ah, bh[nt]);
#pragma unroll
                for (int nt = 0; nt < 4; nt++) MMA_BF16(acc[mt][nt], ah, bl[nt]);
#pragma unroll
                for (int nt = 0; nt < 4; nt++) MMA_BF16(acc[mt][nt], al, bh[nt]);
            }
        }
    };

    const int NC = Ksplit >> 6;
    stage_load(0, 0);
    for (int c = 0; c < NC; c++) {
        CP_WAIT0();
        __syncthreads();
        if (c + 1 < NC) stage_load(c + 1, (c + 1) & 1);
        mma_chunk(c & 1);
    }

    // ---- epilogue ----
    const int qrow = lane >> 2;
    const int qcol = (lane & 3) * 2;
#pragma unroll
    for (int mt = 0; mt < 2; mt++) {
        int row0 = m0 + warp_m + mt * 16 + qrow;
        int row1 = row0 + 8;
#pragma unroll
        for (int nt = 0; nt < 4; nt++) {
            int gn = n0 + warp_n + nt * 8 + qcol;
            if (gn >= Nvalid) continue;
            float2 v0 = make_float2(acc[mt][nt][0], acc[mt][nt][1]);
            float2 v1 = make_float2(acc[mt][nt][2], acc[mt][nt][3]);
            if (mode == 1) {
                float b0 = bias[gn], b1 = bias[gn + 1];
                v0.x += b0; v0.y += b1; v1.x += b0; v1.y += b1;
                v0.x = (v0.x > 20.f) ? v0.x : log1pf(expf(v0.x));
                v0.y = (v0.y > 20.f) ? v0.y : log1pf(expf(v0.y));
                v1.x = (v1.x > 20.f) ? v1.x : log1pf(expf(v1.x));
                v1.y = (v1.y > 20.f) ? v1.y : log1pf(expf(v1.y));
            }
            if (mode == 2) {
                atomicAdd(&C[(size_t)row0 * ldc + gn],     v0.x);
                atomicAdd(&C[(size_t)row0 * ldc + gn + 1], v0.y);
                atomicAdd(&C[(size_t)row1 * ldc + gn],     v1.x);
                atomicAdd(&C[(size_t)row1 * ldc + gn + 1], v1.y);
            } else {
                *reinterpret_cast<float2*>(C + (size_t)row0 * ldc + gn) = v0;
                *reinterpret_cast<float2*>(C + (size_t)row1 * ldc + gn) = v1;
            }
        }
    }
}

// ---------------- fp32 -> bf16 hi/lo converters (MLP=4) ----------------------
__global__ void cvt_kernel(const float* __restrict__ src,
                           bf16* __restrict__ hi, bf16* __restrict__ lo, int n4)
{
    int base = blockIdx.x * blockDim.x * 4 + threadIdx.x;
    float4 v[4];
    int idx[4];
#pragma unroll
    for (int u = 0; u < 4; u++) {
        idx[u] = base + u * 256;
        if (idx[u] < n4) v[u] = reinterpret_cast<const float4*>(src)[idx[u]];
    }
#pragma unroll
    for (int u = 0; u < 4; u++) {
        if (idx[u] >= n4) continue;
        bf16 h0, h1, h2, h3, l0, l1, l2, l3;
        split_bf16(v[u].x, h0, l0); split_bf16(v[u].y, h1, l1);
        split_bf16(v[u].z, h2, l2); split_bf16(v[u].w, h3, l3);
        uint32_t hA = ((uint32_t)__bfloat16_as_ushort(h1) << 16) | __bfloat16_as_ushort(h0);
        uint32_t hB = ((uint32_t)__bfloat16_as_ushort(h3) << 16) | __bfloat16_as_ushort(h2);
        uint32_t lA = ((uint32_t)__bfloat16_as_ushort(l1) << 16) | __bfloat16_as_ushort(l0);
        uint32_t lB = ((uint32_t)__bfloat16_as_ushort(l3) << 16) | __bfloat16_as_ushort(l2);
        reinterpret_cast<uint2*>(hi)[idx[u]] = make_uint2(hA, hB);
        reinterpret_cast<uint2*>(lo)[idx[u]] = make_uint2(lA, lB);
    }
}

__global__ void cvt4_kernel(const float* s0, bf16* h0, bf16* l0, int n0,
                            const float* s1, bf16* h1, bf16* l1, int n1,
                            const float* s2, bf16* h2, bf16* l2, int n2,
                            const float* s3, bf16* h3, bf16* l3, int n3)
{
    int i = blockIdx.x * blockDim.x + threadIdx.x;
    const float* s; bf16 *h, *l; int j = i;
    if (j < n0)      { s = s0; h = h0; l = l0; }
    else { j -= n0;
    if (j < n1)      { s = s1; h = h1; l = l1; }
    else { j -= n1;
    if (j < n2)      { s = s2; h = h2; l = l2; }
    else { j -= n2;
    if (j < n3)      { s = s3; h = h3; l = l3; }
    else return; } } }
    float4 v = reinterpret_cast<const float4*>(s)[j];
    bf16 a0, a1, a2, a3, b0, b1, b2, b3;
    split_bf16(v.x, a0, b0); split_bf16(v.y, a1, b1);
    split_bf16(v.z, a2, b2); split_bf16(v.w, a3, b3);
    uint32_t hA = ((uint32_t)__bfloat16_as_ushort(a1) << 16) | __bfloat16_as_ushort(a0);
    uint32_t hB = ((uint32_t)__bfloat16_as_ushort(a3) << 16) | __bfloat16_as_ushort(a2);
    uint32_t lA = ((uint32_t)__bfloat16_as_ushort(b1) << 16) | __bfloat16_as_ushort(b0);
    uint32_t lB = ((uint32_t)__bfloat16_as_ushort(b3) << 16) | __bfloat16_as_ushort(b2);
    reinterpret_cast<uint2*>(h)[j] = make_uint2(hA, hB);
    reinterpret_cast<uint2*>(l)[j] = make_uint2(lA, lB);
}

__global__ void cvt_xdbl_kernel(const float* __restrict__ xdbl,
                                bf16* __restrict__ hi, bf16* __restrict__ lo)
{
    int i = blockIdx.x * blockDim.x + threadIdx.x;
    int r = i >> 6, c = i & 63;
    float v = xdbl[r * XDBL_W + c];
    bf16 h, l; split_bf16(v, h, l);
    hi[i] = h; lo[i] = l;
}

// ---------------- fused residual-add + LayerNorm ------------------------------
__global__ void resln_kernel(const float* __restrict__ hin,
                             float* __restrict__ res,
                             bf16* __restrict__ hn_hi, bf16* __restrict__ hn_lo,
                             const float* __restrict__ w,
                             const float* __restrict__ b,
                             int first)
{
    const int l   = blockIdx.x;
    const int tid = threadIdx.x;
    float v[4];
    float s = 0.f, sq = 0.f;
#pragma unroll
    for (int i = 0; i < 4; i++) {
        int c = tid + i * 256;
        float x = hin[l * DMODEL + c];
        if (!first) x += res[l * DMODEL + c];
        res[l * DMODEL + c] = x;
        v[i] = x;
        s  += x;
        sq += x * x;
    }
    __shared__ float shs[8], shq[8];
    const int lane = tid & 31, warp = tid >> 5;
#pragma unroll
    for (int o = 16; o > 0; o >>= 1) {
        s  += __shfl_xor_sync(0xffffffffu, s,  o);
        sq += __shfl_xor_sync(0xffffffffu, sq, o);
    }
    if (lane == 0) { shs[warp] = s; shq[warp] = sq; }
    __syncthreads();
    s = 0.f; sq = 0.f;
#pragma unroll
    for (int i = 0; i < 8; i++) { s += shs[i]; sq += shq[i]; }

    const float inv = 1.f / (float)DMODEL;
    const float mu  = s * inv;
    const float var = sq * inv - mu * mu;
    const float rstd = rsqrtf(var + 1e-5f);
#pragma unroll
    for (int i = 0; i < 4; i++) {
        int c = tid + i * 256;
        float o = (v[i] - mu) * rstd * w[c] + b[c];
        bf16 h, lo; split_bf16(o, h, lo);
        hn_hi[l * DMODEL + c] = h;
        hn_lo[l * DMODEL + c] = lo;
    }
}

// =============================================================================
// Fused conv + SiLU + transposes, tiled 32(d) x 32(l), block (32,8).
// Emits: xconv [l][d], xc_hi/lo [l][d], xcT [d][l], zT [d][l].
// Also zeroes xdbl for the x_proj split-K atomics.
// =============================================================================
__global__ void conv_tile_kernel(const float* __restrict__ xz,
                                 const float* __restrict__ cw,
                                 const float* __restrict__ cb,
                                 float* __restrict__ xconv,
                                 bf16* __restrict__ xc_hi,
                                 bf16* __restrict__ xc_lo,
                                 float* __restrict__ xcT,
                                 float* __restrict__ zT,
                                 float* __restrict__ xdbl_zero)
{
    __shared__ float xin[35][33];   // rows l0-3 .. l0+31
    __shared__ float zin[32][33];
    __shared__ float ot [32][33];

    const int d0 = blockIdx.x * 32;
    const int l0 = blockIdx.y * 32;
    const int tx = threadIdx.x, ty = threadIdx.y;

    // zero xdbl (98304 floats over 2048 CTAs x 256 threads)
    {
        int flat = (blockIdx.y * gridDim.x + blockIdx.x) * 256 + ty * 32 + tx;
        if (flat < L_SEQ * XDBL_W) xdbl_zero[flat] = 0.f;
    }

    // load x tile with 3-row halo
#pragma unroll
    for (int i = 0; i < 5; i++) {
        int y = ty + i * 8;
        if (y < 35) {
            int l = l0 + y - 3;
            xin[y][tx] = (l >= 0) ? xz[(size_t)l * (2*DINNER) + d0 + tx] : 0.f;
        }
    }
    // load z tile
#pragma unroll
    for (int i = 0; i < 4; i++) {
        int y = ty + i * 8;
        zin[y][tx] = xz[(size_t)(l0 + y) * (2*DINNER) + DINNER + d0 + tx];
    }
    __syncthreads();

    const int d = d0 + tx;
    const float w0 = cw[d*4+0], w1 = cw[d*4+1], w2 = cw[d*4+2], w3 = cw[d*4+3];
    const float cbd = cb[d];
#pragma unroll
    for (int i = 0; i < 4; i++) {
        int y = ty + i * 8;
        int l = l0 + y;
        float acc = cbd;
        acc = fmaf(w0, xin[y][tx],     acc);   // l-3
        acc = fmaf(w1, xin[y + 1][tx], acc);   // l-2
        acc = fmaf(w2, xin[y + 2][tx], acc);   // l-1
        acc = fmaf(w3, xin[y + 3][tx], acc);   // l
        acc = acc / (1.f + expf(-acc));        // SiLU
        xconv[(size_t)l * DINNER + d] = acc;
        bf16 h, lo; split_bf16(acc, h, lo);
        xc_hi[(size_t)l * DINNER + d] = h;
        xc_lo[(size_t)l * DINNER + d] = lo;
        ot[y][tx] = acc;
    }
    __syncthreads();

    // transposed writes (coalesced along l)
#pragma unroll
    for (int i = 0; i < 4; i++) {
        int y = ty + i * 8;   // local d index
        xcT[(size_t)(d0 + y) * L_SEQ + l0 + tx] = ot[tx][y];
        zT [(size_t)(d0 + y) * L_SEQ + l0 + tx] = zin[tx][y];
    }
}

// ---------------- tiled transpose: delta -> deltaT [d][t] --------------------
__global__ void transpose1_kernel(const float* __restrict__ src,
                                  float* __restrict__ dst)
{
    __shared__ float tile[32][33];
    const int c0 = blockIdx.x * 32;   // d
    const int r0 = blockIdx.y * 32;   // t
    const int x = threadIdx.x, y0 = threadIdx.y;
#pragma unroll
    for (int i = 0; i < 4; i++) {
        int y = y0 + i * 8;
        tile[y][x] = src[(size_t)(r0 + y) * DINNER + c0 + x];
    }
    __syncthreads();
#pragma unroll
    for (int i = 0; i < 4; i++) {
        int y = y0 + i * 8;
        dst[(size_t)(c0 + y) * L_SEQ + r0 + x] = tile[x][y];
    }
}

// ---------------- yT [d][t] -> y hi/lo [t][d]; zeroes out_proj target --------
__global__ void ytr_kernel(const float* __restrict__ yT,
                           bf16* __restrict__ y_hi, bf16* __restrict__ y_lo,
                           float* __restrict__ zero_buf)
{
    {
        int flat = threadIdx.y * 32 + threadIdx.x;
        int zi = (blockIdx.y * gridDim.x + blockIdx.x) * 256 + flat;
        if (zi * 2 < L_SEQ * DMODEL)
            *reinterpret_cast<float2*>(zero_buf + zi * 2) = make_float2(0.f, 0.f);
    }
    __shared__ float tile[32][33];
    const int c0 = blockIdx.x * 32;   // t
    const int r0 = blockIdx.y * 32;   // d
    const int x = threadIdx.x, y0 = threadIdx.y;
#pragma unroll
    for (int i = 0; i < 4; i++) {
        int y = y0 + i * 8;
        tile[y][x] = yT[(size_t)(r0 + y) * L_SEQ + c0 + x];
    }
    __syncthreads();
#pragma unroll
    for (int i = 0; i < 4; i++) {
        int y = y0 + i * 8;
        float v = tile[x][y];
        bf16 h, l; split_bf16(v, h, l);
        y_hi[(size_t)(c0 + y) * DINNER + r0 + x] = h;
        y_lo[(size_t)(c0 + y) * DINNER + r0 + x] = l;
    }
}

// =============================================================================
// Chunked parallel scan — round-8 form (static 10 KB smem, high occupancy).
// =============================================================================
__global__ void __launch_bounds__(256)
scan_kernel(const float* __restrict__ deltaT,
            const float* __restrict__ xcT,
            const float* __restrict__ zT,
            const float* __restrict__ xdbl,
            const float* __restrict__ A_log,
            const float* __restrict__ Dvec,
            float* __restrict__ yT)
{
    __shared__ float s_dl[L_SEQ];
    __shared__ float s_xv[L_SEQ];
    __shared__ float shP[16][16];
    __shared__ float shS[16][16];

    const int d    = blockIdx.x;
    const int tid  = threadIdx.x;
    const int lane = tid & 31;
    const int wrp  = tid >> 5;
    const int j    = wrp * 2 + (lane >> 4);
    const int s    = lane & 15;
    const int t0   = j * 64;

    for (int i = tid; i < L_SEQ; i += 256) {
        s_dl[i] = deltaT[(size_t)d * L_SEQ + i];
        s_xv[i] = xcT[(size_t)d * L_SEQ + i];
    }
    __syncthreads();

    const float a2 = -expf(A_log[d * DSTATE + s]) * 1.4426950408889634f;

    float P = 1.f, S = 0.f;
#pragma unroll 4
    for (int k = 0; k < 64; k++) {
        const int t = t0 + k;
        const float dl = s_dl[t];
        const float Bs = xdbl[t * XDBL_W + DTRANK + s];
        const float dA = exp2f(dl * a2);
        P *= dA;
        S = fmaf(dA, S, dl * s_xv[t] * Bs);
    }
    shP[j][s] = P;
    shS[j][s] = S;
    __syncthreads();

    if (tid < 16) {
        const int ss = tid;
        float run = shS[0][ss];
#pragma unroll
        for (int jj = 1; jj < 16; jj++) {
            run = fmaf(shP[jj][ss], run, shS[jj][ss]);
            shS[jj][ss] = run;
        }
    }
    __syncthreads();

    float h = (j == 0) ? 0.f : shS[j - 1][s];
    const float Dd = Dvec[d];
#pragma unroll 4
    for (int k = 0; k < 64; k++) {
        const int t = t0 + k;
        const float dl = s_dl[t];
        const float xv = s_xv[t];
        const float Bs = xdbl[t * XDBL_W + DTRANK + s];
        const float Cs = xdbl[t * XDBL_W + DTRANK + DSTATE + s];
        const float dA = exp2f(dl * a2);
        h = fmaf(dA, h, dl * xv * Bs);

        float acc = h * Cs;
        acc += __shfl_xor_sync(0xffffffffu, acc, 1);
        acc += __shfl_xor_sync(0xffffffffu, acc, 2);
        acc += __shfl_xor_sync(0xffffffffu, acc, 4);
        acc += __shfl_xor_sync(0xffffffffu, acc, 8);

        if (s == 0) {
            const float zv = zT[(size_t)d * L_SEQ + t];
            float yv = acc + xv * Dd;
            yv *= zv / (1.f + expf(-zv));
            yT[(size_t)d * L_SEQ + t] = yv;
        }
    }
}

// ---------------- host orchestration ----------------------------------------
extern "C" void kernel_launch(void* const* d_in, const int* in_sizes, int n_in,
                              void* d_out, int out_size)
{
    const float* input   = (const float*)d_in[0];
    const float* input_w = (const float*)d_in[2];
    const float* norm_w  = (const float*)d_in[3];
    const float* norm_b  = (const float*)d_in[4];
    const float* ipw     = (const float*)d_in[5];
    const float* cw      = (const float*)d_in[6];
    const float* cb      = (const float*)d_in[7];
    const float* xpw     = (const float*)d_in[8];
    const float* dtw     = (const float*)d_in[9];
    const float* dtb     = (const float*)d_in[10];
    const float* A_log   = (const float*)d_in[11];
    const float* ssm_D   = (const float*)d_in[12];
    const float* opw     = (const float*)d_in[13];

    float *res, *h, *xz, *xconv, *xdbl, *delta, *deltaT, *xcT, *zT, *yT;
    cudaGetSymbolAddress((void**)&res,    g_res);
    cudaGetSymbolAddress((void**)&h,      g_h);
    cudaGetSymbolAddress((void**)&xz,     g_xz);
    cudaGetSymbolAddress((void**)&xconv,  g_xconv);
    cudaGetSymbolAddress((void**)&xdbl,   g_xdbl);
    cudaGetSymbolAddress((void**)&delta,  g_delta);
    cudaGetSymbolAddress((void**)&deltaT, g_deltaT);
    cudaGetSymbolAddress((void**)&xcT,    g_xcT);
    cudaGetSymbolAddress((void**)&zT,     g_zT);
    cudaGetSymbolAddress((void**)&yT,     g_yT);

    bf16 *in_hi, *in_lo, *inw_hi, *inw_lo, *ipw_hi, *ipw_lo, *xpw_hi, *xpw_lo;
    bf16 *dtw_hi, *dtw_lo, *opw_hi, *opw_lo, *hn_hi, *hn_lo, *xc_hi, *xc_lo;
    bf16 *xd_hi, *xd_lo, *y_hi, *y_lo;
    cudaGetSymbolAddress((void**)&in_hi,  c_in_hi);  cudaGetSymbolAddress((void**)&in_lo,  c_in_lo);
    cudaGetSymbolAddress((void**)&inw_hi, c_inw_hi); cudaGetSymbolAddress((void**)&inw_lo, c_inw_lo);
    cudaGetSymbolAddress((void**)&ipw_hi, c_ipw_hi); cudaGetSymbolAddress((void**)&ipw_lo, c_ipw_lo);
    cudaGetSymbolAddress((void**)&xpw_hi, c_xpw_hi); cudaGetSymbolAddress((void**)&xpw_lo, c_xpw_lo);
    cudaGetSymbolAddress((void**)&dtw_hi, c_dtw_hi); cudaGetSymbolAddress((void**)&dtw_lo, c_dtw_lo);
    cudaGetSymbolAddress((void**)&opw_hi, c_opw_hi); cudaGetSymbolAddress((void**)&opw_lo, c_opw_lo);
    cudaGetSymbolAddress((void**)&hn_hi,  c_hn_hi);  cudaGetSymbolAddress((void**)&hn_lo,  c_hn_lo);
    cudaGetSymbolAddress((void**)&xc_hi,  c_xc_hi);  cudaGetSymbolAddress((void**)&xc_lo,  c_xc_lo);
    cudaGetSymbolAddress((void**)&xd_hi,  c_xd_hi);  cudaGetSymbolAddress((void**)&xd_lo,  c_xd_lo);
    cudaGetSymbolAddress((void**)&y_hi,   c_y_hi);   cudaGetSymbolAddress((void**)&y_lo,   c_y_lo);

    cudaFuncSetAttribute(mma_gemm, cudaFuncAttributeMaxDynamicSharedMemorySize, G_SMEM);

    // conversions
    cvt_kernel<<<(NLAYERS*2*DINNER*DMODEL/4 + 1023)/1024, 256>>>(
        ipw, ipw_hi, ipw_lo, NLAYERS*2*DINNER*DMODEL/4);
    cvt_kernel<<<(NLAYERS*DMODEL*DINNER/4 + 1023)/1024, 256>>>(
        opw, opw_hi, opw_lo, NLAYERS*DMODEL*DINNER/4);
    cvt4_kernel<<<(589824 + 255)/256, 256>>>(
        input,   in_hi,  in_lo,  L_SEQ*INLEN/4,
        input_w, inw_hi, inw_lo, DMODEL*INLEN/4,
        xpw,     xpw_hi, xpw_lo, NLAYERS*XDBL_W*DINNER/4,
        dtw,     dtw_hi, dtw_lo, NLAYERS*DINNER*DTRANK/4);

    // h = input @ input_w^T
    mma_gemm<<<dim3(DMODEL/128, L_SEQ/64), 256, G_SMEM>>>(
        in_hi, in_lo, INLEN, inw_hi, inw_lo, INLEN, h, DMODEL,
        DMODEL, INLEN, nullptr, 0);

    for (int i = 0; i < NLAYERS; i++) {
        resln_kernel<<<L_SEQ, 256>>>(h, res, hn_hi, hn_lo,
                                     norm_w + i*DMODEL, norm_b + i*DMODEL, i == 0);

        // xz = hn @ in_proj_w^T   (512 CTAs)
        mma_gemm<<<dim3((2*DINNER)/128, L_SEQ/64), 256, G_SMEM>>>(
            hn_hi, hn_lo, DMODEL,
            ipw_hi + (size_t)i*2*DINNER*DMODEL, ipw_lo + (size_t)i*2*DINNER*DMODEL, DMODEL,
            xz, 2*DINNER, 2*DINNER, DMODEL, nullptr, 0);

        // fused conv + SiLU + xcT/zT transposes + xdbl zeroing
        conv_tile_kernel<<<dim3(DINNER/32, L_SEQ/32), dim3(32, 8)>>>(
            xz, cw + (size_t)i*DINNER*4, cb + i*DINNER,
            xconv, xc_hi, xc_lo, xcT, zT, xdbl);

        // x_dbl = xconv @ x_proj_w^T   split-K=8 (128 CTAs), atomic
        mma_gemm<<<dim3(1, L_SEQ/64, 8), 256, G_SMEM>>>(
            xc_hi, xc_lo, DINNER,
            xpw_hi + (size_t)i*XDBL_W*DINNER, xpw_lo + (size_t)i*XDBL_W*DINNER, DINNER,
            xdbl, XDBL_W, XDBL_W, DINNER/8, nullptr, 2);

        cvt_xdbl_kernel<<<(L_SEQ*DTRANK)/256, 256>>>(xdbl, xd_hi, xd_lo);

        // delta = softplus(xd @ dt_proj_w^T + bias)   (256 CTAs)
        mma_gemm<<<dim3(DINNER/128, L_SEQ/64), 256, G_SMEM>>>(
            xd_hi, xd_lo, DTRANK,
            dtw_hi + (size_t)i*DINNER*DTRANK, dtw_lo + (size_t)i*DINNER*DTRANK, DTRANK,
            delta, DINNER, DINNER, DTRANK, dtb + i*DINNER, 1);

        // transpose delta only
        transpose1_kernel<<<dim3(DINNER/32, L_SEQ/32), dim3(32, 8)>>>(delta, deltaT);

        scan_kernel<<<DINNER, 256>>>(deltaT, xcT, zT, xdbl,
                                     A_log + (size_t)i*DINNER*DSTATE,
                                     ssm_D + i*DINNER, yT);

        // yT -> y hi/lo; zero the split-K out_proj target
        float* outp = (i == NLAYERS-1) ? (float*)d_out : h;
        ytr_kernel<<<dim3(L_SEQ/32, DINNER/32), dim3(32, 8)>>>(yT, y_hi, y_lo, outp);

        // h(next) = y @ out_proj_w^T   split-K=4 (512 CTAs), atomic
        mma_gemm<<<dim3(DMODEL/128, L_SEQ/64, 4), 256, G_SMEM>>>(
            y_hi, y_lo, DINNER,
            opw_hi + (size_t)i*DMODEL*DINNER, opw_lo + (size_t)i*DMODEL*DINNER, DINNER,
            outp, DMODEL, DMODEL, DINNER/4, nullptr, 2);
    }
}

// round 15
// speedup vs baseline: 1.7052x; 1.0023x over previous
#include <cuda_runtime.h>
#include <cuda_bf16.h>
#include <math.h>
#include <stdint.h>

#define L_SEQ   1024
#define INLEN   512
#define DMODEL  1024
#define NLAYERS 4
#define DINNER  2048
#define DSTATE  16
#define DTRANK  64
#define XDBL_W  96   // DT_RANK + 2*D_STATE

typedef __nv_bfloat16 bf16;

// ---------------- fp32 scratch ----------------------------------------------
__device__ float g_res   [L_SEQ * DMODEL];
__device__ float g_h     [L_SEQ * DMODEL];
__device__ float g_xz    [L_SEQ * 2 * DINNER];
__device__ float g_xdbl  [L_SEQ * XDBL_W];
__device__ float g_delta [L_SEQ * DINNER];
__device__ float g_deltaT[DINNER * L_SEQ];
__device__ float g_xcT   [DINNER * L_SEQ];
__device__ float g_zT    [DINNER * L_SEQ];
__device__ float g_yT    [DINNER * L_SEQ];

// ---------------- bf16 hi/lo scratch -----------------------------------------
__device__ bf16 c_in_hi [L_SEQ * INLEN],        c_in_lo [L_SEQ * INLEN];
__device__ bf16 c_inw_hi[DMODEL * INLEN],       c_inw_lo[DMODEL * INLEN];
__device__ bf16 c_ipw_hi[NLAYERS * 2*DINNER * DMODEL], c_ipw_lo[NLAYERS * 2*DINNER * DMODEL];
__device__ bf16 c_xpw_hi[NLAYERS * XDBL_W * DINNER],   c_xpw_lo[NLAYERS * XDBL_W * DINNER];
__device__ bf16 c_dtw_hi[NLAYERS * DINNER * DTRANK],   c_dtw_lo[NLAYERS * DINNER * DTRANK];
__device__ bf16 c_opw_hi[NLAYERS * DMODEL * DINNER],   c_opw_lo[NLAYERS * DMODEL * DINNER];
__device__ bf16 c_hn_hi [L_SEQ * DMODEL],       c_hn_lo [L_SEQ * DMODEL];
__device__ bf16 c_xc_hi [L_SEQ * DINNER],       c_xc_lo [L_SEQ * DINNER];
__device__ bf16 c_xd_hi [L_SEQ * DTRANK],       c_xd_lo [L_SEQ * DTRANK];
__device__ bf16 c_y_hi  [L_SEQ * DINNER],       c_y_lo  [L_SEQ * DINNER];

// ============================ PTX helpers ====================================
__device__ __forceinline__ uint32_t smem_u32(const void* p) {
    uint32_t a;
    asm("{ .reg .u64 t; cvta.to.shared.u64 t, %1; cvt.u32.u64 %0, t; }"
        : "=r"(a) : "l"(p));
    return a;
}
#define CP_ASYNC16(dst, src, sz) \
    asm volatile("cp.async.cg.shared.global [%0], [%1], 16, %2;" \
                 :: "r"(dst), "l"(src), "r"(sz))
#define CP_COMMIT() asm volatile("cp.async.commit_group;" ::: "memory")
#define CP_WAIT0()  asm volatile("cp.async.wait_group 0;" ::: "memory")

#define LDM4(r0, r1, r2, r3, addr) \
    asm volatile("ldmatrix.sync.aligned.m8n8.x4.shared.b16 {%0,%1,%2,%3}, [%4];" \
                 : "=r"(r0), "=r"(r1), "=r"(r2), "=r"(r3) : "r"(addr))

#define MMA_BF16(c, a, b)                                                      \
    asm volatile(                                                              \
        "mma.sync.aligned.m16n8k16.row.col.f32.bf16.bf16.f32 "                 \
        "{%0,%1,%2,%3}, {%4,%5,%6,%7}, {%8,%9}, {%0,%1,%2,%3};"                \
        : "+f"((c)[0]), "+f"((c)[1]), "+f"((c)[2]), "+f"((c)[3])               \
        : "r"((a)[0]), "r"((a)[1]), "r"((a)[2]), "r"((a)[3]),                  \
          "r"((b)[0]), "r"((b)[1]))

__device__ __forceinline__ uint32_t swz(uint32_t off) {
    return off ^ ((off >> 3) & 0x70);
}
__device__ __forceinline__ void split_bf16(float v, bf16& hi, bf16& lo) {
    hi = __float2bfloat16(v);
    lo = __float2bfloat16(v - __bfloat162float(hi));
}

// =============================================================================
// bf16 hi/lo split NT GEMM (3 MMAs per k16), 64x128 tile, 2-stage cp.async,
// 2 CTAs/SM.  C[m,n] = sum_k A[m,k]*B[n,k]
//   Ksplit = K per z-slice.  mode 0: store; 1: softplus(acc+bias); 2: atomicAdd
// =============================================================================
#define G_ABYTES 8192
#define G_BBYTES 16384
#define G_STAGE  (2*G_ABYTES + 2*G_BBYTES)   // 48 KB
#define G_SMEM   (2 * G_STAGE)               // 96 KB

__global__ void __launch_bounds__(256, 2)
mma_gemm(const bf16* __restrict__ Ahi, const bf16* __restrict__ Alo, int lda,
         const bf16* __restrict__ Bhi, const bf16* __restrict__ Blo, int ldb,
         float* __restrict__ C, int ldc,
         int Nvalid, int Ksplit,
         const float* __restrict__ bias, int mode)
{
    extern __shared__ char smem[];
    const uint32_t sb = smem_u32(smem);

    const int tid  = threadIdx.x;
    const int wid  = tid >> 5;
    const int lane = tid & 31;
    const int m0   = blockIdx.y * 64;
    const int n0   = blockIdx.x * 128;
    const int kbase = blockIdx.z * Ksplit;

    const int warp_m = (wid & 1) * 32;
    const int warp_n = (wid >> 1) * 32;

    float acc[2][4][4];
#pragma unroll
    for (int mt = 0; mt < 2; mt++)
#pragma unroll
        for (int nt = 0; nt < 4; nt++)
#pragma unroll
            for (int i = 0; i < 4; i++) acc[mt][nt][i] = 0.f;

    auto stage_load = [&](int c, int buf) {
        const int k0 = kbase + (c << 6);
        const uint32_t st = sb + buf * G_STAGE;
#pragma unroll
        for (int i = 0; i < 2; i++) {
            int j = tid + i * 256;
            int r = j >> 3, u = j & 7;
            uint32_t so = swz((uint32_t)(r * 128 + u * 16));
            const char* ga = (const char*)(Ahi + (size_t)(m0 + r) * lda + k0 + u * 8);
            const char* gl = (const char*)(Alo + (size_t)(m0 + r) * lda + k0 + u * 8);
            CP_ASYNC16(st + so, ga, 16);
            CP_ASYNC16(st + G_ABYTES + so, gl, 16);
        }
#pragma unroll
        for (int i = 0; i < 4; i++) {
            int j = tid + i * 256;
            int r = j >> 3, u = j & 7;
            int gn = n0 + r;
            int sz = (gn < Nvalid) ? 16 : 0;
            int gc = (gn < Nvalid) ? gn : 0;
            uint32_t so = swz((uint32_t)(r * 128 + u * 16));
            const char* gb = (const char*)(Bhi + (size_t)gc * ldb + k0 + u * 8);
            const char* gl = (const char*)(Blo + (size_t)gc * ldb + k0 + u * 8);
            CP_ASYNC16(st + 2 * G_ABYTES + so, gb, sz);
            CP_ASYNC16(st + 2 * G_ABYTES + G_BBYTES + so, gl, sz);
        }
        CP_COMMIT();
    };

    auto mma_chunk = [&](int buf) {
        const uint32_t st  = sb + buf * G_STAGE;
        const uint32_t sAh = st;
        const uint32_t sAl = st + G_ABYTES;
        const uint32_t sBh = st + 2 * G_ABYTES;
        const uint32_t sBl = sBh + G_BBYTES;
#pragma unroll
        for (int ks = 0; ks < 4; ks++) {
            const int kb = ks * 32;
            uint32_t bh[4][2], bl[4][2];
#pragma unroll
            for (int p = 0; p < 2; p++) {
                int row = warp_n + p * 16 + ((lane >> 4) << 3) + (lane & 7);
                int kbyte = kb + ((lane >> 3) & 1) * 16;
                uint32_t off = swz((uint32_t)(row * 128 + kbyte));
                LDM4(bh[2*p][0], bh[2*p][1], bh[2*p+1][0], bh[2*p+1][1], sBh + off);
                LDM4(bl[2*p][0], bl[2*p][1], bl[2*p+1][0], bl[2*p+1][1], sBl + off);
            }
#pragma unroll
            for (int mt = 0; mt < 2; mt++) {
                int row = warp_m + mt * 16 + (lane & 15);
                int kbyte = kb + (lane >> 4) * 16;
                uint32_t off = swz((uint32_t)(row * 128 + kbyte));
                uint32_t ah[4], al[4];
                LDM4(ah[0], ah[1], ah[2], ah[3], sAh + off);
                LDM4(al[0], al[1], al[2], al[3], sAl + off);
#pragma unroll
                for (int nt = 0; nt < 4; nt++) MMA_BF16(acc[mt][nt], ah, bh[nt]);
#pragma unroll
                for (int nt = 0; nt < 4; nt++) MMA_BF16(acc[mt][nt], ah, bl[nt]);
#pragma unroll
                for (int nt = 0; nt < 4; nt++) MMA_BF16(acc[mt][nt], al, bh[nt]);
            }
        }
    };

    const int NC = Ksplit >> 6;
    stage_load(0, 0);
    for (int c = 0; c < NC; c++) {
        CP_WAIT0();
        __syncthreads();
        if (c + 1 < NC) stage_load(c + 1, (c + 1) & 1);
        mma_chunk(c & 1);
    }

    // ---- epilogue ----
    const int qrow = lane >> 2;
    const int qcol = (lane & 3) * 2;
#pragma unroll
    for (int mt = 0; mt < 2; mt++) {
        int row0 = m0 + warp_m + mt * 16 + qrow;
        int row1 = row0 + 8;
#pragma unroll
        for (int nt = 0; nt < 4; nt++) {
            int gn = n0 + warp_n + nt * 8 + qcol;
            if (gn >= Nvalid) continue;
            float2 v0 = make_float2(acc[mt][nt][0], acc[mt][nt][1]);
            float2 v1 = make_float2(acc[mt][nt][2], acc[mt][nt][3]);
            if (mode == 1) {
                float b0 = bias[gn], b1 = bias[gn + 1];
                v0.x += b0; v0.y += b1; v1.x += b0; v1.y += b1;
                v0.x = (v0.x > 20.f) ? v0.x : log1pf(expf(v0.x));
                v0.y = (v0.y > 20.f) ? v0.y : log1pf(expf(v0.y));
                v1.x = (v1.x > 20.f) ? v1.x : log1pf(expf(v1.x));
                v1.y = (v1.y > 20.f) ? v1.y : log1pf(expf(v1.y));
            }
            if (mode == 2) {
                atomicAdd(&C[(size_t)row0 * ldc + gn],     v0.x);
                atomicAdd(&C[(size_t)row0 * ldc + gn + 1], v0.y);
                atomicAdd(&C[(size_t)row1 * ldc + gn],     v1.x);
                atomicAdd(&C[(size_t)row1 * ldc + gn + 1], v1.y);
            } else {
                *reinterpret_cast<float2*>(C + (size_t)row0 * ldc + gn) = v0;
                *reinterpret_cast<float2*>(C + (size_t)row1 * ldc + gn) = v1;
            }
        }
    }
}

// ---------------- zero a float buffer (for split-K atomic targets) -----------
__global__ void zero_kernel(float* __restrict__ p, int n4)
{
    int i = blockIdx.x * blockDim.x + threadIdx.x;
    if (i < n4)
        reinterpret_cast<float4*>(p)[i] = make_float4(0.f, 0.f, 0.f, 0.f);
}

// ---------------- fp32 -> bf16 hi/lo converters (MLP=4) ----------------------
__global__ void cvt_kernel(const float* __restrict__ src,
                           bf16* __restrict__ hi, bf16* __restrict__ lo, int n4)
{
    int base = blockIdx.x * blockDim.x * 4 + threadIdx.x;
    float4 v[4];
    int idx[4];
#pragma unroll
    for (int u = 0; u < 4; u++) {
        idx[u] = base + u * 256;
        if (idx[u] < n4) v[u] = reinterpret_cast<const float4*>(src)[idx[u]];
    }
#pragma unroll
    for (int u = 0; u < 4; u++) {
        if (idx[u] >= n4) continue;
        bf16 h0, h1, h2, h3, l0, l1, l2, l3;
        split_bf16(v[u].x, h0, l0); split_bf16(v[u].y, h1, l1);
        split_bf16(v[u].z, h2, l2); split_bf16(v[u].w, h3, l3);
        uint32_t hA = ((uint32_t)__bfloat16_as_ushort(h1) << 16) | __bfloat16_as_ushort(h0);
        uint32_t hB = ((uint32_t)__bfloat16_as_ushort(h3) << 16) | __bfloat16_as_ushort(h2);
        uint32_t lA = ((uint32_t)__bfloat16_as_ushort(l1) << 16) | __bfloat16_as_ushort(l0);
        uint32_t lB = ((uint32_t)__bfloat16_as_ushort(l3) << 16) | __bfloat16_as_ushort(l2);
        reinterpret_cast<uint2*>(hi)[idx[u]] = make_uint2(hA, hB);
        reinterpret_cast<uint2*>(lo)[idx[u]] = make_uint2(lA, lB);
    }
}

__global__ void cvt4_kernel(const float* s0, bf16* h0, bf16* l0, int n0,
                            const float* s1, bf16* h1, bf16* l1, int n1,
                            const float* s2, bf16* h2, bf16* l2, int n2,
                            const float* s3, bf16* h3, bf16* l3, int n3)
{
    int i = blockIdx.x * blockDim.x + threadIdx.x;
    const float* s; bf16 *h, *l; int j = i;
    if (j < n0)      { s = s0; h = h0; l = l0; }
    else { j -= n0;
    if (j < n1)      { s = s1; h = h1; l = l1; }
    else { j -= n1;
    if (j < n2)      { s = s2; h = h2; l = l2; }
    else { j -= n2;
    if (j < n3)      { s = s3; h = h3; l = l3; }
    else return; } } }
    float4 v = reinterpret_cast<const float4*>(s)[j];
    bf16 a0, a1, a2, a3, b0, b1, b2, b3;
    split_bf16(v.x, a0, b0); split_bf16(v.y, a1, b1);
    split_bf16(v.z, a2, b2); split_bf16(v.w, a3, b3);
    uint32_t hA = ((uint32_t)__bfloat16_as_ushort(a1) << 16) | __bfloat16_as_ushort(a0);
    uint32_t hB = ((uint32_t)__bfloat16_as_ushort(a3) << 16) | __bfloat16_as_ushort(a2);
    uint32_t lA = ((uint32_t)__bfloat16_as_ushort(b1) << 16) | __bfloat16_as_ushort(b0);
    uint32_t lB = ((uint32_t)__bfloat16_as_ushort(b3) << 16) | __bfloat16_as_ushort(b2);
    reinterpret_cast<uint2*>(h)[j] = make_uint2(hA, hB);
    reinterpret_cast<uint2*>(l)[j] = make_uint2(lA, lB);
}

__global__ void cvt_xdbl_kernel(const float* __restrict__ xdbl,
                                bf16* __restrict__ hi, bf16* __restrict__ lo)
{
    int i = blockIdx.x * blockDim.x + threadIdx.x;
    int r = i >> 6, c = i & 63;
    float v = xdbl[r * XDBL_W + c];
    bf16 h, l; split_bf16(v, h, l);
    hi[i] = h; lo[i] = l;
}

// ---------------- fused residual-add + LayerNorm ------------------------------
__global__ void resln_kernel(const float* __restrict__ hin,
                             float* __restrict__ res,
                             bf16* __restrict__ hn_hi, bf16* __restrict__ hn_lo,
                             const float* __restrict__ w,
                             const float* __restrict__ b,
                             int first)
{
    const int l   = blockIdx.x;
    const int tid = threadIdx.x;
    float v[4];
    float s = 0.f, sq = 0.f;
#pragma unroll
    for (int i = 0; i < 4; i++) {
        int c = tid + i * 256;
        float x = hin[l * DMODEL + c];
        if (!first) x += res[l * DMODEL + c];
        res[l * DMODEL + c] = x;
        v[i] = x;
        s  += x;
        sq += x * x;
    }
    __shared__ float shs[8], shq[8];
    const int lane = tid & 31, warp = tid >> 5;
#pragma unroll
    for (int o = 16; o > 0; o >>= 1) {
        s  += __shfl_xor_sync(0xffffffffu, s,  o);
        sq += __shfl_xor_sync(0xffffffffu, sq, o);
    }
    if (lane == 0) { shs[warp] = s; shq[warp] = sq; }
    __syncthreads();
    s = 0.f; sq = 0.f;
#pragma unroll
    for (int i = 0; i < 8; i++) { s += shs[i]; sq += shq[i]; }

    const float inv = 1.f / (float)DMODEL;
    const float mu  = s * inv;
    const float var = sq * inv - mu * mu;
    const float rstd = rsqrtf(var + 1e-5f);
#pragma unroll
    for (int i = 0; i < 4; i++) {
        int c = tid + i * 256;
        float o = (v[i] - mu) * rstd * w[c] + b[c];
        bf16 h, lo; split_bf16(o, h, lo);
        hn_hi[l * DMODEL + c] = h;
        hn_lo[l * DMODEL + c] = lo;
    }
}

// =============================================================================
// Fused conv + SiLU + transposes, tiled 32(d) x 32(l), block (32,8).
// Emits: xc_hi/lo [l][d], xcT [d][l], zT [d][l].  (fp32 xconv store removed:
// it was dead — all consumers use xcT or xc_hi/lo.)
// Also zeroes xdbl for the x_proj split-K atomics.
// =============================================================================
__global__ void conv_tile_kernel(const float* __restrict__ xz,
                                 const float* __restrict__ cw,
                                 const float* __restrict__ cb,
                                 bf16* __restrict__ xc_hi,
                                 bf16* __restrict__ xc_lo,
                                 float* __restrict__ xcT,
                                 float* __restrict__ zT,
                                 float* __restrict__ xdbl_zero)
{
    __shared__ float xin[35][33];   // rows l0-3 .. l0+31
    __shared__ float zin[32][33];
    __shared__ float ot [32][33];

    const int d0 = blockIdx.x * 32;
    const int l0 = blockIdx.y * 32;
    const int tx = threadIdx.x, ty = threadIdx.y;

    // zero xdbl (98304 floats over 2048 CTAs x 256 threads)
    {
        int flat = (blockIdx.y * gridDim.x + blockIdx.x) * 256 + ty * 32 + tx;
        if (flat < L_SEQ * XDBL_W) xdbl_zero[flat] = 0.f;
    }

    // load x tile with 3-row halo
#pragma unroll
    for (int i = 0; i < 5; i++) {
        int y = ty + i * 8;
        if (y < 35) {
            int l = l0 + y - 3;
            xin[y][tx] = (l >= 0) ? xz[(size_t)l * (2*DINNER) + d0 + tx] : 0.f;
        }
    }
    // load z tile
#pragma unroll
    for (int i = 0; i < 4; i++) {
        int y = ty + i * 8;
        zin[y][tx] = xz[(size_t)(l0 + y) * (2*DINNER) + DINNER + d0 + tx];
    }
    __syncthreads();

    const int d = d0 + tx;
    const float w0 = cw[d*4+0], w1 = cw[d*4+1], w2 = cw[d*4+2], w3 = cw[d*4+3];
    const float cbd = cb[d];
#pragma unroll
    for (int i = 0; i < 4; i++) {
        int y = ty + i * 8;
        int l = l0 + y;
        float acc = cbd;
        acc = fmaf(w0, xin[y][tx],     acc);   // l-3
        acc = fmaf(w1, xin[y + 1][tx], acc);   // l-2
        acc = fmaf(w2, xin[y + 2][tx], acc);   // l-1
        acc = fmaf(w3, xin[y + 3][tx], acc);   // l
        acc = acc / (1.f + expf(-acc));        // SiLU
        bf16 h, lo; split_bf16(acc, h, lo);
        xc_hi[(size_t)l * DINNER + d] = h;
        xc_lo[(size_t)l * DINNER + d] = lo;
        ot[y][tx] = acc;
    }
    __syncthreads();

    // transposed writes (coalesced along l)
#pragma unroll
    for (int i = 0; i < 4; i++) {
        int y = ty + i * 8;   // local d index
        xcT[(size_t)(d0 + y) * L_SEQ + l0 + tx] = ot[tx][y];
        zT [(size_t)(d0 + y) * L_SEQ + l0 + tx] = zin[tx][y];
    }
}

// ---------------- tiled transpose: delta -> deltaT [d][t] --------------------
__global__ void transpose1_kernel(const float* __restrict__ src,
                                  float* __restrict__ dst)
{
    __shared__ float tile[32][33];
    const int c0 = blockIdx.x * 32;   // d
    const int r0 = blockIdx.y * 32;   // t
    const int x = threadIdx.x, y0 = threadIdx.y;
#pragma unroll
    for (int i = 0; i < 4; i++) {
        int y = y0 + i * 8;
        tile[y][x] = src[(size_t)(r0 + y) * DINNER + c0 + x];
    }
    __syncthreads();
#pragma unroll
    for (int i = 0; i < 4; i++) {
        int y = y0 + i * 8;
        dst[(size_t)(c0 + y) * L_SEQ + r0 + x] = tile[x][y];
    }
}

// ---------------- yT [d][t] -> y hi/lo [t][d]; zeroes out_proj target --------
__global__ void ytr_kernel(const float* __restrict__ yT,
                           bf16* __restrict__ y_hi, bf16* __restrict__ y_lo,
                           float* __restrict__ zero_buf)
{
    {
        int flat = threadIdx.y * 32 + threadIdx.x;
        int zi = (blockIdx.y * gridDim.x + blockIdx.x) * 256 + flat;
        if (zi * 2 < L_SEQ * DMODEL)
            *reinterpret_cast<float2*>(zero_buf + zi * 2) = make_float2(0.f, 0.f);
    }
    __shared__ float tile[32][33];
    const int c0 = blockIdx.x * 32;   // t
    const int r0 = blockIdx.y * 32;   // d
    const int x = threadIdx.x, y0 = threadIdx.y;
#pragma unroll
    for (int i = 0; i < 4; i++) {
        int y = y0 + i * 8;
        tile[y][x] = yT[(size_t)(r0 + y) * L_SEQ + c0 + x];
    }
    __syncthreads();
#pragma unroll
    for (int i = 0; i < 4; i++) {
        int y = y0 + i * 8;
        float v = tile[x][y];
        bf16 h, l; split_bf16(v, h, l);
        y_hi[(size_t)(c0 + y) * DINNER + r0 + x] = h;
        y_lo[(size_t)(c0 + y) * DINNER + r0 + x] = l;
    }
}

// =============================================================================
// Chunked parallel scan — round-8 form (static 10 KB smem, high occupancy).
// =============================================================================
__global__ void __launch_bounds__(256)
scan_kernel(const float* __restrict__ deltaT,
            const float* __restrict__ xcT,
            const float* __restrict__ zT,
            const float* __restrict__ xdbl,
            const float* __restrict__ A_log,
            const float* __restrict__ Dvec,
            float* __restrict__ yT)
{
    __shared__ float s_dl[L_SEQ];
    __shared__ float s_xv[L_SEQ];
    __shared__ float shP[16][16];
    __shared__ float shS[16][16];

    const int d    = blockIdx.x;
    const int tid  = threadIdx.x;
    const int lane = tid & 31;
    const int wrp  = tid >> 5;
    const int j    = wrp * 2 + (lane >> 4);
    const int s    = lane & 15;
    const int t0   = j * 64;

    for (int i = tid; i < L_SEQ; i += 256) {
        s_dl[i] = deltaT[(size_t)d * L_SEQ + i];
        s_xv[i] = xcT[(size_t)d * L_SEQ + i];
    }
    __syncthreads();

    const float a2 = -expf(A_log[d * DSTATE + s]) * 1.4426950408889634f;

    float P = 1.f, S = 0.f;
#pragma unroll 4
    for (int k = 0; k < 64; k++) {
        const int t = t0 + k;
        const float dl = s_dl[t];
        const float Bs = xdbl[t * XDBL_W + DTRANK + s];
        const float dA = exp2f(dl * a2);
        P *= dA;
        S = fmaf(dA, S, dl * s_xv[t] * Bs);
    }
    shP[j][s] = P;
    shS[j][s] = S;
    __syncthreads();

    if (tid < 16) {
        const int ss = tid;
        float run = shS[0][ss];
#pragma unroll
        for (int jj = 1; jj < 16; jj++) {
            run = fmaf(shP[jj][ss], run, shS[jj][ss]);
            shS[jj][ss] = run;
        }
    }
    __syncthreads();

    float h = (j == 0) ? 0.f : shS[j - 1][s];
    const float Dd = Dvec[d];
#pragma unroll 4
    for (int k = 0; k < 64; k++) {
        const int t = t0 + k;
        const float dl = s_dl[t];
        const float xv = s_xv[t];
        const float Bs = xdbl[t * XDBL_W + DTRANK + s];
        const float Cs = xdbl[t * XDBL_W + DTRANK + DSTATE + s];
        const float dA = exp2f(dl * a2);
        h = fmaf(dA, h, dl * xv * Bs);

        float acc = h * Cs;
        acc += __shfl_xor_sync(0xffffffffu, acc, 1);
        acc += __shfl_xor_sync(0xffffffffu, acc, 2);
        acc += __shfl_xor_sync(0xffffffffu, acc, 4);
        acc += __shfl_xor_sync(0xffffffffu, acc, 8);

        if (s == 0) {
            const float zv = zT[(size_t)d * L_SEQ + t];
            float yv = acc + xv * Dd;
            yv *= zv / (1.f + expf(-zv));
            yT[(size_t)d * L_SEQ + t] = yv;
        }
    }
}

// ---------------- host orchestration ----------------------------------------
extern "C" void kernel_launch(void* const* d_in, const int* in_sizes, int n_in,
                              void* d_out, int out_size)
{
    const float* input   = (const float*)d_in[0];
    const float* input_w = (const float*)d_in[2];
    const float* norm_w  = (const float*)d_in[3];
    const float* norm_b  = (const float*)d_in[4];
    const float* ipw     = (const float*)d_in[5];
    const float* cw      = (const float*)d_in[6];
    const float* cb      = (const float*)d_in[7];
    const float* xpw     = (const float*)d_in[8];
    const float* dtw     = (const float*)d_in[9];
    const float* dtb     = (const float*)d_in[10];
    const float* A_log   = (const float*)d_in[11];
    const float* ssm_D   = (const float*)d_in[12];
    const float* opw     = (const float*)d_in[13];

    float *res, *h, *xz, *xdbl, *delta, *deltaT, *xcT, *zT, *yT;
    cudaGetSymbolAddress((void**)&res,    g_res);
    cudaGetSymbolAddress((void**)&h,      g_h);
    cudaGetSymbolAddress((void**)&xz,     g_xz);
    cudaGetSymbolAddress((void**)&xdbl,   g_xdbl);
    cudaGetSymbolAddress((void**)&delta,  g_delta);
    cudaGetSymbolAddress((void**)&deltaT, g_deltaT);
    cudaGetSymbolAddress((void**)&xcT,    g_xcT);
    cudaGetSymbolAddress((void**)&zT,     g_zT);
    cudaGetSymbolAddress((void**)&yT,     g_yT);

    bf16 *in_hi, *in_lo, *inw_hi, *inw_lo, *ipw_hi, *ipw_lo, *xpw_hi, *xpw_lo;
    bf16 *dtw_hi, *dtw_lo, *opw_hi, *opw_lo, *hn_hi, *hn_lo, *xc_hi, *xc_lo;
    bf16 *xd_hi, *xd_lo, *y_hi, *y_lo;
    cudaGetSymbolAddress((void**)&in_hi,  c_in_hi);  cudaGetSymbolAddress((void**)&in_lo,  c_in_lo);
    cudaGetSymbolAddress((void**)&inw_hi, c_inw_hi); cudaGetSymbolAddress((void**)&inw_lo, c_inw_lo);
    cudaGetSymbolAddress((void**)&ipw_hi, c_ipw_hi); cudaGetSymbolAddress((void**)&ipw_lo, c_ipw_lo);
    cudaGetSymbolAddress((void**)&xpw_hi, c_xpw_hi); cudaGetSymbolAddress((void**)&xpw_lo, c_xpw_lo);
    cudaGetSymbolAddress((void**)&dtw_hi, c_dtw_hi); cudaGetSymbolAddress((void**)&dtw_lo, c_dtw_lo);
    cudaGetSymbolAddress((void**)&opw_hi, c_opw_hi); cudaGetSymbolAddress((void**)&opw_lo, c_opw_lo);
    cudaGetSymbolAddress((void**)&hn_hi,  c_hn_hi);  cudaGetSymbolAddress((void**)&hn_lo,  c_hn_lo);
    cudaGetSymbolAddress((void**)&xc_hi,  c_xc_hi);  cudaGetSymbolAddress((void**)&xc_lo,  c_xc_lo);
    cudaGetSymbolAddress((void**)&xd_hi,  c_xd_hi);  cudaGetSymbolAddress((void**)&xd_lo,  c_xd_lo);
    cudaGetSymbolAddress((void**)&y_hi,   c_y_hi);   cudaGetSymbolAddress((void**)&y_lo,   c_y_lo);

    cudaFuncSetAttribute(mma_gemm, cudaFuncAttributeMaxDynamicSharedMemorySize, G_SMEM);

    // conversions + zero h for input split-K
    cvt_kernel<<<(NLAYERS*2*DINNER*DMODEL/4 + 1023)/1024, 256>>>(
        ipw, ipw_hi, ipw_lo, NLAYERS*2*DINNER*DMODEL/4);
    cvt_kernel<<<(NLAYERS*DMODEL*DINNER/4 + 1023)/1024, 256>>>(
        opw, opw_hi, opw_lo, NLAYERS*DMODEL*DINNER/4);
    cvt4_kernel<<<(589824 + 255)/256, 256>>>(
        input,   in_hi,  in_lo,  L_SEQ*INLEN/4,
        input_w, inw_hi, inw_lo, DMODEL*INLEN/4,
        xpw,     xpw_hi, xpw_lo, NLAYERS*XDBL_W*DINNER/4,
        dtw,     dtw_hi, dtw_lo, NLAYERS*DINNER*DTRANK/4);
    zero_kernel<<<(L_SEQ*DMODEL/4 + 255)/256, 256>>>(h, L_SEQ*DMODEL/4);

    // h = input @ input_w^T   split-K=2 (256 CTAs), atomic
    mma_gemm<<<dim3(DMODEL/128, L_SEQ/64, 2), 256, G_SMEM>>>(
        in_hi, in_lo, INLEN, inw_hi, inw_lo, INLEN, h, DMODEL,
        DMODEL, INLEN/2, nullptr, 2);

    for (int i = 0; i < NLAYERS; i++) {
        resln_kernel<<<L_SEQ, 256>>>(h, res, hn_hi, hn_lo,
                                     norm_w + i*DMODEL, norm_b + i*DMODEL, i == 0);

        // xz = hn @ in_proj_w^T   (512 CTAs)
        mma_gemm<<<dim3((2*DINNER)/128, L_SEQ/64), 256, G_SMEM>>>(
            hn_hi, hn_lo, DMODEL,
            ipw_hi + (size_t)i*2*DINNER*DMODEL, ipw_lo + (size_t)i*2*DINNER*DMODEL, DMODEL,
            xz, 2*DINNER, 2*DINNER, DMODEL, nullptr, 0);

        // fused conv + SiLU + xcT/zT transposes + xdbl zeroing
        conv_tile_kernel<<<dim3(DINNER/32, L_SEQ/32), dim3(32, 8)>>>(
            xz, cw + (size_t)i*DINNER*4, cb + i*DINNER,
            xc_hi, xc_lo, xcT, zT, xdbl);

        // x_dbl = xconv @ x_proj_w^T   split-K=8 (128 CTAs), atomic
        mma_gemm<<<dim3(1, L_SEQ/64, 8), 256, G_SMEM>>>(
            xc_hi, xc_lo, DINNER,
            xpw_hi + (size_t)i*XDBL_W*DINNER, xpw_lo + (size_t)i*XDBL_W*DINNER, DINNER,
            xdbl, XDBL_W, XDBL_W, DINNER/8, nullptr, 2);

        cvt_xdbl_kernel<<<(L_SEQ*DTRANK)/256, 256>>>(xdbl, xd_hi, xd_lo);

        // delta = softplus(xd @ dt_proj_w^T + bias)   (256 CTAs)
        mma_gemm<<<dim3(DINNER/128, L_SEQ/64), 256, G_SMEM>>>(
            xd_hi, xd_lo, DTRANK,
            dtw_hi + (size_t)i*DINNER*DTRANK, dtw_lo + (size_t)i*DINNER*DTRANK, DTRANK,
            delta, DINNER, DINNER, DTRANK, dtb + i*DINNER, 1);

        // transpose delta only
        transpose1_kernel<<<dim3(DINNER/32, L_SEQ/32), dim3(32, 8)>>>(delta, deltaT);

        scan_kernel<<<DINNER, 256>>>(deltaT, xcT, zT, xdbl,
                                     A_log + (size_t)i*DINNER*DSTATE,
                                     ssm_D + i*DINNER, yT);

        // yT -> y hi/lo; zero the split-K out_proj target
        float* outp = (i == NLAYERS-1) ? (float*)d_out : h;
        ytr_kernel<<<dim3(L_SEQ/32, DINNER/32), dim3(32, 8)>>>(yT, y_hi, y_lo, outp);

        // h(next) = y @ out_proj_w^T   split-K=4 (512 CTAs), atomic
        mma_gemm<<<dim3(DMODEL/128, L_SEQ/64, 4), 256, G_SMEM>>>(
            y_hi, y_lo, DINNER,
            opw_hi + (size_t)i*DMODEL*DINNER, opw_lo + (size_t)i*DMODEL*DINNER, DINNER,
            outp, DMODEL, DMODEL, DINNER/4, nullptr, 2);
    }
}

// round 16
// speedup vs baseline: 1.7174x; 1.0072x over previous
#include <cuda_runtime.h>
#include <cuda_bf16.h>
#include <math.h>
#include <stdint.h>

#define L_SEQ   1024
#define INLEN   512
#define DMODEL  1024
#define NLAYERS 4
#define DINNER  2048
#define DSTATE  16
#define DTRANK  64
#define XDBL_W  96   // DT_RANK + 2*D_STATE

typedef __nv_bfloat16 bf16;

// ---------------- fp32 scratch ----------------------------------------------
__device__ float g_res   [L_SEQ * DMODEL];
__device__ float g_h     [L_SEQ * DMODEL];
__device__ float g_xz    [L_SEQ * 2 * DINNER];
__device__ float g_xdbl  [L_SEQ * XDBL_W];
__device__ float g_deltaT[DINNER * L_SEQ];
__device__ float g_xcT   [DINNER * L_SEQ];
__device__ float g_zT    [DINNER * L_SEQ];
__device__ float g_yT    [DINNER * L_SEQ];

// ---------------- bf16 hi/lo scratch -----------------------------------------
__device__ bf16 c_in_hi [L_SEQ * INLEN],        c_in_lo [L_SEQ * INLEN];
__device__ bf16 c_inw_hi[DMODEL * INLEN],       c_inw_lo[DMODEL * INLEN];
__device__ bf16 c_ipw_hi[NLAYERS * 2*DINNER * DMODEL], c_ipw_lo[NLAYERS * 2*DINNER * DMODEL];
__device__ bf16 c_xpw_hi[NLAYERS * XDBL_W * DINNER],   c_xpw_lo[NLAYERS * XDBL_W * DINNER];
__device__ bf16 c_dtw_hi[NLAYERS * DINNER * DTRANK],   c_dtw_lo[NLAYERS * DINNER * DTRANK];
__device__ bf16 c_opw_hi[NLAYERS * DMODEL * DINNER],   c_opw_lo[NLAYERS * DMODEL * DINNER];
__device__ bf16 c_hn_hi [L_SEQ * DMODEL],       c_hn_lo [L_SEQ * DMODEL];
__device__ bf16 c_xc_hi [L_SEQ * DINNER],       c_xc_lo [L_SEQ * DINNER];
__device__ bf16 c_xd_hi [L_SEQ * DTRANK],       c_xd_lo [L_SEQ * DTRANK];
__device__ bf16 c_y_hi  [L_SEQ * DINNER],       c_y_lo  [L_SEQ * DINNER];

// ============================ PTX helpers ====================================
__device__ __forceinline__ uint32_t smem_u32(const void* p) {
    uint32_t a;
    asm("{ .reg .u64 t; cvta.to.shared.u64 t, %1; cvt.u32.u64 %0, t; }"
        : "=r"(a) : "l"(p));
    return a;
}
#define CP_ASYNC16(dst, src, sz) \
    asm volatile("cp.async.cg.shared.global [%0], [%1], 16, %2;" \
                 :: "r"(dst), "l"(src), "r"(sz))
#define CP_COMMIT() asm volatile("cp.async.commit_group;" ::: "memory")
#define CP_WAIT0()  asm volatile("cp.async.wait_group 0;" ::: "memory")

#define LDM4(r0, r1, r2, r3, addr) \
    asm volatile("ldmatrix.sync.aligned.m8n8.x4.shared.b16 {%0,%1,%2,%3}, [%4];" \
                 : "=r"(r0), "=r"(r1), "=r"(r2), "=r"(r3) : "r"(addr))

#define MMA_BF16(c, a, b)                                                      \
    asm volatile(                                                              \
        "mma.sync.aligned.m16n8k16.row.col.f32.bf16.bf16.f32 "                 \
        "{%0,%1,%2,%3}, {%4,%5,%6,%7}, {%8,%9}, {%0,%1,%2,%3};"                \
        : "+f"((c)[0]), "+f"((c)[1]), "+f"((c)[2]), "+f"((c)[3])               \
        : "r"((a)[0]), "r"((a)[1]), "r"((a)[2]), "r"((a)[3]),                  \
          "r"((b)[0]), "r"((b)[1]))

__device__ __forceinline__ uint32_t swz(uint32_t off) {
    return off ^ ((off >> 3) & 0x70);
}
__device__ __forceinline__ void split_bf16(float v, bf16& hi, bf16& lo) {
    hi = __float2bfloat16(v);
    lo = __float2bfloat16(v - __bfloat162float(hi));
}
__device__ __forceinline__ float softplus_f(float v) {
    return (v > 20.f) ? v : log1pf(expf(v));
}

// =============================================================================
// bf16 hi/lo split NT GEMM (3 MMAs per k16), 64x128 tile, 2-stage cp.async,
// 2 CTAs/SM.  C[m,n] = sum_k A[m,k]*B[n,k]
//   mode 0: store; 1: softplus(acc+bias); 2: atomicAdd;
//   mode 3: softplus(acc+bias) then TRANSPOSED store C[n][m] (ldc = M-stride)
// =============================================================================
#define G_ABYTES 8192
#define G_BBYTES 16384
#define G_STAGE  (2*G_ABYTES + 2*G_BBYTES)   // 48 KB
#define G_SMEM   (2 * G_STAGE)               // 96 KB

__global__ void __launch_bounds__(256, 2)
mma_gemm(const bf16* __restrict__ Ahi, const bf16* __restrict__ Alo, int lda,
         const bf16* __restrict__ Bhi, const bf16* __restrict__ Blo, int ldb,
         float* __restrict__ C, int ldc,
         int Nvalid, int Ksplit,
         const float* __restrict__ bias, int mode)
{
    extern __shared__ char smem[];
    const uint32_t sb = smem_u32(smem);

    const int tid  = threadIdx.x;
    const int wid  = tid >> 5;
    const int lane = tid & 31;
    const int m0   = blockIdx.y * 64;
    const int n0   = blockIdx.x * 128;
    const int kbase = blockIdx.z * Ksplit;

    const int warp_m = (wid & 1) * 32;
    const int warp_n = (wid >> 1) * 32;

    float acc[2][4][4];
#pragma unroll
    for (int mt = 0; mt < 2; mt++)
#pragma unroll
        for (int nt = 0; nt < 4; nt++)
#pragma unroll
            for (int i = 0; i < 4; i++) acc[mt][nt][i] = 0.f;

    auto stage_load = [&](int c, int buf) {
        const int k0 = kbase + (c << 6);
        const uint32_t st = sb + buf * G_STAGE;
#pragma unroll
        for (int i = 0; i < 2; i++) {
            int j = tid + i * 256;
            int r = j >> 3, u = j & 7;
            uint32_t so = swz((uint32_t)(r * 128 + u * 16));
            const char* ga = (const char*)(Ahi + (size_t)(m0 + r) * lda + k0 + u * 8);
            const char* gl = (const char*)(Alo + (size_t)(m0 + r) * lda + k0 + u * 8);
            CP_ASYNC16(st + so, ga, 16);
            CP_ASYNC16(st + G_ABYTES + so, gl, 16);
        }
#pragma unroll
        for (int i = 0; i < 4; i++) {
            int j = tid + i * 256;
            int r = j >> 3, u = j & 7;
            int gn = n0 + r;
            int sz = (gn < Nvalid) ? 16 : 0;
            int gc = (gn < Nvalid) ? gn : 0;
            uint32_t so = swz((uint32_t)(r * 128 + u * 16));
            const char* gb = (const char*)(Bhi + (size_t)gc * ldb + k0 + u * 8);
            const char* gl = (const char*)(Blo + (size_t)gc * ldb + k0 + u * 8);
            CP_ASYNC16(st + 2 * G_ABYTES + so, gb, sz);
            CP_ASYNC16(st + 2 * G_ABYTES + G_BBYTES + so, gl, sz);
        }
        CP_COMMIT();
    };

    auto mma_chunk = [&](int buf) {
        const uint32_t st  = sb + buf * G_STAGE;
        const uint32_t sAh = st;
        const uint32_t sAl = st + G_ABYTES;
        const uint32_t sBh = st + 2 * G_ABYTES;
        const uint32_t sBl = sBh + G_BBYTES;
#pragma unroll
        for (int ks = 0; ks < 4; ks++) {
            const int kb = ks * 32;
            uint32_t bh[4][2], bl[4][2];
#pragma unroll
            for (int p = 0; p < 2; p++) {
                int row = warp_n + p * 16 + ((lane >> 4) << 3) + (lane & 7);
                int kbyte = kb + ((lane >> 3) & 1) * 16;
                uint32_t off = swz((uint32_t)(row * 128 + kbyte));
                LDM4(bh[2*p][0], bh[2*p][1], bh[2*p+1][0], bh[2*p+1][1], sBh + off);
                LDM4(bl[2*p][0], bl[2*p][1], bl[2*p+1][0], bl[2*p+1][1], sBl + off);
            }
#pragma unroll
            for (int mt = 0; mt < 2; mt++) {
                int row = warp_m + mt * 16 + (lane & 15);
                int kbyte = kb + (lane >> 4) * 16;
                uint32_t off = swz((uint32_t)(row * 128 + kbyte));
                uint32_t ah[4], al[4];
                LDM4(ah[0], ah[1], ah[2], ah[3], sAh + off);
                LDM4(al[0], al[1], al[2], al[3], sAl + off);
#pragma unroll
                for (int nt = 0; nt < 4; nt++) MMA_BF16(acc[mt][nt], ah, bh[nt]);
#pragma unroll
                for (int nt = 0; nt < 4; nt++) MMA_BF16(acc[mt][nt], ah, bl[nt]);
#pragma unroll
                for (int nt = 0; nt < 4; nt++) MMA_BF16(acc[mt][nt], al, bh[nt]);
            }
        }
    };

    const int NC = Ksplit >> 6;
    stage_load(0, 0);
    for (int c = 0; c < NC; c++) {
        CP_WAIT0();
        __syncthreads();
        if (c + 1 < NC) stage_load(c + 1, (c + 1) & 1);
        mma_chunk(c & 1);
    }

    // ---- epilogue ----
    const int qrow = lane >> 2;
    const int qcol = (lane & 3) * 2;

    if (mode == 3) {
        // softplus(acc+bias), stage 64x128 tile in smem, transposed store
        float* tileT = reinterpret_cast<float*>(smem);   // [64][129]
        __syncthreads();   // pipeline drained; safe to reuse stages
#pragma unroll
        for (int mt = 0; mt < 2; mt++) {
            int lr0 = warp_m + mt * 16 + qrow;
            int lr1 = lr0 + 8;
#pragma unroll
            for (int nt = 0; nt < 4; nt++) {
                int lc = warp_n + nt * 8 + qcol;
                float b0 = bias[n0 + lc], b1 = bias[n0 + lc + 1];
                tileT[lr0 * 129 + lc]     = softplus_f(acc[mt][nt][0] + b0);
                tileT[lr0 * 129 + lc + 1] = softplus_f(acc[mt][nt][1] + b1);
                tileT[lr1 * 129 + lc]     = softplus_f(acc[mt][nt][2] + b0);
                tileT[lr1 * 129 + lc + 1] = softplus_f(acc[mt][nt][3] + b1);
            }
        }
        __syncthreads();
        // write: column c of tile -> deltaT[(n0+c)*ldc + m0 .. +63]
        const int c  = tid >> 1;
        const int hf = (tid & 1) * 32;
        float* dst = C + (size_t)(n0 + c) * ldc + m0 + hf;
#pragma unroll
        for (int k = 0; k < 32; k += 4) {
            float4 v;
            v.x = tileT[(hf + k + 0) * 129 + c];
            v.y = tileT[(hf + k + 1) * 129 + c];
            v.z = tileT[(hf + k + 2) * 129 + c];
            v.w = tileT[(hf + k + 3) * 129 + c];
            *reinterpret_cast<float4*>(dst + k) = v;
        }
        return;
    }

#pragma unroll
    for (int mt = 0; mt < 2; mt++) {
        int row0 = m0 + warp_m + mt * 16 + qrow;
        int row1 = row0 + 8;
#pragma unroll
        for (int nt = 0; nt < 4; nt++) {
            int gn = n0 + warp_n + nt * 8 + qcol;
            if (gn >= Nvalid) continue;
            float2 v0 = make_float2(acc[mt][nt][0], acc[mt][nt][1]);
            float2 v1 = make_float2(acc[mt][nt][2], acc[mt][nt][3]);
            if (mode == 1) {
                float b0 = bias[gn], b1 = bias[gn + 1];
                v0.x = softplus_f(v0.x + b0); v0.y = softplus_f(v0.y + b1);
                v1.x = softplus_f(v1.x + b0); v1.y = softplus_f(v1.y + b1);
            }
            if (mode == 2) {
                atomicAdd(&C[(size_t)row0 * ldc + gn],     v0.x);
                atomicAdd(&C[(size_t)row0 * ldc + gn + 1], v0.y);
                atomicAdd(&C[(size_t)row1 * ldc + gn],     v1.x);
                atomicAdd(&C[(size_t)row1 * ldc + gn + 1], v1.y);
            } else {
                *reinterpret_cast<float2*>(C + (size_t)row0 * ldc + gn) = v0;
                *reinterpret_cast<float2*>(C + (size_t)row1 * ldc + gn) = v1;
            }
        }
    }
}

// ---------------- zero a float buffer (for split-K atomic targets) -----------
__global__ void zero_kernel(float* __restrict__ p, int n4)
{
    int i = blockIdx.x * blockDim.x + threadIdx.x;
    if (i < n4)
        reinterpret_cast<float4*>(p)[i] = make_float4(0.f, 0.f, 0.f, 0.f);
}

// ---------------- fp32 -> bf16 hi/lo converters (MLP=4) ----------------------
__global__ void cvt_kernel(const float* __restrict__ src,
                           bf16* __restrict__ hi, bf16* __restrict__ lo, int n4)
{
    int base = blockIdx.x * blockDim.x * 4 + threadIdx.x;
    float4 v[4];
    int idx[4];
#pragma unroll
    for (int u = 0; u < 4; u++) {
        idx[u] = base + u * 256;
        if (idx[u] < n4) v[u] = reinterpret_cast<const float4*>(src)[idx[u]];
    }
#pragma unroll
    for (int u = 0; u < 4; u++) {
        if (idx[u] >= n4) continue;
        bf16 h0, h1, h2, h3, l0, l1, l2, l3;
        split_bf16(v[u].x, h0, l0); split_bf16(v[u].y, h1, l1);
        split_bf16(v[u].z, h2, l2); split_bf16(v[u].w, h3, l3);
        uint32_t hA = ((uint32_t)__bfloat16_as_ushort(h1) << 16) | __bfloat16_as_ushort(h0);
        uint32_t hB = ((uint32_t)__bfloat16_as_ushort(h3) << 16) | __bfloat16_as_ushort(h2);
        uint32_t lA = ((uint32_t)__bfloat16_as_ushort(l1) << 16) | __bfloat16_as_ushort(l0);
        uint32_t lB = ((uint32_t)__bfloat16_as_ushort(l3) << 16) | __bfloat16_as_ushort(l2);
        reinterpret_cast<uint2*>(hi)[idx[u]] = make_uint2(hA, hB);
        reinterpret_cast<uint2*>(lo)[idx[u]] = make_uint2(lA, lB);
    }
}

__global__ void cvt4_kernel(const float* s0, bf16* h0, bf16* l0, int n0,
                            const float* s1, bf16* h1, bf16* l1, int n1,
                            const float* s2, bf16* h2, bf16* l2, int n2,
                            const float* s3, bf16* h3, bf16* l3, int n3)
{
    int i = blockIdx.x * blockDim.x + threadIdx.x;
    const float* s; bf16 *h, *l; int j = i;
    if (j < n0)      { s = s0; h = h0; l = l0; }
    else { j -= n0;
    if (j < n1)      { s = s1; h = h1; l = l1; }
    else { j -= n1;
    if (j < n2)      { s = s2; h = h2; l = l2; }
    else { j -= n2;
    if (j < n3)      { s = s3; h = h3; l = l3; }
    else return; } } }
    float4 v = reinterpret_cast<const float4*>(s)[j];
    bf16 a0, a1, a2, a3, b0, b1, b2, b3;
    split_bf16(v.x, a0, b0); split_bf16(v.y, a1, b1);
    split_bf16(v.z, a2, b2); split_bf16(v.w, a3, b3);
    uint32_t hA = ((uint32_t)__bfloat16_as_ushort(a1) << 16) | __bfloat16_as_ushort(a0);
    uint32_t hB = ((uint32_t)__bfloat16_as_ushort(a3) << 16) | __bfloat16_as_ushort(a2);
    uint32_t lA = ((uint32_t)__bfloat16_as_ushort(b1) << 16) | __bfloat16_as_ushort(b0);
    uint32_t lB = ((uint32_t)__bfloat16_as_ushort(b3) << 16) | __bfloat16_as_ushort(b2);
    reinterpret_cast<uint2*>(h)[j] = make_uint2(hA, hB);
    reinterpret_cast<uint2*>(l)[j] = make_uint2(lA, lB);
}

__global__ void cvt_xdbl_kernel(const float* __restrict__ xdbl,
                                bf16* __restrict__ hi, bf16* __restrict__ lo)
{
    int i = blockIdx.x * blockDim.x + threadIdx.x;
    int r = i >> 6, c = i & 63;
    float v = xdbl[r * XDBL_W + c];
    bf16 h, l; split_bf16(v, h, l);
    hi[i] = h; lo[i] = l;
}

// ---------------- fused residual-add + LayerNorm ------------------------------
__global__ void resln_kernel(const float* __restrict__ hin,
                             float* __restrict__ res,
                             bf16* __restrict__ hn_hi, bf16* __restrict__ hn_lo,
                             const float* __restrict__ w,
                             const float* __restrict__ b,
                             int first)
{
    const int l   = blockIdx.x;
    const int tid = threadIdx.x;
    float v[4];
    float s = 0.f, sq = 0.f;
#pragma unroll
    for (int i = 0; i < 4; i++) {
        int c = tid + i * 256;
        float x = hin[l * DMODEL + c];
        if (!first) x += res[l * DMODEL + c];
        res[l * DMODEL + c] = x;
        v[i] = x;
        s  += x;
        sq += x * x;
    }
    __shared__ float shs[8], shq[8];
    const int lane = tid & 31, warp = tid >> 5;
#pragma unroll
    for (int o = 16; o > 0; o >>= 1) {
        s  += __shfl_xor_sync(0xffffffffu, s,  o);
        sq += __shfl_xor_sync(0xffffffffu, sq, o);
    }
    if (lane == 0) { shs[warp] = s; shq[warp] = sq; }
    __syncthreads();
    s = 0.f; sq = 0.f;
#pragma unroll
    for (int i = 0; i < 8; i++) { s += shs[i]; sq += shq[i]; }

    const float inv = 1.f / (float)DMODEL;
    const float mu  = s * inv;
    const float var = sq * inv - mu * mu;
    const float rstd = rsqrtf(var + 1e-5f);
#pragma unroll
    for (int i = 0; i < 4; i++) {
        int c = tid + i * 256;
        float o = (v[i] - mu) * rstd * w[c] + b[c];
        bf16 h, lo; split_bf16(o, h, lo);
        hn_hi[l * DMODEL + c] = h;
        hn_lo[l * DMODEL + c] = lo;
    }
}

// =============================================================================
// Fused conv + SiLU + transposes, tiled 32(d) x 32(l), block (32,8).
// Emits: xc_hi/lo [l][d], xcT [d][l], zT [d][l]; zeroes xdbl.
// =============================================================================
__global__ void conv_tile_kernel(const float* __restrict__ xz,
                                 const float* __restrict__ cw,
                                 const float* __restrict__ cb,
                                 bf16* __restrict__ xc_hi,
                                 bf16* __restrict__ xc_lo,
                                 float* __restrict__ xcT,
                                 float* __restrict__ zT,
                                 float* __restrict__ xdbl_zero)
{
    __shared__ float xin[35][33];
    __shared__ float zin[32][33];
    __shared__ float ot [32][33];

    const int d0 = blockIdx.x * 32;
    const int l0 = blockIdx.y * 32;
    const int tx = threadIdx.x, ty = threadIdx.y;

    {
        int flat = (blockIdx.y * gridDim.x + blockIdx.x) * 256 + ty * 32 + tx;
        if (flat < L_SEQ * XDBL_W) xdbl_zero[flat] = 0.f;
    }

#pragma unroll
    for (int i = 0; i < 5; i++) {
        int y = ty + i * 8;
        if (y < 35) {
            int l = l0 + y - 3;
            xin[y][tx] = (l >= 0) ? xz[(size_t)l * (2*DINNER) + d0 + tx] : 0.f;
        }
    }
#pragma unroll
    for (int i = 0; i < 4; i++) {
        int y = ty + i * 8;
        zin[y][tx] = xz[(size_t)(l0 + y) * (2*DINNER) + DINNER + d0 + tx];
    }
    __syncthreads();

    const int d = d0 + tx;
    const float w0 = cw[d*4+0], w1 = cw[d*4+1], w2 = cw[d*4+2], w3 = cw[d*4+3];
    const float cbd = cb[d];
#pragma unroll
    for (int i = 0; i < 4; i++) {
        int y = ty + i * 8;
        int l = l0 + y;
        float acc = cbd;
        acc = fmaf(w0, xin[y][tx],     acc);
        acc = fmaf(w1, xin[y + 1][tx], acc);
        acc = fmaf(w2, xin[y + 2][tx], acc);
        acc = fmaf(w3, xin[y + 3][tx], acc);
        acc = acc / (1.f + expf(-acc));
        bf16 h, lo; split_bf16(acc, h, lo);
        xc_hi[(size_t)l * DINNER + d] = h;
        xc_lo[(size_t)l * DINNER + d] = lo;
        ot[y][tx] = acc;
    }
    __syncthreads();

#pragma unroll
    for (int i = 0; i < 4; i++) {
        int y = ty + i * 8;
        xcT[(size_t)(d0 + y) * L_SEQ + l0 + tx] = ot[tx][y];
        zT [(size_t)(d0 + y) * L_SEQ + l0 + tx] = zin[tx][y];
    }
}

// ---------------- yT [d][t] -> y hi/lo [t][d]; zeroes out_proj target --------
__global__ void ytr_kernel(const float* __restrict__ yT,
                           bf16* __restrict__ y_hi, bf16* __restrict__ y_lo,
                           float* __restrict__ zero_buf)
{
    {
        int flat = threadIdx.y * 32 + threadIdx.x;
        int zi = (blockIdx.y * gridDim.x + blockIdx.x) * 256 + flat;
        if (zi * 2 < L_SEQ * DMODEL)
            *reinterpret_cast<float2*>(zero_buf + zi * 2) = make_float2(0.f, 0.f);
    }
    __shared__ float tile[32][33];
    const int c0 = blockIdx.x * 32;   // t
    const int r0 = blockIdx.y * 32;   // d
    const int x = threadIdx.x, y0 = threadIdx.y;
#pragma unroll
    for (int i = 0; i < 4; i++) {
        int y = y0 + i * 8;
        tile[y][x] = yT[(size_t)(r0 + y) * L_SEQ + c0 + x];
    }
    __syncthreads();
#pragma unroll
    for (int i = 0; i < 4; i++) {
        int y = y0 + i * 8;
        float v = tile[x][y];
        bf16 h, l; split_bf16(v, h, l);
        y_hi[(size_t)(c0 + y) * DINNER + r0 + x] = h;
        y_lo[(size_t)(c0 + y) * DINNER + r0 + x] = l;
    }
}

// =============================================================================
// Chunked parallel scan — round-8 form (static 10 KB smem, high occupancy).
// =============================================================================
__global__ void __launch_bounds__(256)
scan_kernel(const float* __restrict__ deltaT,
            const float* __restrict__ xcT,
            const float* __restrict__ zT,
            const float* __restrict__ xdbl,
            const float* __restrict__ A_log,
            const float* __restrict__ Dvec,
            float* __restrict__ yT)
{
    __shared__ float s_dl[L_SEQ];
    __shared__ float s_xv[L_SEQ];
    __shared__ float shP[16][16];
    __shared__ float shS[16][16];

    const int d    = blockIdx.x;
    const int tid  = threadIdx.x;
    const int lane = tid & 31;
    const int wrp  = tid >> 5;
    const int j    = wrp * 2 + (lane >> 4);
    const int s    = lane & 15;
    const int t0   = j * 64;

    for (int i = tid; i < L_SEQ; i += 256) {
        s_dl[i] = deltaT[(size_t)d * L_SEQ + i];
        s_xv[i] = xcT[(size_t)d * L_SEQ + i];
    }
    __syncthreads();

    const float a2 = -expf(A_log[d * DSTATE + s]) * 1.4426950408889634f;

    float P = 1.f, S = 0.f;
#pragma unroll 4
    for (int k = 0; k < 64; k++) {
        const int t = t0 + k;
        const float dl = s_dl[t];
        const float Bs = xdbl[t * XDBL_W + DTRANK + s];
        const float dA = exp2f(dl * a2);
        P *= dA;
        S = fmaf(dA, S, dl * s_xv[t] * Bs);
    }
    shP[j][s] = P;
    shS[j][s] = S;
    __syncthreads();

    if (tid < 16) {
        const int ss = tid;
        float run = shS[0][ss];
#pragma unroll
        for (int jj = 1; jj < 16; jj++) {
            run = fmaf(shP[jj][ss], run, shS[jj][ss]);
            shS[jj][ss] = run;
        }
    }
    __syncthreads();

    float h = (j == 0) ? 0.f : shS[j - 1][s];
    const float Dd = Dvec[d];
#pragma unroll 4
    for (int k = 0; k < 64; k++) {
        const int t = t0 + k;
        const float dl = s_dl[t];
        const float xv = s_xv[t];
        const float Bs = xdbl[t * XDBL_W + DTRANK + s];
        const float Cs = xdbl[t * XDBL_W + DTRANK + DSTATE + s];
        const float dA = exp2f(dl * a2);
        h = fmaf(dA, h, dl * xv * Bs);

        float acc = h * Cs;
        acc += __shfl_xor_sync(0xffffffffu, acc, 1);
        acc += __shfl_xor_sync(0xffffffffu, acc, 2);
        acc += __shfl_xor_sync(0xffffffffu, acc, 4);
        acc += __shfl_xor_sync(0xffffffffu, acc, 8);

        if (s == 0) {
            const float zv = zT[(size_t)d * L_SEQ + t];
            float yv = acc + xv * Dd;
            yv *= zv / (1.f + expf(-zv));
            yT[(size_t)d * L_SEQ + t] = yv;
        }
    }
}

// ---------------- host orchestration ----------------------------------------
extern "C" void kernel_launch(void* const* d_in, const int* in_sizes, int n_in,
                              void* d_out, int out_size)
{
    const float* input   = (const float*)d_in[0];
    const float* input_w = (const float*)d_in[2];
    const float* norm_w  = (const float*)d_in[3];
    const float* norm_b  = (const float*)d_in[4];
    const float* ipw     = (const float*)d_in[5];
    const float* cw      = (const float*)d_in[6];
    const float* cb      = (const float*)d_in[7];
    const float* xpw     = (const float*)d_in[8];
    const float* dtw     = (const float*)d_in[9];
    const float* dtb     = (const float*)d_in[10];
    const float* A_log   = (const float*)d_in[11];
    const float* ssm_D   = (const float*)d_in[12];
    const float* opw     = (const float*)d_in[13];

    float *res, *h, *xz, *xdbl, *deltaT, *xcT, *zT, *yT;
    cudaGetSymbolAddress((void**)&res,    g_res);
    cudaGetSymbolAddress((void**)&h,      g_h);
    cudaGetSymbolAddress((void**)&xz,     g_xz);
    cudaGetSymbolAddress((void**)&xdbl,   g_xdbl);
    cudaGetSymbolAddress((void**)&deltaT, g_deltaT);
    cudaGetSymbolAddress((void**)&xcT,    g_xcT);
    cudaGetSymbolAddress((void**)&zT,     g_zT);
    cudaGetSymbolAddress((void**)&yT,     g_yT);

    bf16 *in_hi, *in_lo, *inw_hi, *inw_lo, *ipw_hi, *ipw_lo, *xpw_hi, *xpw_lo;
    bf16 *dtw_hi, *dtw_lo, *opw_hi, *opw_lo, *hn_hi, *hn_lo, *xc_hi, *xc_lo;
    bf16 *xd_hi, *xd_lo, *y_hi, *y_lo;
    cudaGetSymbolAddress((void**)&in_hi,  c_in_hi);  cudaGetSymbolAddress((void**)&in_lo,  c_in_lo);
    cudaGetSymbolAddress((void**)&inw_hi, c_inw_hi); cudaGetSymbolAddress((void**)&inw_lo, c_inw_lo);
    cudaGetSymbolAddress((void**)&ipw_hi, c_ipw_hi); cudaGetSymbolAddress((void**)&ipw_lo, c_ipw_lo);
    cudaGetSymbolAddress((void**)&xpw_hi, c_xpw_hi); cudaGetSymbolAddress((void**)&xpw_lo, c_xpw_lo);
    cudaGetSymbolAddress((void**)&dtw_hi, c_dtw_hi); cudaGetSymbolAddress((void**)&dtw_lo, c_dtw_lo);
    cudaGetSymbolAddress((void**)&opw_hi, c_opw_hi); cudaGetSymbolAddress((void**)&opw_lo, c_opw_lo);
    cudaGetSymbolAddress((void**)&hn_hi,  c_hn_hi);  cudaGetSymbolAddress((void**)&hn_lo,  c_hn_lo);
    cudaGetSymbolAddress((void**)&xc_hi,  c_xc_hi);  cudaGetSymbolAddress((void**)&xc_lo,  c_xc_lo);
    cudaGetSymbolAddress((void**)&xd_hi,  c_xd_hi);  cudaGetSymbolAddress((void**)&xd_lo,  c_xd_lo);
    cudaGetSymbolAddress((void**)&y_hi,   c_y_hi);   cudaGetSymbolAddress((void**)&y_lo,   c_y_lo);

    cudaFuncSetAttribute(mma_gemm, cudaFuncAttributeMaxDynamicSharedMemorySize, G_SMEM);

    // conversions + zero h for input split-K
    cvt_kernel<<<(NLAYERS*2*DINNER*DMODEL/4 + 1023)/1024, 256>>>(
        ipw, ipw_hi, ipw_lo, NLAYERS*2*DINNER*DMODEL/4);
    cvt_kernel<<<(NLAYERS*DMODEL*DINNER/4 + 1023)/1024, 256>>>(
        opw, opw_hi, opw_lo, NLAYERS*DMODEL*DINNER/4);
    cvt4_kernel<<<(589824 + 255)/256, 256>>>(
        input,   in_hi,  in_lo,  L_SEQ*INLEN/4,
        input_w, inw_hi, inw_lo, DMODEL*INLEN/4,
        xpw,     xpw_hi, xpw_lo, NLAYERS*XDBL_W*DINNER/4,
        dtw,     dtw_hi, dtw_lo, NLAYERS*DINNER*DTRANK/4);
    zero_kernel<<<(L_SEQ*DMODEL/4 + 255)/256, 256>>>(h, L_SEQ*DMODEL/4);

    // h = input @ input_w^T   split-K=2 (256 CTAs), atomic
    mma_gemm<<<dim3(DMODEL/128, L_SEQ/64, 2), 256, G_SMEM>>>(
        in_hi, in_lo, INLEN, inw_hi, inw_lo, INLEN, h, DMODEL,
        DMODEL, INLEN/2, nullptr, 2);

    for (int i = 0; i < NLAYERS; i++) {
        resln_kernel<<<L_SEQ, 256>>>(h, res, hn_hi, hn_lo,
                                     norm_w + i*DMODEL, norm_b + i*DMODEL, i == 0);

        // xz = hn @ in_proj_w^T   (512 CTAs)
        mma_gemm<<<dim3((2*DINNER)/128, L_SEQ/64), 256, G_SMEM>>>(
            hn_hi, hn_lo, DMODEL,
            ipw_hi + (size_t)i*2*DINNER*DMODEL, ipw_lo + (size_t)i*2*DINNER*DMODEL, DMODEL,
            xz, 2*DINNER, 2*DINNER, DMODEL, nullptr, 0);

        // fused conv + SiLU + xcT/zT transposes + xdbl zeroing
        conv_tile_kernel<<<dim3(DINNER/32, L_SEQ/32), dim3(32, 8)>>>(
            xz, cw + (size_t)i*DINNER*4, cb + i*DINNER,
            xc_hi, xc_lo, xcT, zT, xdbl);

        // x_dbl = xconv @ x_proj_w^T   split-K=8 (128 CTAs), atomic
        mma_gemm<<<dim3(1, L_SEQ/64, 8), 256, G_SMEM>>>(
            xc_hi, xc_lo, DINNER,
            xpw_hi + (size_t)i*XDBL_W*DINNER, xpw_lo + (size_t)i*XDBL_W*DINNER, DINNER,
            xdbl, XDBL_W, XDBL_W, DINNER/8, nullptr, 2);

        cvt_xdbl_kernel<<<(L_SEQ*DTRANK)/256, 256>>>(xdbl, xd_hi, xd_lo);

        // deltaT = softplus(xd @ dt_proj_w^T + bias)^T  (mode 3: direct
        // transposed store; ldc = L_SEQ) — transpose1 kernel eliminated
        mma_gemm<<<dim3(DINNER/128, L_SEQ/64), 256, G_SMEM>>>(
            xd_hi, xd_lo, DTRANK,
            dtw_hi + (size_t)i*DINNER*DTRANK, dtw_lo + (size_t)i*DINNER*DTRANK, DTRANK,
            deltaT, L_SEQ, DINNER, DTRANK, dtb + i*DINNER, 3);

        scan_kernel<<<DINNER, 256>>>(deltaT, xcT, zT, xdbl,
                                     A_log + (size_t)i*DINNER*DSTATE,
                                     ssm_D + i*DINNER, yT);

        // yT -> y hi/lo; zero the split-K out_proj target
        float* outp = (i == NLAYERS-1) ? (float*)d_out : h;
        ytr_kernel<<<dim3(L_SEQ/32, DINNER/32), dim3(32, 8)>>>(yT, y_hi, y_lo, outp);

        // h(next) = y @ out_proj_w^T   split-K=4 (512 CTAs), atomic
        mma_gemm<<<dim3(DMODEL/128, L_SEQ/64, 4), 256, G_SMEM>>>(
            y_hi, y_lo, DINNER,
            opw_hi + (size_t)i*DMODEL*DINNER, opw_lo + (size_t)i*DMODEL*DINNER, DINNER,
            outp, DMODEL, DMODEL, DINNER/4, nullptr, 2);
    }
}

// round 17
// speedup vs baseline: 1.7570x; 1.0230x over previous
#include <cuda_runtime.h>
#include <cuda_bf16.h>
#include <math.h>
#include <stdint.h>

#define L_SEQ   1024
#define INLEN   512
#define DMODEL  1024
#define NLAYERS 4
#define DINNER  2048
#define DSTATE  16
#define DTRANK  64
#define XDBL_W  96   // DT_RANK + 2*D_STATE

typedef __nv_bfloat16 bf16;

// ---------------- fp32 scratch ----------------------------------------------
__device__ float g_res   [L_SEQ * DMODEL];
__device__ float g_h     [L_SEQ * DMODEL];
__device__ float g_xz    [L_SEQ * 2 * DINNER];
__device__ float g_xdbl  [L_SEQ * XDBL_W];
__device__ float g_deltaT[DINNER * L_SEQ];
__device__ float g_xcT   [DINNER * L_SEQ];
__device__ float g_zT    [DINNER * L_SEQ];
__device__ float g_yT    [DINNER * L_SEQ];

// ---------------- bf16 hi/lo scratch -----------------------------------------
__device__ bf16 c_in_hi [L_SEQ * INLEN],        c_in_lo [L_SEQ * INLEN];
__device__ bf16 c_inw_hi[DMODEL * INLEN],       c_inw_lo[DMODEL * INLEN];
__device__ bf16 c_ipw_hi[NLAYERS * 2*DINNER * DMODEL], c_ipw_lo[NLAYERS * 2*DINNER * DMODEL];
__device__ bf16 c_xpw_hi[NLAYERS * XDBL_W * DINNER],   c_xpw_lo[NLAYERS * XDBL_W * DINNER];
__device__ bf16 c_dtw_hi[NLAYERS * DINNER * DTRANK],   c_dtw_lo[NLAYERS * DINNER * DTRANK];
__device__ bf16 c_opw_hi[NLAYERS * DMODEL * DINNER],   c_opw_lo[NLAYERS * DMODEL * DINNER];
__device__ bf16 c_hn_hi [L_SEQ * DMODEL],       c_hn_lo [L_SEQ * DMODEL];
__device__ bf16 c_xc_hi [L_SEQ * DINNER],       c_xc_lo [L_SEQ * DINNER];
__device__ bf16 c_y_hi  [L_SEQ * DINNER],       c_y_lo  [L_SEQ * DINNER];

// ============================ PTX helpers ====================================
__device__ __forceinline__ uint32_t smem_u32(const void* p) {
    uint32_t a;
    asm("{ .reg .u64 t; cvta.to.shared.u64 t, %1; cvt.u32.u64 %0, t; }"
        : "=r"(a) : "l"(p));
    return a;
}
#define CP_ASYNC16(dst, src, sz) \
    asm volatile("cp.async.cg.shared.global [%0], [%1], 16, %2;" \
                 :: "r"(dst), "l"(src), "r"(sz))
#define CP_COMMIT() asm volatile("cp.async.commit_group;" ::: "memory")
#define CP_WAIT0()  asm volatile("cp.async.wait_group 0;" ::: "memory")

#define LDM4(r0, r1, r2, r3, addr) \
    asm volatile("ldmatrix.sync.aligned.m8n8.x4.shared.b16 {%0,%1,%2,%3}, [%4];" \
                 : "=r"(r0), "=r"(r1), "=r"(r2), "=r"(r3) : "r"(addr))

#define MMA_BF16(c, a, b)                                                      \
    asm volatile(                                                              \
        "mma.sync.aligned.m16n8k16.row.col.f32.bf16.bf16.f32 "                 \
        "{%0,%1,%2,%3}, {%4,%5,%6,%7}, {%8,%9}, {%0,%1,%2,%3};"                \
        : "+f"((c)[0]), "+f"((c)[1]), "+f"((c)[2]), "+f"((c)[3])               \
        : "r"((a)[0]), "r"((a)[1]), "r"((a)[2]), "r"((a)[3]),                  \
          "r"((b)[0]), "r"((b)[1]))

__device__ __forceinline__ uint32_t swz(uint32_t off) {
    return off ^ ((off >> 3) & 0x70);
}
__device__ __forceinline__ void split_bf16(float v, bf16& hi, bf16& lo) {
    hi = __float2bfloat16(v);
    lo = __float2bfloat16(v - __bfloat162float(hi));
}
__device__ __forceinline__ float softplus_f(float v) {
    return (v > 20.f) ? v : log1pf(expf(v));
}
__device__ __forceinline__ uint32_t pack2(bf16 a, bf16 b) {
    return ((uint32_t)__bfloat16_as_ushort(b) << 16) | __bfloat16_as_ushort(a);
}

// =============================================================================
// bf16 hi/lo split NT GEMM (3 MMAs per k16), 64x128 tile, 2-stage cp.async,
// 2 CTAs/SM.  C[m,n] = sum_k A[m,k]*B[n,k]
//   mode 0: store; 1: softplus(acc+bias); 2: atomicAdd;
//   mode 3: softplus(acc+bias) + TRANSPOSED store C[n][m] (ldc = M-stride)
//   afp32 != 0: Ahi is const float* (lda in floats), converted inline.
// =============================================================================
#define G_ABYTES 8192
#define G_BBYTES 16384
#define G_STAGE  (2*G_ABYTES + 2*G_BBYTES)   // 48 KB
#define G_SMEM   (2 * G_STAGE)               // 96 KB

__global__ void __launch_bounds__(256, 2)
mma_gemm(const void* __restrict__ Ahi_v, const bf16* __restrict__ Alo, int lda,
         const bf16* __restrict__ Bhi, const bf16* __restrict__ Blo, int ldb,
         float* __restrict__ C, int ldc,
         int Nvalid, int Ksplit,
         const float* __restrict__ bias, int mode, int afp32)
{
    extern __shared__ char smem[];
    const uint32_t sb = smem_u32(smem);

    const int tid  = threadIdx.x;
    const int wid  = tid >> 5;
    const int lane = tid & 31;
    const int m0   = blockIdx.y * 64;
    const int n0   = blockIdx.x * 128;
    const int kbase = blockIdx.z * Ksplit;

    const int warp_m = (wid & 1) * 32;
    const int warp_n = (wid >> 1) * 32;

    float acc[2][4][4];
#pragma unroll
    for (int mt = 0; mt < 2; mt++)
#pragma unroll
        for (int nt = 0; nt < 4; nt++)
#pragma unroll
            for (int i = 0; i < 4; i++) acc[mt][nt][i] = 0.f;

    auto stage_load = [&](int c, int buf) {
        const int k0 = kbase + (c << 6);
        const uint32_t st = sb + buf * G_STAGE;
        if (afp32) {
            const float* Afp = (const float*)Ahi_v;
#pragma unroll
            for (int i = 0; i < 2; i++) {
                int j = tid + i * 256;
                int r = j >> 3, u = j & 7;
                const float* src = Afp + (size_t)(m0 + r) * lda + k0 + u * 8;
                float4 v0 = *reinterpret_cast<const float4*>(src);
                float4 v1 = *reinterpret_cast<const float4*>(src + 4);
                bf16 h0,h1,h2,h3,h4,h5,h6,h7, l0,l1,l2,l3,l4,l5,l6,l7;
                split_bf16(v0.x,h0,l0); split_bf16(v0.y,h1,l1);
                split_bf16(v0.z,h2,l2); split_bf16(v0.w,h3,l3);
                split_bf16(v1.x,h4,l4); split_bf16(v1.y,h5,l5);
                split_bf16(v1.z,h6,l6); split_bf16(v1.w,h7,l7);
                uint32_t so = swz((uint32_t)(r * 128 + u * 16));
                *reinterpret_cast<uint4*>(smem + buf * G_STAGE + so) =
                    make_uint4(pack2(h0,h1), pack2(h2,h3), pack2(h4,h5), pack2(h6,h7));
                *reinterpret_cast<uint4*>(smem + buf * G_STAGE + G_ABYTES + so) =
                    make_uint4(pack2(l0,l1), pack2(l2,l3), pack2(l4,l5), pack2(l6,l7));
            }
        } else {
            const bf16* Ahi = (const bf16*)Ahi_v;
#pragma unroll
            for (int i = 0; i < 2; i++) {
                int j = tid + i * 256;
                int r = j >> 3, u = j & 7;
                uint32_t so = swz((uint32_t)(r * 128 + u * 16));
                const char* ga = (const char*)(Ahi + (size_t)(m0 + r) * lda + k0 + u * 8);
                const char* gl = (const char*)(Alo + (size_t)(m0 + r) * lda + k0 + u * 8);
                CP_ASYNC16(st + so, ga, 16);
                CP_ASYNC16(st + G_ABYTES + so, gl, 16);
            }
        }
#pragma unroll
        for (int i = 0; i < 4; i++) {
            int j = tid + i * 256;
            int r = j >> 3, u = j & 7;
            int gn = n0 + r;
            int sz = (gn < Nvalid) ? 16 : 0;
            int gc = (gn < Nvalid) ? gn : 0;
            uint32_t so = swz((uint32_t)(r * 128 + u * 16));
            const char* gb = (const char*)(Bhi + (size_t)gc * ldb + k0 + u * 8);
            const char* gl = (const char*)(Blo + (size_t)gc * ldb + k0 + u * 8);
            CP_ASYNC16(st + 2 * G_ABYTES + so, gb, sz);
            CP_ASYNC16(st + 2 * G_ABYTES + G_BBYTES + so, gl, sz);
        }
        CP_COMMIT();
    };

    auto mma_chunk = [&](int buf) {
        const uint32_t st  = sb + buf * G_STAGE;
        const uint32_t sAh = st;
        const uint32_t sAl = st + G_ABYTES;
        const uint32_t sBh = st + 2 * G_ABYTES;
        const uint32_t sBl = sBh + G_BBYTES;
#pragma unroll
        for (int ks = 0; ks < 4; ks++) {
            const int kb = ks * 32;
            uint32_t bh[4][2], bl[4][2];
#pragma unroll
            for (int p = 0; p < 2; p++) {
                int row = warp_n + p * 16 + ((lane >> 4) << 3) + (lane & 7);
                int kbyte = kb + ((lane >> 3) & 1) * 16;
                uint32_t off = swz((uint32_t)(row * 128 + kbyte));
                LDM4(bh[2*p][0], bh[2*p][1], bh[2*p+1][0], bh[2*p+1][1], sBh + off);
                LDM4(bl[2*p][0], bl[2*p][1], bl[2*p+1][0], bl[2*p+1][1], sBl + off);
            }
#pragma unroll
            for (int mt = 0; mt < 2; mt++) {
                int row = warp_m + mt * 16 + (lane & 15);
                int kbyte = kb + (lane >> 4) * 16;
                uint32_t off = swz((uint32_t)(row * 128 + kbyte));
                uint32_t ah[4], al[4];
                LDM4(ah[0], ah[1], ah[2], ah[3], sAh + off);
                LDM4(al[0], al[1], al[2], al[3], sAl + off);
#pragma unroll
                for (int nt = 0; nt < 4; nt++) MMA_BF16(acc[mt][nt], ah, bh[nt]);
#pragma unroll
                for (int nt = 0; nt < 4; nt++) MMA_BF16(acc[mt][nt], ah, bl[nt]);
#pragma unroll
                for (int nt = 0; nt < 4; nt++) MMA_BF16(acc[mt][nt], al, bh[nt]);
            }
        }
    };

    const int NC = Ksplit >> 6;
    stage_load(0, 0);
    for (int c = 0; c < NC; c++) {
        CP_WAIT0();
        __syncthreads();
        if (c + 1 < NC) stage_load(c + 1, (c + 1) & 1);
        mma_chunk(c & 1);
    }

    // ---- epilogue ----
    const int qrow = lane >> 2;
    const int qcol = (lane & 3) * 2;

    if (mode == 3) {
        float* tileT = reinterpret_cast<float*>(smem);   // [64][129]
        __syncthreads();
#pragma unroll
        for (int mt = 0; mt < 2; mt++) {
            int lr0 = warp_m + mt * 16 + qrow;
            int lr1 = lr0 + 8;
#pragma unroll
            for (int nt = 0; nt < 4; nt++) {
                int lc = warp_n + nt * 8 + qcol;
                float b0 = bias[n0 + lc], b1 = bias[n0 + lc + 1];
                tileT[lr0 * 129 + lc]     = softplus_f(acc[mt][nt][0] + b0);
                tileT[lr0 * 129 + lc + 1] = softplus_f(acc[mt][nt][1] + b1);
                tileT[lr1 * 129 + lc]     = softplus_f(acc[mt][nt][2] + b0);
                tileT[lr1 * 129 + lc + 1] = softplus_f(acc[mt][nt][3] + b1);
            }
        }
        __syncthreads();
        const int c  = tid >> 1;
        const int hf = (tid & 1) * 32;
        float* dst = C + (size_t)(n0 + c) * ldc + m0 + hf;
#pragma unroll
        for (int k = 0; k < 32; k += 4) {
            float4 v;
            v.x = tileT[(hf + k + 0) * 129 + c];
            v.y = tileT[(hf + k + 1) * 129 + c];
            v.z = tileT[(hf + k + 2) * 129 + c];
            v.w = tileT[(hf + k + 3) * 129 + c];
            *reinterpret_cast<float4*>(dst + k) = v;
        }
        return;
    }

#pragma unroll
    for (int mt = 0; mt < 2; mt++) {
        int row0 = m0 + warp_m + mt * 16 + qrow;
        int row1 = row0 + 8;
#pragma unroll
        for (int nt = 0; nt < 4; nt++) {
            int gn = n0 + warp_n + nt * 8 + qcol;
            if (gn >= Nvalid) continue;
            float2 v0 = make_float2(acc[mt][nt][0], acc[mt][nt][1]);
            float2 v1 = make_float2(acc[mt][nt][2], acc[mt][nt][3]);
            if (mode == 1) {
                float b0 = bias[gn], b1 = bias[gn + 1];
                v0.x = softplus_f(v0.x + b0); v0.y = softplus_f(v0.y + b1);
                v1.x = softplus_f(v1.x + b0); v1.y = softplus_f(v1.y + b1);
            }
            if (mode == 2) {
                atomicAdd(&C[(size_t)row0 * ldc + gn],     v0.x);
                atomicAdd(&C[(size_t)row0 * ldc + gn + 1], v0.y);
                atomicAdd(&C[(size_t)row1 * ldc + gn],     v1.x);
                atomicAdd(&C[(size_t)row1 * ldc + gn + 1], v1.y);
            } else {
                *reinterpret_cast<float2*>(C + (size_t)row0 * ldc + gn) = v0;
                *reinterpret_cast<float2*>(C + (size_t)row1 * ldc + gn) = v1;
            }
        }
    }
}

// ---------------- zero a float buffer ----------------------------------------
__global__ void zero_kernel(float* __restrict__ p, int n4)
{
    int i = blockIdx.x * blockDim.x + threadIdx.x;
    if (i < n4)
        reinterpret_cast<float4*>(p)[i] = make_float4(0.f, 0.f, 0.f, 0.f);
}

// ---------------- fp32 -> bf16 hi/lo converters (MLP=4) ----------------------
__global__ void cvt_kernel(const float* __restrict__ src,
                           bf16* __restrict__ hi, bf16* __restrict__ lo, int n4)
{
    int base = blockIdx.x * blockDim.x * 4 + threadIdx.x;
    float4 v[4];
    int idx[4];
#pragma unroll
    for (int u = 0; u < 4; u++) {
        idx[u] = base + u * 256;
        if (idx[u] < n4) v[u] = reinterpret_cast<const float4*>(src)[idx[u]];
    }
#pragma unroll
    for (int u = 0; u < 4; u++) {
        if (idx[u] >= n4) continue;
        bf16 h0, h1, h2, h3, l0, l1, l2, l3;
        split_bf16(v[u].x, h0, l0); split_bf16(v[u].y, h1, l1);
        split_bf16(v[u].z, h2, l2); split_bf16(v[u].w, h3, l3);
        reinterpret_cast<uint2*>(hi)[idx[u]] = make_uint2(pack2(h0,h1), pack2(h2,h3));
        reinterpret_cast<uint2*>(lo)[idx[u]] = make_uint2(pack2(l0,l1), pack2(l2,l3));
    }
}

__global__ void cvt4_kernel(const float* s0, bf16* h0, bf16* l0, int n0,
                            const float* s1, bf16* h1, bf16* l1, int n1,
                            const float* s2, bf16* h2, bf16* l2, int n2,
                            const float* s3, bf16* h3, bf16* l3, int n3)
{
    int i = blockIdx.x * blockDim.x + threadIdx.x;
    const float* s; bf16 *h, *l; int j = i;
    if (j < n0)      { s = s0; h = h0; l = l0; }
    else { j -= n0;
    if (j < n1)      { s = s1; h = h1; l = l1; }
    else { j -= n1;
    if (j < n2)      { s = s2; h = h2; l = l2; }
    else { j -= n2;
    if (j < n3)      { s = s3; h = h3; l = l3; }
    else return; } } }
    float4 v = reinterpret_cast<const float4*>(s)[j];
    bf16 a0, a1, a2, a3, b0, b1, b2, b3;
    split_bf16(v.x, a0, b0); split_bf16(v.y, a1, b1);
    split_bf16(v.z, a2, b2); split_bf16(v.w, a3, b3);
    reinterpret_cast<uint2*>(h)[j] = make_uint2(pack2(a0,a1), pack2(a2,a3));
    reinterpret_cast<uint2*>(l)[j] = make_uint2(pack2(b0,b1), pack2(b2,b3));
}

// ---------------- fused residual-add + LayerNorm ------------------------------
__global__ void resln_kernel(const float* __restrict__ hin,
                             float* __restrict__ res,
                             bf16* __restrict__ hn_hi, bf16* __restrict__ hn_lo,
                             const float* __restrict__ w,
                             const float* __restrict__ b,
                             int first)
{
    const int l   = blockIdx.x;
    const int tid = threadIdx.x;
    float v[4];
    float s = 0.f, sq = 0.f;
#pragma unroll
    for (int i = 0; i < 4; i++) {
        int c = tid + i * 256;
        float x = hin[l * DMODEL + c];
        if (!first) x += res[l * DMODEL + c];
        res[l * DMODEL + c] = x;
        v[i] = x;
        s  += x;
        sq += x * x;
    }
    __shared__ float shs[8], shq[8];
    const int lane = tid & 31, warp = tid >> 5;
#pragma unroll
    for (int o = 16; o > 0; o >>= 1) {
        s  += __shfl_xor_sync(0xffffffffu, s,  o);
        sq += __shfl_xor_sync(0xffffffffu, sq, o);
    }
    if (lane == 0) { shs[warp] = s; shq[warp] = sq; }
    __syncthreads();
    s = 0.f; sq = 0.f;
#pragma unroll
    for (int i = 0; i < 8; i++) { s += shs[i]; sq += shq[i]; }

    const float inv = 1.f / (float)DMODEL;
    const float mu  = s * inv;
    const float var = sq * inv - mu * mu;
    const float rstd = rsqrtf(var + 1e-5f);
#pragma unroll
    for (int i = 0; i < 4; i++) {
        int c = tid + i * 256;
        float o = (v[i] - mu) * rstd * w[c] + b[c];
        bf16 h, lo; split_bf16(o, h, lo);
        hn_hi[l * DMODEL + c] = h;
        hn_lo[l * DMODEL + c] = lo;
    }
}

// =============================================================================
// Fused conv + SiLU + transposes, tiled 32(d) x 32(l), block (32,8).
// =============================================================================
__global__ void conv_tile_kernel(const float* __restrict__ xz,
                                 const float* __restrict__ cw,
                                 const float* __restrict__ cb,
                                 bf16* __restrict__ xc_hi,
                                 bf16* __restrict__ xc_lo,
                                 float* __restrict__ xcT,
                                 float* __restrict__ zT,
                                 float* __restrict__ xdbl_zero)
{
    __shared__ float xin[35][33];
    __shared__ float zin[32][33];
    __shared__ float ot [32][33];

    const int d0 = blockIdx.x * 32;
    const int l0 = blockIdx.y * 32;
    const int tx = threadIdx.x, ty = threadIdx.y;

    {
        int flat = (blockIdx.y * gridDim.x + blockIdx.x) * 256 + ty * 32 + tx;
        if (flat < L_SEQ * XDBL_W) xdbl_zero[flat] = 0.f;
    }

#pragma unroll
    for (int i = 0; i < 5; i++) {
        int y = ty + i * 8;
        if (y < 35) {
            int l = l0 + y - 3;
            xin[y][tx] = (l >= 0) ? xz[(size_t)l * (2*DINNER) + d0 + tx] : 0.f;
        }
    }
#pragma unroll
    for (int i = 0; i < 4; i++) {
        int y = ty + i * 8;
        zin[y][tx] = xz[(size_t)(l0 + y) * (2*DINNER) + DINNER + d0 + tx];
    }
    __syncthreads();

    const int d = d0 + tx;
    const float w0 = cw[d*4+0], w1 = cw[d*4+1], w2 = cw[d*4+2], w3 = cw[d*4+3];
    const float cbd = cb[d];
#pragma unroll
    for (int i = 0; i < 4; i++) {
        int y = ty + i * 8;
        int l = l0 + y;
        float acc = cbd;
        acc = fmaf(w0, xin[y][tx],     acc);
        acc = fmaf(w1, xin[y + 1][tx], acc);
        acc = fmaf(w2, xin[y + 2][tx], acc);
        acc = fmaf(w3, xin[y + 3][tx], acc);
        acc = acc / (1.f + expf(-acc));
        bf16 h, lo; split_bf16(acc, h, lo);
        xc_hi[(size_t)l * DINNER + d] = h;
        xc_lo[(size_t)l * DINNER + d] = lo;
        ot[y][tx] = acc;
    }
    __syncthreads();

#pragma unroll
    for (int i = 0; i < 4; i++) {
        int y = ty + i * 8;
        xcT[(size_t)(d0 + y) * L_SEQ + l0 + tx] = ot[tx][y];
        zT [(size_t)(d0 + y) * L_SEQ + l0 + tx] = zin[tx][y];
    }
}

// ---------------- yT [d][t] -> y hi/lo [t][d]; zeroes out_proj target --------
__global__ void ytr_kernel(const float* __restrict__ yT,
                           bf16* __restrict__ y_hi, bf16* __restrict__ y_lo,
                           float* __restrict__ zero_buf)
{
    {
        int flat = threadIdx.y * 32 + threadIdx.x;
        int zi = (blockIdx.y * gridDim.x + blockIdx.x) * 256 + flat;
        if (zi * 2 < L_SEQ * DMODEL)
            *reinterpret_cast<float2*>(zero_buf + zi * 2) = make_float2(0.f, 0.f);
    }
    __shared__ float tile[32][33];
    const int c0 = blockIdx.x * 32;   // t
    const int r0 = blockIdx.y * 32;   // d
    const int x = threadIdx.x, y0 = threadIdx.y;
#pragma unroll
    for (int i = 0; i < 4; i++) {
        int y = y0 + i * 8;
        tile[y][x] = yT[(size_t)(r0 + y) * L_SEQ + c0 + x];
    }
    __syncthreads();
#pragma unroll
    for (int i = 0; i < 4; i++) {
        int y = y0 + i * 8;
        float v = tile[x][y];
        bf16 h, l; split_bf16(v, h, l);
        y_hi[(size_t)(c0 + y) * DINNER + r0 + x] = h;
        y_lo[(size_t)(c0 + y) * DINNER + r0 + x] = l;
    }
}

// =============================================================================
// Chunked parallel scan — round-8 form (static 10 KB smem, high occupancy).
// =============================================================================
__global__ void __launch_bounds__(256)
scan_kernel(const float* __restrict__ deltaT,
            const float* __restrict__ xcT,
            const float* __restrict__ zT,
            const float* __restrict__ xdbl,
            const float* __restrict__ A_log,
            const float* __restrict__ Dvec,
            float* __restrict__ yT)
{
    __shared__ float s_dl[L_SEQ];
    __shared__ float s_xv[L_SEQ];
    __shared__ float shP[16][16];
    __shared__ float shS[16][16];

    const int d    = blockIdx.x;
    const int tid  = threadIdx.x;
    const int lane = tid & 31;
    const int wrp  = tid >> 5;
    const int j    = wrp * 2 + (lane >> 4);
    const int s    = lane & 15;
    const int t0   = j * 64;

    for (int i = tid; i < L_SEQ; i += 256) {
        s_dl[i] = deltaT[(size_t)d * L_SEQ + i];
        s_xv[i] = xcT[(size_t)d * L_SEQ + i];
    }
    __syncthreads();

    const float a2 = -expf(A_log[d * DSTATE + s]) * 1.4426950408889634f;

    float P = 1.f, S = 0.f;
#pragma unroll 4
    for (int k = 0; k < 64; k++) {
        const int t = t0 + k;
        const float dl = s_dl[t];
        const float Bs = xdbl[t * XDBL_W + DTRANK + s];
        const float dA = exp2f(dl * a2);
        P *= dA;
        S = fmaf(dA, S, dl * s_xv[t] * Bs);
    }
    shP[j][s] = P;
    shS[j][s] = S;
    __syncthreads();

    if (tid < 16) {
        const int ss = tid;
        float run = shS[0][ss];
#pragma unroll
        for (int jj = 1; jj < 16; jj++) {
            run = fmaf(shP[jj][ss], run, shS[jj][ss]);
            shS[jj][ss] = run;
        }
    }
    __syncthreads();

    float h = (j == 0) ? 0.f : shS[j - 1][s];
    const float Dd = Dvec[d];
#pragma unroll 4
    for (int k = 0; k < 64; k++) {
        const int t = t0 + k;
        const float dl = s_dl[t];
        const float xv = s_xv[t];
        const float Bs = xdbl[t * XDBL_W + DTRANK + s];
        const float Cs = xdbl[t * XDBL_W + DTRANK + DSTATE + s];
        const float dA = exp2f(dl * a2);
        h = fmaf(dA, h, dl * xv * Bs);

        float acc = h * Cs;
        acc += __shfl_xor_sync(0xffffffffu, acc, 1);
        acc += __shfl_xor_sync(0xffffffffu, acc, 2);
        acc += __shfl_xor_sync(0xffffffffu, acc, 4);
        acc += __shfl_xor_sync(0xffffffffu, acc, 8);

        if (s == 0) {
            const float zv = zT[(size_t)d * L_SEQ + t];
            float yv = acc + xv * Dd;
            yv *= zv / (1.f + expf(-zv));
            yT[(size_t)d * L_SEQ + t] = yv;
        }
    }
}

// ---------------- host orchestration ----------------------------------------
extern "C" void kernel_launch(void* const* d_in, const int* in_sizes, int n_in,
                              void* d_out, int out_size)
{
    const float* input   = (const float*)d_in[0];
    const float* input_w = (const float*)d_in[2];
    const float* norm_w  = (const float*)d_in[3];
    const float* norm_b  = (const float*)d_in[4];
    const float* ipw     = (const float*)d_in[5];
    const float* cw      = (const float*)d_in[6];
    const float* cb      = (const float*)d_in[7];
    const float* xpw     = (const float*)d_in[8];
    const float* dtw     = (const float*)d_in[9];
    const float* dtb     = (const float*)d_in[10];
    const float* A_log   = (const float*)d_in[11];
    const float* ssm_D   = (const float*)d_in[12];
    const float* opw     = (const float*)d_in[13];

    float *res, *h, *xz, *xdbl, *deltaT, *xcT, *zT, *yT;
    cudaGetSymbolAddress((void**)&res,    g_res);
    cudaGetSymbolAddress((void**)&h,      g_h);
    cudaGetSymbolAddress((void**)&xz,     g_xz);
    cudaGetSymbolAddress((void**)&xdbl,   g_xdbl);
    cudaGetSymbolAddress((void**)&deltaT, g_deltaT);
    cudaGetSymbolAddress((void**)&xcT,    g_xcT);
    cudaGetSymbolAddress((void**)&zT,     g_zT);
    cudaGetSymbolAddress((void**)&yT,     g_yT);

    bf16 *in_hi, *in_lo, *inw_hi, *inw_lo, *ipw_hi, *ipw_lo, *xpw_hi, *xpw_lo;
    bf16 *dtw_hi, *dtw_lo, *opw_hi, *opw_lo, *hn_hi, *hn_lo, *xc_hi, *xc_lo;
    bf16 *y_hi, *y_lo;
    cudaGetSymbolAddress((void**)&in_hi,  c_in_hi);  cudaGetSymbolAddress((void**)&in_lo,  c_in_lo);
    cudaGetSymbolAddress((void**)&inw_hi, c_inw_hi); cudaGetSymbolAddress((void**)&inw_lo, c_inw_lo);
    cudaGetSymbolAddress((void**)&ipw_hi, c_ipw_hi); cudaGetSymbolAddress((void**)&ipw_lo, c_ipw_lo);
    cudaGetSymbolAddress((void**)&xpw_hi, c_xpw_hi); cudaGetSymbolAddress((void**)&xpw_lo, c_xpw_lo);
    cudaGetSymbolAddress((void**)&dtw_hi, c_dtw_hi); cudaGetSymbolAddress((void**)&dtw_lo, c_dtw_lo);
    cudaGetSymbolAddress((void**)&opw_hi, c_opw_hi); cudaGetSymbolAddress((void**)&opw_lo, c_opw_lo);
    cudaGetSymbolAddress((void**)&hn_hi,  c_hn_hi);  cudaGetSymbolAddress((void**)&hn_lo,  c_hn_lo);
    cudaGetSymbolAddress((void**)&xc_hi,  c_xc_hi);  cudaGetSymbolAddress((void**)&xc_lo,  c_xc_lo);
    cudaGetSymbolAddress((void**)&y_hi,   c_y_hi);   cudaGetSymbolAddress((void**)&y_lo,   c_y_lo);

    cudaFuncSetAttribute(mma_gemm, cudaFuncAttributeMaxDynamicSharedMemorySize, G_SMEM);

    // conversions + zero h for input split-K
    cvt_kernel<<<(NLAYERS*2*DINNER*DMODEL/4 + 1023)/1024, 256>>>(
        ipw, ipw_hi, ipw_lo, NLAYERS*2*DINNER*DMODEL/4);
    cvt_kernel<<<(NLAYERS*DMODEL*DINNER/4 + 1023)/1024, 256>>>(
        opw, opw_hi, opw_lo, NLAYERS*DMODEL*DINNER/4);
    cvt4_kernel<<<(589824 + 255)/256, 256>>>(
        input,   in_hi,  in_lo,  L_SEQ*INLEN/4,
        input_w, inw_hi, inw_lo, DMODEL*INLEN/4,
        xpw,     xpw_hi, xpw_lo, NLAYERS*XDBL_W*DINNER/4,
        dtw,     dtw_hi, dtw_lo, NLAYERS*DINNER*DTRANK/4);
    zero_kernel<<<(L_SEQ*DMODEL/4 + 255)/256, 256>>>(h, L_SEQ*DMODEL/4);

    // h = input @ input_w^T   split-K=2 (256 CTAs), atomic
    mma_gemm<<<dim3(DMODEL/128, L_SEQ/64, 2), 256, G_SMEM>>>(
        in_hi, in_lo, INLEN, inw_hi, inw_lo, INLEN, h, DMODEL,
        DMODEL, INLEN/2, nullptr, 2, 0);

    for (int i = 0; i < NLAYERS; i++) {
        resln_kernel<<<L_SEQ, 256>>>(h, res, hn_hi, hn_lo,
                                     norm_w + i*DMODEL, norm_b + i*DMODEL, i == 0);

        // xz = hn @ in_proj_w^T   (512 CTAs)
        mma_gemm<<<dim3((2*DINNER)/128, L_SEQ/64), 256, G_SMEM>>>(
            hn_hi, hn_lo, DMODEL,
            ipw_hi + (size_t)i*2*DINNER*DMODEL, ipw_lo + (size_t)i*2*DINNER*DMODEL, DMODEL,
            xz, 2*DINNER, 2*DINNER, DMODEL, nullptr, 0, 0);

        // fused conv + SiLU + xcT/zT transposes + xdbl zeroing
        conv_tile_kernel<<<dim3(DINNER/32, L_SEQ/32), dim3(32, 8)>>>(
            xz, cw + (size_t)i*DINNER*4, cb + i*DINNER,
            xc_hi, xc_lo, xcT, zT, xdbl);

        // x_dbl = xconv @ x_proj_w^T   split-K=16 (256 CTAs), atomic
        mma_gemm<<<dim3(1, L_SEQ/64, 16), 256, G_SMEM>>>(
            xc_hi, xc_lo, DINNER,
            xpw_hi + (size_t)i*XDBL_W*DINNER, xpw_lo + (size_t)i*XDBL_W*DINNER, DINNER,
            xdbl, XDBL_W, XDBL_W, DINNER/16, nullptr, 2, 0);

        // deltaT = softplus(xdbl[:, :64] @ dt_proj_w^T + bias)^T
        // mode 3 (transposed store) + afp32 (reads fp32 xdbl directly,
        // converts inline) — cvt_xdbl kernel eliminated
        mma_gemm<<<dim3(DINNER/128, L_SEQ/64), 256, G_SMEM>>>(
            xdbl, nullptr, XDBL_W,
            dtw_hi + (size_t)i*DINNER*DTRANK, dtw_lo + (size_t)i*DINNER*DTRANK, DTRANK,
            deltaT, L_SEQ, DINNER, DTRANK, dtb + i*DINNER, 3, 1);

        scan_kernel<<<DINNER, 256>>>(deltaT, xcT, zT, xdbl,
                                     A_log + (size_t)i*DINNER*DSTATE,
                                     ssm_D + i*DINNER, yT);

        // yT -> y hi/lo; zero the split-K out_proj target
        float* outp = (i == NLAYERS-1) ? (float*)d_out : h;
        ytr_kernel<<<dim3(L_SEQ/32, DINNER/32), dim3(32, 8)>>>(yT, y_hi, y_lo, outp);

        // h(next) = y @ out_proj_w^T   split-K=4 (512 CTAs), atomic
        mma_gemm<<<dim3(DMODEL/128, L_SEQ/64, 4), 256, G_SMEM>>>(
            y_hi, y_lo, DINNER,
            opw_hi + (size_t)i*DMODEL*DINNER, opw_lo + (size_t)i*DMODEL*DINNER, DINNER,
            outp, DMODEL, DMODEL, DINNER/4, nullptr, 2, 0);
    }
}